// round 1
// baseline (speedup 1.0000x reference)
#include <cuda_runtime.h>
#include <math.h>

#define NSEQ   2048
#define BATCH  2
#define HEADS  16
#define HD     64
#define CDIM   1024
#define MTOK   (BATCH*NSEQ)      // 4096

// Scratch (no allocations allowed)
__device__ float g_q[BATCH*HEADS*NSEQ*HD];
__device__ float g_k[BATCH*HEADS*NSEQ*HD];
__device__ float g_v[BATCH*HEADS*NSEQ*HD];
__device__ float g_ao[MTOK*CDIM];

// ---------------------------------------------------------------------------
// QKV GEMM: Y[M=4096, 3072] = x[4096,1024] @ qkv_w^T (qkv_w is [3072,1024])
// Epilogue scatters into g_q / g_k / g_v in [B,H,N,D] layout.
// 128x128 tile, BK=8, 256 threads, 8x8 microtile.
// ---------------------------------------------------------------------------
__global__ __launch_bounds__(256) void qkv_gemm_kernel(
    const float* __restrict__ x, const float* __restrict__ w)
{
    __shared__ float As[8][128];
    __shared__ float Bs[8][128];
    const int K = 1024;
    const int tid = threadIdx.x;
    const int rowBase = blockIdx.y * 128;
    const int colBase = blockIdx.x * 128;
    const int lr = tid >> 1;
    const int lk = (tid & 1) * 4;
    const int r0 = (tid >> 4) * 8;
    const int c0 = (tid & 15) * 8;

    float acc[8][8];
#pragma unroll
    for (int i = 0; i < 8; i++)
#pragma unroll
        for (int j = 0; j < 8; j++) acc[i][j] = 0.0f;

    const float* aptr = x + (size_t)(rowBase + lr) * K + lk;
    const float* bptr = w + (size_t)(colBase + lr) * K + lk;

    for (int k0 = 0; k0 < K; k0 += 8) {
        float4 a4 = *(const float4*)(aptr + k0);
        float4 b4 = *(const float4*)(bptr + k0);
        As[lk + 0][lr] = a4.x; As[lk + 1][lr] = a4.y;
        As[lk + 2][lr] = a4.z; As[lk + 3][lr] = a4.w;
        Bs[lk + 0][lr] = b4.x; Bs[lk + 1][lr] = b4.y;
        Bs[lk + 2][lr] = b4.z; Bs[lk + 3][lr] = b4.w;
        __syncthreads();
#pragma unroll
        for (int kk = 0; kk < 8; kk++) {
            float4 a0 = *(const float4*)&As[kk][r0];
            float4 a1 = *(const float4*)&As[kk][r0 + 4];
            float4 b0 = *(const float4*)&Bs[kk][c0];
            float4 b1 = *(const float4*)&Bs[kk][c0 + 4];
            float af[8] = {a0.x, a0.y, a0.z, a0.w, a1.x, a1.y, a1.z, a1.w};
            float bf[8] = {b0.x, b0.y, b0.z, b0.w, b1.x, b1.y, b1.z, b1.w};
#pragma unroll
            for (int i = 0; i < 8; i++)
#pragma unroll
                for (int j = 0; j < 8; j++)
                    acc[i][j] = fmaf(af[i], bf[j], acc[i][j]);
        }
        __syncthreads();
    }

#pragma unroll
    for (int i = 0; i < 8; i++) {
        int row = rowBase + r0 + i;
        int b = row >> 11;          // /2048
        int n = row & 2047;
#pragma unroll
        for (int j = 0; j < 8; j++) {
            int col = colBase + c0 + j;
            int t = col >> 10;      // 0=q,1=k,2=v
            int rem = col & 1023;
            int h = rem >> 6;
            int d = rem & 63;
            float* dst = (t == 0) ? g_q : (t == 1) ? g_k : g_v;
            dst[(((size_t)(b * HEADS + h)) * NSEQ + n) * HD + d] = acc[i][j];
        }
    }
}

// ---------------------------------------------------------------------------
// RoPE in place on g_q and g_k. One thread per (row, pair).
// ---------------------------------------------------------------------------
__global__ __launch_bounds__(256) void rope_kernel()
{
    const int per = BATCH * HEADS * NSEQ * 32;  // 2097152 pairs per tensor
    int idx = blockIdx.x * blockDim.x + threadIdx.x;
    float* base = (idx < per) ? g_q : g_k;
    int rem = (idx < per) ? idx : idx - per;
    int pair = rem & 31;
    int row = rem >> 5;
    int n = row & (NSEQ - 1);

    float inv = powf(10000.0f, -(float)pair * (1.0f / 32.0f));
    float ang = (float)n * inv;
    float s, c;
    sincosf(ang, &s, &c);

    float* p = base + (size_t)row * 64;
    float t1 = p[pair];
    float t2 = p[pair + 32];
    p[pair]      = t1 * c - t2 * s;
    p[pair + 32] = t2 * c + t1 * s;
}

// ---------------------------------------------------------------------------
// Flash-style attention: block = (q-tile 64, head, batch), 256 threads.
// Online softmax with per-warp register state (each warp owns 8 S-rows).
// Writes g_ao in [B, N, H*D] layout (ready for projection).
// ---------------------------------------------------------------------------
#define KV_STRIDE 68
#define ATTN_SMEM ((4096 + 64*KV_STRIDE + 4096) * 4)  // 50176 bytes

__global__ __launch_bounds__(256) void attn_kernel(const float* __restrict__ slopes)
{
    extern __shared__ float sm[];
    float* Qs = sm;                       // [64][64]
    float* KV = sm + 4096;                // 64 rows, stride 68 (K^T then V)
    float* Ps = sm + 4096 + 64 * KV_STRIDE; // [64][64]

    const int tid = threadIdx.x;
    const int qt = blockIdx.x, h = blockIdx.y, b = blockIdx.z;
    const int bh = b * HEADS + h;
    const float slope8 = slopes[h] * 8.0f;
    const int r0 = (tid >> 4) * 4;       // microtile row base (0..60)
    const int c0 = (tid & 15) * 4;       // microtile col base (0..60)
    const int lane = tid & 31;
    const int wrow = (tid >> 5) * 8;     // warp's first row
    const bool hiHalf = (r0 & 4) != 0;   // which half of warp's 8 rows

    const float* qptr = g_q + ((size_t)bh * NSEQ + qt * 64) * 64;
    for (int i = tid; i < 4096; i += 256) Qs[i] = qptr[i];

    float o[4][4];
#pragma unroll
    for (int i = 0; i < 4; i++)
#pragma unroll
        for (int j = 0; j < 4; j++) o[i][j] = 0.0f;
    float mreg[8], lreg[8];
#pragma unroll
    for (int r = 0; r < 8; r++) { mreg[r] = -1e30f; lreg[r] = 0.0f; }

    for (int kt = 0; kt < 32; kt++) {
        const float* kptr = g_k + ((size_t)bh * NSEQ + kt * 64) * 64;
        __syncthreads();  // prev iter done with KV/Ps (and Qs loaded on iter 0)
        for (int i = tid; i < 4096; i += 256) {
            int j = i >> 6, d = i & 63;
            KV[d * KV_STRIDE + j] = kptr[i];   // K transposed: [d][j]
        }
        __syncthreads();

        // S = Q @ K^T  (4x4 microtile, K unrolled by 4)
        float s[4][4];
#pragma unroll
        for (int i = 0; i < 4; i++)
#pragma unroll
            for (int j = 0; j < 4; j++) s[i][j] = 0.0f;

        for (int d0 = 0; d0 < 64; d0 += 4) {
            float4 k0v = *(const float4*)(KV + (d0 + 0) * KV_STRIDE + c0);
            float4 k1v = *(const float4*)(KV + (d0 + 1) * KV_STRIDE + c0);
            float4 k2v = *(const float4*)(KV + (d0 + 2) * KV_STRIDE + c0);
            float4 k3v = *(const float4*)(KV + (d0 + 3) * KV_STRIDE + c0);
#pragma unroll
            for (int ii = 0; ii < 4; ii++) {
                float4 qf = *(const float4*)(Qs + (r0 + ii) * 64 + d0);
                s[ii][0] = fmaf(qf.x, k0v.x, fmaf(qf.y, k1v.x, fmaf(qf.z, k2v.x, fmaf(qf.w, k3v.x, s[ii][0]))));
                s[ii][1] = fmaf(qf.x, k0v.y, fmaf(qf.y, k1v.y, fmaf(qf.z, k2v.y, fmaf(qf.w, k3v.y, s[ii][1]))));
                s[ii][2] = fmaf(qf.x, k0v.z, fmaf(qf.y, k1v.z, fmaf(qf.z, k2v.z, fmaf(qf.w, k3v.z, s[ii][2]))));
                s[ii][3] = fmaf(qf.x, k0v.w, fmaf(qf.y, k1v.w, fmaf(qf.z, k2v.w, fmaf(qf.w, k3v.w, s[ii][3]))));
            }
        }

        // scale + ALiBi, write raw scores to Ps
#pragma unroll
        for (int ii = 0; ii < 4; ii++) {
            int ig = qt * 64 + r0 + ii;
            float t[4];
#pragma unroll
            for (int jj = 0; jj < 4; jj++) {
                int jg = kt * 64 + c0 + jj;
                float diff = (float)(jg - ig);
                if (diff > 0.0f) diff = 0.0f;
                t[jj] = s[ii][jj] * 0.125f + slope8 * diff;
            }
            *(float4*)(Ps + (r0 + ii) * 64 + c0) = make_float4(t[0], t[1], t[2], t[3]);
        }
        __syncwarp();

        // Online softmax: warp owns rows [wrow, wrow+8)
        float sf[8];
#pragma unroll
        for (int rr = 0; rr < 8; rr++) {
            int row = wrow + rr;
            float v0 = Ps[row * 64 + lane];
            float v1 = Ps[row * 64 + 32 + lane];
            float mx = fmaxf(v0, v1);
#pragma unroll
            for (int off = 16; off; off >>= 1)
                mx = fmaxf(mx, __shfl_xor_sync(0xffffffffu, mx, off));
            float newm = fmaxf(mreg[rr], mx);
            float p0 = __expf(v0 - newm);
            float p1 = __expf(v1 - newm);
            Ps[row * 64 + lane] = p0;
            Ps[row * 64 + 32 + lane] = p1;
            float sum = p0 + p1;
#pragma unroll
            for (int off = 16; off; off >>= 1)
                sum += __shfl_xor_sync(0xffffffffu, sum, off);
            float f = __expf(mreg[rr] - newm);
            sf[rr] = f;
            lreg[rr] = lreg[rr] * f + sum;
            mreg[rr] = newm;
        }
        __syncwarp();

        // rescale O accumulators
#pragma unroll
        for (int ii = 0; ii < 4; ii++) {
            float f = hiHalf ? sf[ii + 4] : sf[ii];
#pragma unroll
            for (int jj = 0; jj < 4; jj++) o[ii][jj] *= f;
        }
        __syncthreads();  // all warps done reading K^T before V overwrite

        // load V (natural [j][d] layout, stride 68)
        const float* vptr = g_v + ((size_t)bh * NSEQ + kt * 64) * 64;
        for (int i = tid; i < 4096; i += 256) {
            int j = i >> 6, d = i & 63;
            KV[j * KV_STRIDE + d] = vptr[i];
        }
        __syncthreads();

        // O += P @ V
        for (int j0 = 0; j0 < 64; j0 += 4) {
            float4 v0v = *(const float4*)(KV + (j0 + 0) * KV_STRIDE + c0);
            float4 v1v = *(const float4*)(KV + (j0 + 1) * KV_STRIDE + c0);
            float4 v2v = *(const float4*)(KV + (j0 + 2) * KV_STRIDE + c0);
            float4 v3v = *(const float4*)(KV + (j0 + 3) * KV_STRIDE + c0);
#pragma unroll
            for (int ii = 0; ii < 4; ii++) {
                float4 pf = *(const float4*)(Ps + (r0 + ii) * 64 + j0);
                o[ii][0] = fmaf(pf.x, v0v.x, fmaf(pf.y, v1v.x, fmaf(pf.z, v2v.x, fmaf(pf.w, v3v.x, o[ii][0]))));
                o[ii][1] = fmaf(pf.x, v0v.y, fmaf(pf.y, v1v.y, fmaf(pf.z, v2v.y, fmaf(pf.w, v3v.y, o[ii][1]))));
                o[ii][2] = fmaf(pf.x, v0v.z, fmaf(pf.y, v1v.z, fmaf(pf.z, v2v.z, fmaf(pf.w, v3v.z, o[ii][2]))));
                o[ii][3] = fmaf(pf.x, v0v.w, fmaf(pf.y, v1v.w, fmaf(pf.z, v2v.w, fmaf(pf.w, v3v.w, o[ii][3]))));
            }
        }
    }

    // finalize: divide by l, write [B, N, H*D]
#pragma unroll
    for (int ii = 0; ii < 4; ii++) {
        int ig = qt * 64 + r0 + ii;
        float l = hiHalf ? lreg[ii + 4] : lreg[ii];
        float invl = 1.0f / l;
        float* dst = g_ao + ((size_t)(b * NSEQ + ig)) * CDIM + h * 64 + c0;
        *(float4*)dst = make_float4(o[ii][0] * invl, o[ii][1] * invl,
                                    o[ii][2] * invl, o[ii][3] * invl);
    }
}

// ---------------------------------------------------------------------------
// Output projection: out[4096,1024] = g_ao @ proj_w^T + proj_b
// ---------------------------------------------------------------------------
__global__ __launch_bounds__(256) void proj_gemm_kernel(
    const float* __restrict__ w, const float* __restrict__ bias,
    float* __restrict__ out)
{
    __shared__ float As[8][128];
    __shared__ float Bs[8][128];
    const int K = 1024;
    const int tid = threadIdx.x;
    const int rowBase = blockIdx.y * 128;
    const int colBase = blockIdx.x * 128;
    const int lr = tid >> 1;
    const int lk = (tid & 1) * 4;
    const int r0 = (tid >> 4) * 8;
    const int c0 = (tid & 15) * 8;

    float acc[8][8];
#pragma unroll
    for (int i = 0; i < 8; i++)
#pragma unroll
        for (int j = 0; j < 8; j++) acc[i][j] = 0.0f;

    const float* aptr = g_ao + (size_t)(rowBase + lr) * K + lk;
    const float* bptr = w + (size_t)(colBase + lr) * K + lk;

    for (int k0 = 0; k0 < K; k0 += 8) {
        float4 a4 = *(const float4*)(aptr + k0);
        float4 b4 = *(const float4*)(bptr + k0);
        As[lk + 0][lr] = a4.x; As[lk + 1][lr] = a4.y;
        As[lk + 2][lr] = a4.z; As[lk + 3][lr] = a4.w;
        Bs[lk + 0][lr] = b4.x; Bs[lk + 1][lr] = b4.y;
        Bs[lk + 2][lr] = b4.z; Bs[lk + 3][lr] = b4.w;
        __syncthreads();
#pragma unroll
        for (int kk = 0; kk < 8; kk++) {
            float4 a0 = *(const float4*)&As[kk][r0];
            float4 a1 = *(const float4*)&As[kk][r0 + 4];
            float4 b0 = *(const float4*)&Bs[kk][c0];
            float4 b1 = *(const float4*)&Bs[kk][c0 + 4];
            float af[8] = {a0.x, a0.y, a0.z, a0.w, a1.x, a1.y, a1.z, a1.w};
            float bf[8] = {b0.x, b0.y, b0.z, b0.w, b1.x, b1.y, b1.z, b1.w};
#pragma unroll
            for (int i = 0; i < 8; i++)
#pragma unroll
                for (int j = 0; j < 8; j++)
                    acc[i][j] = fmaf(af[i], bf[j], acc[i][j]);
        }
        __syncthreads();
    }

#pragma unroll
    for (int i = 0; i < 8; i++) {
        int row = rowBase + r0 + i;
#pragma unroll
        for (int j = 0; j < 8; j++) {
            int col = colBase + c0 + j;
            out[(size_t)row * CDIM + col] = acc[i][j] + bias[col];
        }
    }
}

// ---------------------------------------------------------------------------
extern "C" void kernel_launch(void* const* d_in, const int* in_sizes, int n_in,
                              void* d_out, int out_size)
{
    const float* x      = (const float*)d_in[0];
    const float* qkv_w  = (const float*)d_in[1];
    const float* proj_w = (const float*)d_in[2];
    const float* proj_b = (const float*)d_in[3];
    const float* slopes = (const float*)d_in[4];
    float* out = (float*)d_out;

    qkv_gemm_kernel<<<dim3(3072 / 128, MTOK / 128), 256>>>(x, qkv_w);
    rope_kernel<<<(2 * BATCH * HEADS * NSEQ * 32) / 256, 256>>>();

    cudaFuncSetAttribute(attn_kernel,
                         cudaFuncAttributeMaxDynamicSharedMemorySize, ATTN_SMEM);
    attn_kernel<<<dim3(NSEQ / 64, HEADS, BATCH), 256, ATTN_SMEM>>>(slopes);

    proj_gemm_kernel<<<dim3(CDIM / 128, MTOK / 128), 256>>>(proj_w, proj_b, out);
}

// round 3
// speedup vs baseline: 2.0882x; 2.0882x over previous
#include <cuda_runtime.h>
#include <cuda_bf16.h>
#include <cstdint>
#include <math.h>

#define NSEQ   2048
#define BATCH  2
#define HEADS  16
#define HD     64
#define CDIM   1024
#define MTOK   (BATCH*NSEQ)      // 4096

typedef __nv_bfloat16  bf16;
typedef __nv_bfloat162 bf162;

// ---------------- device scratch (no allocations allowed) ------------------
__device__ bf16 g_xhi[MTOK*CDIM],  g_xlo[MTOK*CDIM];
__device__ bf16 g_wqhi[3*CDIM*CDIM], g_wqlo[3*CDIM*CDIM];
__device__ bf16 g_wphi[CDIM*CDIM],  g_wplo[CDIM*CDIM];
__device__ float g_qf[MTOK*CDIM], g_kf[MTOK*CDIM];
__device__ bf16 g_qhi[MTOK*CDIM], g_qlo[MTOK*CDIM];
__device__ bf16 g_khi[MTOK*CDIM], g_klo[MTOK*CDIM];
__device__ bf16 g_vhi[MTOK*CDIM], g_vlo[MTOK*CDIM];
__device__ bf16 g_aohi[MTOK*CDIM], g_aolo[MTOK*CDIM];

// ---------------- mma / ldmatrix helpers ----------------------------------
__device__ __forceinline__ void mma_bf16(float c[4], const uint32_t a[4], const uint32_t b[2]) {
    asm volatile(
        "mma.sync.aligned.m16n8k16.row.col.f32.bf16.bf16.f32 "
        "{%0,%1,%2,%3}, {%4,%5,%6,%7}, {%8,%9}, {%0,%1,%2,%3};\n"
        : "+f"(c[0]), "+f"(c[1]), "+f"(c[2]), "+f"(c[3])
        : "r"(a[0]), "r"(a[1]), "r"(a[2]), "r"(a[3]), "r"(b[0]), "r"(b[1]));
}

// A fragment (m16 x k16, row-major in smem)
__device__ __forceinline__ void lda_frag(uint32_t r[4], const bf16* base, int row0, int col0, int ld) {
    const int lane = threadIdx.x & 31;
    const bf16* p = base + (row0 + (lane & 15)) * ld + col0 + ((lane >> 4) << 3);
    uint32_t a = (uint32_t)__cvta_generic_to_shared(p);
    asm volatile("ldmatrix.sync.aligned.m8n8.x4.shared.b16 {%0,%1,%2,%3}, [%4];"
                 : "=r"(r[0]), "=r"(r[1]), "=r"(r[2]), "=r"(r[3]) : "r"(a));
}

// B fragment (k16 x n8) where smem holds B^T row-major: rows = n, cols = k
__device__ __forceinline__ void ldb_frag(uint32_t r[2], const bf16* base, int n0, int k0, int ld) {
    const int lane = threadIdx.x & 31;
    const bf16* p = base + (n0 + (lane & 7)) * ld + k0 + (((lane >> 3) & 1) << 3);
    uint32_t a = (uint32_t)__cvta_generic_to_shared(p);
    asm volatile("ldmatrix.sync.aligned.m8n8.x2.shared.b16 {%0,%1}, [%2];"
                 : "=r"(r[0]), "=r"(r[1]) : "r"(a));
}

__device__ __forceinline__ bf162 pack_split(float a, float b, bf162& lo) {
    bf16 ha = __float2bfloat16_rn(a);
    bf16 hb = __float2bfloat16_rn(b);
    lo.x = __float2bfloat16_rn(a - __bfloat162float(ha));
    lo.y = __float2bfloat16_rn(b - __bfloat162float(hb));
    bf162 hi; hi.x = ha; hi.y = hb; return hi;
}

// ---------------- fp32 -> (hi,lo) bf16 split ------------------------------
__global__ __launch_bounds__(256) void split_kernel(
    const float* __restrict__ in, bf16* __restrict__ hi, bf16* __restrict__ lo)
{
    int i = blockIdx.x * 256 + threadIdx.x;
    float4 v = ((const float4*)in)[i];
    bf162 l0, l1;
    bf162 h0 = pack_split(v.x, v.y, l0);
    bf162 h1 = pack_split(v.z, v.w, l1);
    ((bf162*)hi)[2*i]   = h0;  ((bf162*)hi)[2*i+1] = h1;
    ((bf162*)lo)[2*i]   = l0;  ((bf162*)lo)[2*i+1] = l1;
}

// ---------------- shared 128x128 split-bf16 GEMM tile ----------------------
// K = 1024 fixed. smem needs 4 * 128*40 bf16 = 40960 B.
#define GLDS 40
__device__ __forceinline__ void gemm_tile(
    const bf16* __restrict__ Ah, const bf16* __restrict__ Al,
    const bf16* __restrict__ Bh, const bf16* __restrict__ Bl,
    bf16* smem, float c[4][4][4])
{
    bf16* sAh = smem;
    bf16* sAl = smem + 128*GLDS;
    bf16* sBh = smem + 2*128*GLDS;
    bf16* sBl = smem + 3*128*GLDS;
    const int tid = threadIdx.x, wid = tid >> 5;
    const int wm = wid >> 2, wn = wid & 3;
    const int lrow = tid >> 1, lseg = (tid & 1) << 4;

    for (int kt = 0; kt < 1024; kt += 32) {
        __syncthreads();
        const uint4* pa0 = (const uint4*)(Ah + (size_t)lrow*1024 + kt + lseg);
        const uint4* pa1 = (const uint4*)(Al + (size_t)lrow*1024 + kt + lseg);
        const uint4* pb0 = (const uint4*)(Bh + (size_t)lrow*1024 + kt + lseg);
        const uint4* pb1 = (const uint4*)(Bl + (size_t)lrow*1024 + kt + lseg);
        uint4* qa0 = (uint4*)(sAh + lrow*GLDS + lseg);
        uint4* qa1 = (uint4*)(sAl + lrow*GLDS + lseg);
        uint4* qb0 = (uint4*)(sBh + lrow*GLDS + lseg);
        uint4* qb1 = (uint4*)(sBl + lrow*GLDS + lseg);
        qa0[0] = pa0[0]; qa0[1] = pa0[1];
        qa1[0] = pa1[0]; qa1[1] = pa1[1];
        qb0[0] = pb0[0]; qb0[1] = pb0[1];
        qb1[0] = pb1[0]; qb1[1] = pb1[1];
        __syncthreads();

#pragma unroll
        for (int ks = 0; ks < 32; ks += 16) {
            uint32_t bh[4][2], bl[4][2];
#pragma unroll
            for (int ni = 0; ni < 4; ni++) {
                ldb_frag(bh[ni], sBh, wn*32 + ni*8, ks, GLDS);
                ldb_frag(bl[ni], sBl, wn*32 + ni*8, ks, GLDS);
            }
#pragma unroll
            for (int mi = 0; mi < 4; mi++) {
                uint32_t ah[4], al[4];
                lda_frag(ah, sAh, wm*64 + mi*16, ks, GLDS);
                lda_frag(al, sAl, wm*64 + mi*16, ks, GLDS);
#pragma unroll
                for (int ni = 0; ni < 4; ni++) {
                    mma_bf16(c[mi][ni], ah, bh[ni]);
                    mma_bf16(c[mi][ni], ah, bl[ni]);
                    mma_bf16(c[mi][ni], al, bh[ni]);
                }
            }
        }
    }
}

// ---------------- QKV GEMM + scatter epilogue ------------------------------
__global__ __launch_bounds__(256, 2) void qkv_mma_kernel()
{
    __shared__ bf16 smem[4*128*GLDS];
    float c[4][4][4];
#pragma unroll
    for (int a = 0; a < 4; a++)
#pragma unroll
        for (int b = 0; b < 4; b++)
#pragma unroll
            for (int d = 0; d < 4; d++) c[a][b][d] = 0.0f;

    const int rowBase = blockIdx.y * 128, colBase = blockIdx.x * 128;
    gemm_tile(g_xhi + (size_t)rowBase*1024, g_xlo + (size_t)rowBase*1024,
              g_wqhi + (size_t)colBase*1024, g_wqlo + (size_t)colBase*1024,
              smem, c);

    const int lane = threadIdx.x & 31, wid = threadIdx.x >> 5;
    const int wm = wid >> 2, wn = wid & 3;
    const int g = lane >> 2, t2 = (lane & 3) << 1;
    const int tix = colBase >> 10;   // 0=q, 1=k, 2=v (uniform per block)

#pragma unroll
    for (int mi = 0; mi < 4; mi++) {
        int row = rowBase + wm*64 + mi*16 + g;
        int bb = row >> 11, n = row & 2047;
#pragma unroll
        for (int ni = 0; ni < 4; ni++) {
            int colg = colBase + wn*32 + ni*8 + t2;
            int rem = colg & 1023, hh = rem >> 6, d = rem & 63;
            size_t base0 = (((size_t)(bb*HEADS + hh))*NSEQ + n)*HD + d;
            size_t base1 = base0 + 8*HD;
            float* f = c[mi][ni];
            if (tix == 0) {
                *(float2*)(g_qf + base0) = make_float2(f[0], f[1]);
                *(float2*)(g_qf + base1) = make_float2(f[2], f[3]);
            } else if (tix == 1) {
                *(float2*)(g_kf + base0) = make_float2(f[0], f[1]);
                *(float2*)(g_kf + base1) = make_float2(f[2], f[3]);
            } else {
                bf162 l0, l1;
                bf162 h0 = pack_split(f[0], f[1], l0);
                bf162 h1 = pack_split(f[2], f[3], l1);
                *(bf162*)(g_vhi + base0) = h0; *(bf162*)(g_vlo + base0) = l0;
                *(bf162*)(g_vhi + base1) = h1; *(bf162*)(g_vlo + base1) = l1;
            }
        }
    }
}

// ---------------- RoPE + split -------------------------------------------
__global__ __launch_bounds__(256) void rope_split_kernel()
{
    const int per = BATCH*HEADS*NSEQ*32;
    int idx = blockIdx.x*256 + threadIdx.x;
    bool isq = idx < per;
    int rem = isq ? idx : idx - per;
    int pair = rem & 31;
    int rowI = rem >> 5;
    int n = rowI & (NSEQ-1);

    float inv = powf(10000.0f, -(float)pair * (1.0f/32.0f));
    float s, cc;
    sincosf((float)n * inv, &s, &cc);

    const float* src = isq ? g_qf : g_kf;
    bf16* dh = isq ? g_qhi : g_khi;
    bf16* dl = isq ? g_qlo : g_klo;
    size_t p0 = (size_t)rowI*64 + pair;
    float t1 = src[p0], t2 = src[p0+32];
    float r1 = t1*cc - t2*s;
    float r2 = t2*cc + t1*s;
    bf16 h1 = __float2bfloat16_rn(r1);
    bf16 h2 = __float2bfloat16_rn(r2);
    dh[p0]    = h1; dl[p0]    = __float2bfloat16_rn(r1 - __bfloat162float(h1));
    dh[p0+32] = h2; dl[p0+32] = __float2bfloat16_rn(r2 - __bfloat162float(h2));
}

// ---------------- flash attention with split-bf16 mma ----------------------
// block: 128 q rows x (head, batch). 8 warps; warp w owns m-rows [w*16, w*16+16).
#define ALD 72
#define ATTN_SMEM ((2*128*ALD + 4*64*ALD + 2*128*ALD) * 2)   // 110592 B

__global__ __launch_bounds__(256, 1) void attn_mma_kernel(const float* __restrict__ slopes)
{
    extern __shared__ bf16 sm[];
    bf16* sQh = sm;
    bf16* sQl = sQh + 128*ALD;
    bf16* sKh = sQl + 128*ALD;
    bf16* sKl = sKh + 64*ALD;
    bf16* sVh = sKl + 64*ALD;   // V^T: rows = d, cols = j
    bf16* sVl = sVh + 64*ALD;
    bf16* sPh = sVl + 64*ALD;
    bf16* sPl = sPh + 128*ALD;

    const int tid = threadIdx.x, wid = tid >> 5, lane = tid & 31;
    const int g = lane >> 2, t2 = (lane & 3) << 1;
    const int qt = blockIdx.x, h = blockIdx.y, b = blockIdx.z;
    const int bh = b*HEADS + h;
    const float slope8 = slopes[h] * 8.0f;

    // load Q tile (128x64, both planes)
    const size_t qoff = ((size_t)bh*NSEQ + qt*128)*HD;
    for (int v = tid; v < 1024; v += 256) {
        int row = v >> 3, seg = (v & 7) << 3;
        *(uint4*)(sQh + row*ALD + seg) = *(const uint4*)(g_qhi + qoff + row*64 + seg);
        *(uint4*)(sQl + row*ALD + seg) = *(const uint4*)(g_qlo + qoff + row*64 + seg);
    }
    __syncthreads();

    // hoist Q fragments for all 4 k-steps
    uint32_t qh[4][4], ql[4][4];
#pragma unroll
    for (int ks = 0; ks < 4; ks++) {
        lda_frag(qh[ks], sQh, wid*16, ks*16, ALD);
        lda_frag(ql[ks], sQl, wid*16, ks*16, ALD);
    }

    float o[8][4];
#pragma unroll
    for (int nt = 0; nt < 8; nt++)
#pragma unroll
        for (int d = 0; d < 4; d++) o[nt][d] = 0.0f;
    float m0 = -1e30f, m1 = -1e30f, l0 = 0.0f, l1 = 0.0f;
    const int rowg = qt*128 + wid*16 + g;   // global q position (rows rowg, rowg+8)

    for (int kt = 0; kt < 32; kt++) {
        __syncthreads();   // previous iteration done with K/V
        const size_t koff = ((size_t)bh*NSEQ + kt*64)*HD;
        for (int v = tid; v < 512; v += 256) {
            int row = v >> 3, seg = (v & 7) << 3;
            *(uint4*)(sKh + row*ALD + seg) = *(const uint4*)(g_khi + koff + row*64 + seg);
            *(uint4*)(sKl + row*ALD + seg) = *(const uint4*)(g_klo + koff + row*64 + seg);
        }
        for (int v = tid; v < 512; v += 256) {
            int j = v & 63, dblk = (v >> 6) << 3;
            union { uint4 u; bf16 e[8]; } th, tl;
            th.u = *(const uint4*)(g_vhi + koff + (size_t)j*64 + dblk);
            tl.u = *(const uint4*)(g_vlo + koff + (size_t)j*64 + dblk);
#pragma unroll
            for (int u = 0; u < 8; u++) {
                sVh[(dblk+u)*ALD + j] = th.e[u];
                sVl[(dblk+u)*ALD + j] = tl.e[u];
            }
        }
        __syncthreads();

        // S = Q K^T (fp32 accum, 3-mma split)
        float s[8][4];
#pragma unroll
        for (int nt = 0; nt < 8; nt++)
#pragma unroll
            for (int d = 0; d < 4; d++) s[nt][d] = 0.0f;
#pragma unroll
        for (int ks = 0; ks < 4; ks++) {
#pragma unroll
            for (int nt = 0; nt < 8; nt++) {
                uint32_t kh2[2], kl2[2];
                ldb_frag(kh2, sKh, nt*8, ks*16, ALD);
                ldb_frag(kl2, sKl, nt*8, ks*16, ALD);
                mma_bf16(s[nt], qh[ks], kh2);
                mma_bf16(s[nt], qh[ks], kl2);
                mma_bf16(s[nt], ql[ks], kh2);
            }
        }

        // scale + ALiBi, row max
        float mx0 = -1e30f, mx1 = -1e30f;
#pragma unroll
        for (int nt = 0; nt < 8; nt++) {
            int colb = kt*64 + nt*8 + t2;
            float d00 = fminf(0.0f, (float)(colb     - rowg));
            float d01 = fminf(0.0f, (float)(colb + 1 - rowg));
            float d10 = fminf(0.0f, (float)(colb     - rowg - 8));
            float d11 = fminf(0.0f, (float)(colb + 1 - rowg - 8));
            s[nt][0] = s[nt][0]*0.125f + slope8*d00;
            s[nt][1] = s[nt][1]*0.125f + slope8*d01;
            s[nt][2] = s[nt][2]*0.125f + slope8*d10;
            s[nt][3] = s[nt][3]*0.125f + slope8*d11;
            mx0 = fmaxf(mx0, fmaxf(s[nt][0], s[nt][1]));
            mx1 = fmaxf(mx1, fmaxf(s[nt][2], s[nt][3]));
        }
#pragma unroll
        for (int off = 1; off <= 2; off <<= 1) {
            mx0 = fmaxf(mx0, __shfl_xor_sync(0xffffffffu, mx0, off));
            mx1 = fmaxf(mx1, __shfl_xor_sync(0xffffffffu, mx1, off));
        }
        float nm0 = fmaxf(m0, mx0), nm1 = fmaxf(m1, mx1);
        float f0 = __expf(m0 - nm0), f1 = __expf(m1 - nm1);
        m0 = nm0; m1 = nm1;

        float sum0 = 0.0f, sum1 = 0.0f;
#pragma unroll
        for (int nt = 0; nt < 8; nt++) {
            float p0 = __expf(s[nt][0] - nm0);
            float p1 = __expf(s[nt][1] - nm0);
            float p2 = __expf(s[nt][2] - nm1);
            float p3 = __expf(s[nt][3] - nm1);
            sum0 += p0 + p1; sum1 += p2 + p3;
            bf162 lo0, lo1;
            bf162 hi0 = pack_split(p0, p1, lo0);
            bf162 hi1 = pack_split(p2, p3, lo1);
            int r0i = wid*16 + g;
            *(bf162*)(sPh + r0i*ALD + nt*8 + t2)      = hi0;
            *(bf162*)(sPl + r0i*ALD + nt*8 + t2)      = lo0;
            *(bf162*)(sPh + (r0i+8)*ALD + nt*8 + t2)  = hi1;
            *(bf162*)(sPl + (r0i+8)*ALD + nt*8 + t2)  = lo1;
        }
#pragma unroll
        for (int off = 1; off <= 2; off <<= 1) {
            sum0 += __shfl_xor_sync(0xffffffffu, sum0, off);
            sum1 += __shfl_xor_sync(0xffffffffu, sum1, off);
        }
        l0 = l0*f0 + sum0;
        l1 = l1*f1 + sum1;
#pragma unroll
        for (int nt = 0; nt < 8; nt++) {
            o[nt][0] *= f0; o[nt][1] *= f0;
            o[nt][2] *= f1; o[nt][3] *= f1;
        }
        __syncwarp();

        // O += P V  (3-mma split; P rows belong to this warp only)
#pragma unroll
        for (int ks = 0; ks < 4; ks++) {
            uint32_t ph[4], pl[4];
            lda_frag(ph, sPh, wid*16, ks*16, ALD);
            lda_frag(pl, sPl, wid*16, ks*16, ALD);
#pragma unroll
            for (int nt = 0; nt < 8; nt++) {
                uint32_t vh2[2], vl2[2];
                ldb_frag(vh2, sVh, nt*8, ks*16, ALD);
                ldb_frag(vl2, sVl, nt*8, ks*16, ALD);
                mma_bf16(o[nt], ph, vh2);
                mma_bf16(o[nt], ph, vl2);
                mma_bf16(o[nt], pl, vh2);
            }
        }
    }

    // epilogue: normalize, split, store to ao planes [B, N, H*D]
    float i0 = 1.0f / l0, i1 = 1.0f / l1;
#pragma unroll
    for (int nt = 0; nt < 8; nt++) {
        int col = h*64 + nt*8 + t2;
        size_t idx0 = ((size_t)b*NSEQ + rowg)*CDIM + col;
        size_t idx1 = idx0 + 8*CDIM;
        bf162 lo0, lo1;
        bf162 hi0 = pack_split(o[nt][0]*i0, o[nt][1]*i0, lo0);
        bf162 hi1 = pack_split(o[nt][2]*i1, o[nt][3]*i1, lo1);
        *(bf162*)(g_aohi + idx0) = hi0; *(bf162*)(g_aolo + idx0) = lo0;
        *(bf162*)(g_aohi + idx1) = hi1; *(bf162*)(g_aolo + idx1) = lo1;
    }
}

// ---------------- output projection ---------------------------------------
__global__ __launch_bounds__(256, 2) void proj_mma_kernel(
    const float* __restrict__ bias, float* __restrict__ out)
{
    __shared__ bf16 smem[4*128*GLDS];
    float c[4][4][4];
#pragma unroll
    for (int a = 0; a < 4; a++)
#pragma unroll
        for (int b = 0; b < 4; b++)
#pragma unroll
            for (int d = 0; d < 4; d++) c[a][b][d] = 0.0f;

    const int rowBase = blockIdx.y * 128, colBase = blockIdx.x * 128;
    gemm_tile(g_aohi + (size_t)rowBase*1024, g_aolo + (size_t)rowBase*1024,
              g_wphi + (size_t)colBase*1024, g_wplo + (size_t)colBase*1024,
              smem, c);

    const int lane = threadIdx.x & 31, wid = threadIdx.x >> 5;
    const int wm = wid >> 2, wn = wid & 3;
    const int g = lane >> 2, t2 = (lane & 3) << 1;

#pragma unroll
    for (int mi = 0; mi < 4; mi++) {
        int row = rowBase + wm*64 + mi*16 + g;
#pragma unroll
        for (int ni = 0; ni < 4; ni++) {
            int colg = colBase + wn*32 + ni*8 + t2;
            float b0 = bias[colg], b1 = bias[colg+1];
            float* f = c[mi][ni];
            *(float2*)(out + (size_t)row*CDIM + colg)     = make_float2(f[0]+b0, f[1]+b1);
            *(float2*)(out + (size_t)(row+8)*CDIM + colg) = make_float2(f[2]+b0, f[3]+b1);
        }
    }
}

// ---------------------------------------------------------------------------
extern "C" void kernel_launch(void* const* d_in, const int* in_sizes, int n_in,
                              void* d_out, int out_size)
{
    const float* x      = (const float*)d_in[0];
    const float* qkv_w  = (const float*)d_in[1];
    const float* proj_w = (const float*)d_in[2];
    const float* proj_b = (const float*)d_in[3];
    const float* slopes = (const float*)d_in[4];
    float* out = (float*)d_out;

    bf16 *xhi, *xlo, *wqhi, *wqlo, *wphi, *wplo;
    cudaGetSymbolAddress((void**)&xhi,  g_xhi);  cudaGetSymbolAddress((void**)&xlo,  g_xlo);
    cudaGetSymbolAddress((void**)&wqhi, g_wqhi); cudaGetSymbolAddress((void**)&wqlo, g_wqlo);
    cudaGetSymbolAddress((void**)&wphi, g_wphi); cudaGetSymbolAddress((void**)&wplo, g_wplo);

    split_kernel<<<MTOK*CDIM/1024, 256>>>(x, xhi, xlo);
    split_kernel<<<3*CDIM*CDIM/1024, 256>>>(qkv_w, wqhi, wqlo);
    split_kernel<<<CDIM*CDIM/1024, 256>>>(proj_w, wphi, wplo);

    qkv_mma_kernel<<<dim3(3072/128, MTOK/128), 256>>>();
    rope_split_kernel<<<2*BATCH*HEADS*NSEQ*32/256, 256>>>();

    cudaFuncSetAttribute(attn_mma_kernel,
                         cudaFuncAttributeMaxDynamicSharedMemorySize, ATTN_SMEM);
    attn_mma_kernel<<<dim3(NSEQ/128, HEADS, BATCH), 256, ATTN_SMEM>>>(slopes);

    proj_mma_kernel<<<dim3(CDIM/128, MTOK/128), 256>>>(proj_b, out);
}

// round 5
// speedup vs baseline: 2.6272x; 1.2581x over previous
#include <cuda_runtime.h>
#include <cuda_bf16.h>
#include <cstdint>
#include <math.h>

#define NSEQ   2048
#define BATCH  2
#define HEADS  16
#define HD     64
#define CDIM   1024
#define MTOK   (BATCH*NSEQ)      // 4096

typedef __nv_bfloat16  bf16;
typedef __nv_bfloat162 bf162;

// ---------------- device scratch (no allocations allowed) ------------------
__device__ __align__(16) bf16 g_xhi[MTOK*CDIM],  g_xlo[MTOK*CDIM];
__device__ __align__(16) bf16 g_wqhi[3*CDIM*CDIM], g_wqlo[3*CDIM*CDIM];
__device__ __align__(16) bf16 g_wphi[CDIM*CDIM],  g_wplo[CDIM*CDIM];
__device__ __align__(16) float g_qf[MTOK*CDIM], g_kf[MTOK*CDIM];
__device__ __align__(16) bf16 g_qhi[MTOK*CDIM], g_qlo[MTOK*CDIM];
__device__ __align__(16) bf16 g_khi[MTOK*CDIM], g_klo[MTOK*CDIM];
__device__ __align__(16) bf16 g_vhi[MTOK*CDIM], g_vlo[MTOK*CDIM];
__device__ __align__(16) bf16 g_aohi[MTOK*CDIM], g_aolo[MTOK*CDIM];

// ======================= helpers ===========================================
__device__ __forceinline__ bf162 pack_split(float a, float b, bf162& lo) {
    bf16 ha = __float2bfloat16_rn(a);
    bf16 hb = __float2bfloat16_rn(b);
    lo.x = __float2bfloat16_rn(a - __bfloat162float(ha));
    lo.y = __float2bfloat16_rn(b - __bfloat162float(hb));
    bf162 hi; hi.x = ha; hi.y = hb; return hi;
}

__device__ __forceinline__ void mma_bf16(float c[4], const uint32_t a[4], const uint32_t b[2]) {
    asm volatile(
        "mma.sync.aligned.m16n8k16.row.col.f32.bf16.bf16.f32 "
        "{%0,%1,%2,%3}, {%4,%5,%6,%7}, {%8,%9}, {%0,%1,%2,%3};\n"
        : "+f"(c[0]), "+f"(c[1]), "+f"(c[2]), "+f"(c[3])
        : "r"(a[0]), "r"(a[1]), "r"(a[2]), "r"(a[3]), "r"(b[0]), "r"(b[1]));
}

// A fragment (m16 x k16, row-major in smem)
__device__ __forceinline__ void lda_frag(uint32_t r[4], const bf16* base, int row0, int col0, int ld) {
    const int lane = threadIdx.x & 31;
    const bf16* p = base + (row0 + (lane & 15)) * ld + col0 + ((lane >> 4) << 3);
    uint32_t a = (uint32_t)__cvta_generic_to_shared(p);
    asm volatile("ldmatrix.sync.aligned.m8n8.x4.shared.b16 {%0,%1,%2,%3}, [%4];"
                 : "=r"(r[0]), "=r"(r[1]), "=r"(r[2]), "=r"(r[3]) : "r"(a));
}

// TWO B fragments (k16 x n8 each) for n0..n0+15, smem holds B^T row-major (rows=n, cols=k)
__device__ __forceinline__ void ldbx4(uint32_t r[4], const bf16* base, int n0, int k0, int ld) {
    const int lane = threadIdx.x & 31;
    const bf16* p = base + (n0 + ((lane >> 4) << 3) + (lane & 7)) * ld
                         + k0 + (((lane >> 3) & 1) << 3);
    uint32_t a = (uint32_t)__cvta_generic_to_shared(p);
    asm volatile("ldmatrix.sync.aligned.m8n8.x4.shared.b16 {%0,%1,%2,%3}, [%4];"
                 : "=r"(r[0]), "=r"(r[1]), "=r"(r[2]), "=r"(r[3]) : "r"(a));
}

// TWO B fragments from NATURAL row-major B [k][n] via trans (for V)
__device__ __forceinline__ void ldbx4t(uint32_t r[4], const bf16* base, int n0, int k0, int ld) {
    const int lane = threadIdx.x & 31;
    const bf16* p = base + (k0 + (lane & 15)) * ld + n0 + ((lane >> 4) << 3);
    uint32_t a = (uint32_t)__cvta_generic_to_shared(p);
    asm volatile("ldmatrix.sync.aligned.m8n8.x4.trans.shared.b16 {%0,%1,%2,%3}, [%4];"
                 : "=r"(r[0]), "=r"(r[1]), "=r"(r[2]), "=r"(r[3]) : "r"(a));
}

__device__ __forceinline__ void cp_async16(uint32_t saddr, const void* gaddr) {
    asm volatile("cp.async.cg.shared.global [%0], [%1], 16;" :: "r"(saddr), "l"(gaddr));
}
#define CP_COMMIT()  asm volatile("cp.async.commit_group;" ::: "memory")
#define CP_WAIT(n)   asm volatile("cp.async.wait_group %0;" :: "n"(n) : "memory")

// ---------------- fp32 -> (hi,lo) bf16 split ------------------------------
__global__ __launch_bounds__(256) void split_kernel(
    const float* __restrict__ in, bf16* __restrict__ hi, bf16* __restrict__ lo)
{
    int i = blockIdx.x * 256 + threadIdx.x;
    float4 v = ((const float4*)in)[i];
    bf162 l0, l1;
    bf162 h0 = pack_split(v.x, v.y, l0);
    bf162 h1 = pack_split(v.z, v.w, l1);
    ((bf162*)hi)[2*i]   = h0;  ((bf162*)hi)[2*i+1] = h1;
    ((bf162*)lo)[2*i]   = l0;  ((bf162*)lo)[2*i+1] = l1;
}

// ================= double-buffered split-bf16 GEMM tile =====================
// 128x128 tile, K=1024 in 32 chunks of 32 cols. 2 stages x 4 planes x 128x40.
#define GLDS    40
#define G_PLANE (128*GLDS)          // 5120 elements
#define G_STAGE (4*G_PLANE)         // 20480 elements
#define G_SMEM  (2*G_STAGE*2)       // 81920 bytes

__device__ __forceinline__ void g_prefetch(
    uint32_t smem_u32, int c,
    const bf16* A0, const bf16* A1, const bf16* B0, const bf16* B1)
{
    const int tid = threadIdx.x;
    uint32_t sb = smem_u32 + (c & 1) * (G_STAGE * 2);
    const bf16* gp[4] = {A0, A1, B0, B1};
#pragma unroll
    for (int i = 0; i < 8; i++) {
        int idx = tid + i * 256;            // 0..2047
        int p = idx >> 9;                   // plane
        int r = (idx >> 2) & 127;           // row
        int seg = idx & 3;                  // 16B segment within 32 cols
        const bf16* g = gp[p] + (size_t)r * 1024 + c * 32 + seg * 8;
        uint32_t d = sb + p * (G_PLANE * 2) + r * (GLDS * 2) + seg * 16;
        cp_async16(d, g);
    }
    CP_COMMIT();
}

__device__ __forceinline__ void gemm_tile2(
    const bf16* __restrict__ Ah, const bf16* __restrict__ Al,
    const bf16* __restrict__ Bh, const bf16* __restrict__ Bl,
    bf16* smem, float c[4][4][4])
{
    uint32_t smem_u32 = (uint32_t)__cvta_generic_to_shared(smem);
    const int wid = threadIdx.x >> 5;
    const int wm = wid >> 2, wn = wid & 3;

    g_prefetch(smem_u32, 0, Ah, Al, Bh, Bl);

    for (int ch = 0; ch < 32; ch++) {
        if (ch + 1 < 32) {
            g_prefetch(smem_u32, ch + 1, Ah, Al, Bh, Bl);
            CP_WAIT(1);
        } else {
            CP_WAIT(0);
        }
        __syncthreads();

        bf16* st  = smem + (ch & 1) * G_STAGE;
        bf16* sAh = st;
        bf16* sAl = st + G_PLANE;
        bf16* sBh = st + 2 * G_PLANE;
        bf16* sBl = st + 3 * G_PLANE;

#pragma unroll
        for (int ks = 0; ks < 32; ks += 16) {
            uint32_t bh4[2][4], bl4[2][4];
#pragma unroll
            for (int ntp = 0; ntp < 2; ntp++) {
                ldbx4(bh4[ntp], sBh, wn * 32 + ntp * 16, ks, GLDS);
                ldbx4(bl4[ntp], sBl, wn * 32 + ntp * 16, ks, GLDS);
            }
#pragma unroll
            for (int mi = 0; mi < 4; mi++) {
                uint32_t ah[4], al[4];
                lda_frag(ah, sAh, wm * 64 + mi * 16, ks, GLDS);
                lda_frag(al, sAl, wm * 64 + mi * 16, ks, GLDS);
#pragma unroll
                for (int ni = 0; ni < 4; ni++) {
                    const uint32_t* bh2 = &bh4[ni >> 1][(ni & 1) * 2];
                    const uint32_t* bl2 = &bl4[ni >> 1][(ni & 1) * 2];
                    mma_bf16(c[mi][ni], ah, bh2);
                    mma_bf16(c[mi][ni], ah, bl2);
                    mma_bf16(c[mi][ni], al, bh2);
                }
            }
        }
        __syncthreads();
    }
}

// ---------------- QKV GEMM + scatter epilogue ------------------------------
__global__ __launch_bounds__(256, 2) void qkv_mma_kernel()
{
    extern __shared__ bf16 gsm[];
    float c[4][4][4];
#pragma unroll
    for (int a = 0; a < 4; a++)
#pragma unroll
        for (int b = 0; b < 4; b++)
#pragma unroll
            for (int d = 0; d < 4; d++) c[a][b][d] = 0.0f;

    const int rowBase = blockIdx.y * 128, colBase = blockIdx.x * 128;
    gemm_tile2(g_xhi + (size_t)rowBase*1024, g_xlo + (size_t)rowBase*1024,
               g_wqhi + (size_t)colBase*1024, g_wqlo + (size_t)colBase*1024,
               gsm, c);

    const int lane = threadIdx.x & 31, wid = threadIdx.x >> 5;
    const int wm = wid >> 2, wn = wid & 3;
    const int g = lane >> 2, t2 = (lane & 3) << 1;
    const int tix = colBase >> 10;   // 0=q, 1=k, 2=v (uniform per block)

#pragma unroll
    for (int mi = 0; mi < 4; mi++) {
        int row = rowBase + wm*64 + mi*16 + g;
        int bb = row >> 11, n = row & 2047;
#pragma unroll
        for (int ni = 0; ni < 4; ni++) {
            int colg = colBase + wn*32 + ni*8 + t2;
            int rem = colg & 1023, hh = rem >> 6, d = rem & 63;
            size_t base0 = (((size_t)(bb * HEADS + hh)) * NSEQ + n) * HD + d;
            size_t base1 = base0 + 8*HD;
            float* f = c[mi][ni];
            if (tix == 0) {
                *(float2*)(g_qf + base0) = make_float2(f[0], f[1]);
                *(float2*)(g_qf + base1) = make_float2(f[2], f[3]);
            } else if (tix == 1) {
                *(float2*)(g_kf + base0) = make_float2(f[0], f[1]);
                *(float2*)(g_kf + base1) = make_float2(f[2], f[3]);
            } else {
                bf162 l0, l1;
                bf162 h0 = pack_split(f[0], f[1], l0);
                bf162 h1 = pack_split(f[2], f[3], l1);
                *(bf162*)(g_vhi + base0) = h0; *(bf162*)(g_vlo + base0) = l0;
                *(bf162*)(g_vhi + base1) = h1; *(bf162*)(g_vlo + base1) = l1;
            }
        }
    }
}

// ---------------- output projection ---------------------------------------
__global__ __launch_bounds__(256, 2) void proj_mma_kernel(
    const float* __restrict__ bias, float* __restrict__ out)
{
    extern __shared__ bf16 gsm[];
    float c[4][4][4];
#pragma unroll
    for (int a = 0; a < 4; a++)
#pragma unroll
        for (int b = 0; b < 4; b++)
#pragma unroll
            for (int d = 0; d < 4; d++) c[a][b][d] = 0.0f;

    const int rowBase = blockIdx.y * 128, colBase = blockIdx.x * 128;
    gemm_tile2(g_aohi + (size_t)rowBase*1024, g_aolo + (size_t)rowBase*1024,
               g_wphi + (size_t)colBase*1024, g_wplo + (size_t)colBase*1024,
               gsm, c);

    const int lane = threadIdx.x & 31, wid = threadIdx.x >> 5;
    const int wm = wid >> 2, wn = wid & 3;
    const int g = lane >> 2, t2 = (lane & 3) << 1;

#pragma unroll
    for (int mi = 0; mi < 4; mi++) {
        int row = rowBase + wm*64 + mi*16 + g;
#pragma unroll
        for (int ni = 0; ni < 4; ni++) {
            int colg = colBase + wn*32 + ni*8 + t2;
            float b0 = bias[colg], b1 = bias[colg+1];
            float* f = c[mi][ni];
            *(float2*)(out + (size_t)row*CDIM + colg)     = make_float2(f[0]+b0, f[1]+b1);
            *(float2*)(out + (size_t)(row+8)*CDIM + colg) = make_float2(f[2]+b0, f[3]+b1);
        }
    }
}

// ---------------- RoPE + split -------------------------------------------
__global__ __launch_bounds__(256) void rope_split_kernel()
{
    const int per = BATCH*HEADS*NSEQ*32;
    int idx = blockIdx.x*256 + threadIdx.x;
    bool isq = idx < per;
    int rem = isq ? idx : idx - per;
    int pair = rem & 31;
    int rowI = rem >> 5;
    int n = rowI & (NSEQ-1);

    float inv = powf(10000.0f, -(float)pair * (1.0f/32.0f));
    float s, cc;
    sincosf((float)n * inv, &s, &cc);

    const float* src = isq ? g_qf : g_kf;
    bf16* dh = isq ? g_qhi : g_khi;
    bf16* dl = isq ? g_qlo : g_klo;
    size_t p0 = (size_t)rowI*64 + pair;
    float t1 = src[p0], t2 = src[p0+32];
    float r1 = t1*cc - t2*s;
    float r2 = t2*cc + t1*s;
    bf16 h1 = __float2bfloat16_rn(r1);
    bf16 h2 = __float2bfloat16_rn(r2);
    dh[p0]    = h1; dl[p0]    = __float2bfloat16_rn(r1 - __bfloat162float(h1));
    dh[p0+32] = h2; dl[p0+32] = __float2bfloat16_rn(r2 - __bfloat162float(h2));
}

// ============ flash attention: double-buffered K/V + x4 ldmatrix ============
#define ALD     72
#define A_QH    0
#define A_QL    (128*ALD)                 // 9216
#define A_K     (2*128*ALD)               // 18432 ; stage s: +s*9216, lo plane +4608
#define A_V     (A_K + 2*2*64*ALD)        // 36864 ; same structure (natural [j][d])
#define A_PH    (A_V + 2*2*64*ALD)        // 55296
#define A_PL    (A_PH + 128*ALD)          // 64512
#define ATTN_SMEM ((A_PL + 128*ALD) * 2)  // 147456 bytes

__device__ __forceinline__ void attn_prefetch(uint32_t smem_u32, int kt, int bh)
{
    const int tid = threadIdx.x;
    const size_t koff = ((size_t)bh * NSEQ + kt * 64) * HD;
    uint32_t kb = smem_u32 + (A_K + (kt & 1) * 9216) * 2;
    uint32_t vb = smem_u32 + (A_V + (kt & 1) * 9216) * 2;
#pragma unroll
    for (int i = 0; i < 8; i++) {
        int idx = tid + i * 256;            // 0..2047
        int t = idx >> 9;                   // 0=kh,1=kl,2=vh,3=vl
        int r = (idx >> 3) & 63;
        int seg = idx & 7;
        const bf16* g = (t == 0 ? g_khi : t == 1 ? g_klo : t == 2 ? g_vhi : g_vlo)
                        + koff + r * 64 + seg * 8;
        uint32_t d = (t == 0 ? kb : t == 1 ? kb + 4608*2 : t == 2 ? vb : vb + 4608*2)
                     + r * (ALD * 2) + seg * 16;
        cp_async16(d, g);
    }
    CP_COMMIT();
}

__global__ __launch_bounds__(256, 1) void attn_mma_kernel(const float* __restrict__ slopes)
{
    extern __shared__ bf16 sm[];
    uint32_t smem_u32 = (uint32_t)__cvta_generic_to_shared(sm);
    bf16* sQh = sm + A_QH;
    bf16* sQl = sm + A_QL;
    bf16* sPh = sm + A_PH;
    bf16* sPl = sm + A_PL;

    const int tid = threadIdx.x, wid = tid >> 5, lane = tid & 31;
    const int g = lane >> 2, t2 = (lane & 3) << 1;
    const int qt = blockIdx.x, h = blockIdx.y, b = blockIdx.z;
    const int bh = b*HEADS + h;
    const float slope8 = slopes[h] * 8.0f;

    // load Q tile (128x64, both planes)
    const size_t qoff = ((size_t)bh*NSEQ + qt*128)*HD;
    for (int v = tid; v < 1024; v += 256) {
        int row = v >> 3, seg = (v & 7) << 3;
        *(uint4*)(sQh + row*ALD + seg) = *(const uint4*)(g_qhi + qoff + row*64 + seg);
        *(uint4*)(sQl + row*ALD + seg) = *(const uint4*)(g_qlo + qoff + row*64 + seg);
    }
    attn_prefetch(smem_u32, 0, bh);
    __syncthreads();

    // hoist Q fragments for all 4 k-steps
    uint32_t qh[4][4], ql[4][4];
#pragma unroll
    for (int ks = 0; ks < 4; ks++) {
        lda_frag(qh[ks], sQh, wid*16, ks*16, ALD);
        lda_frag(ql[ks], sQl, wid*16, ks*16, ALD);
    }

    float o[8][4];
#pragma unroll
    for (int nt = 0; nt < 8; nt++)
#pragma unroll
        for (int d = 0; d < 4; d++) o[nt][d] = 0.0f;
    float m0 = -1e30f, m1 = -1e30f, l0 = 0.0f, l1 = 0.0f;
    const int rowg = qt*128 + wid*16 + g;   // this thread's rows: rowg, rowg+8

    for (int kt = 0; kt < 32; kt++) {
        if (kt + 1 < 32) {
            attn_prefetch(smem_u32, kt + 1, bh);
            CP_WAIT(1);
        } else {
            CP_WAIT(0);
        }
        __syncthreads();

        bf16* sKh = sm + A_K + (kt & 1) * 9216;
        bf16* sKl = sKh + 4608;
        bf16* sVh = sm + A_V + (kt & 1) * 9216;
        bf16* sVl = sVh + 4608;

        // S = Q K^T (3-mma split)
        float s[8][4];
#pragma unroll
        for (int nt = 0; nt < 8; nt++)
#pragma unroll
            for (int d = 0; d < 4; d++) s[nt][d] = 0.0f;
#pragma unroll
        for (int ks = 0; ks < 4; ks++) {
#pragma unroll
            for (int ntp = 0; ntp < 4; ntp++) {
                uint32_t kh4[4], kl4[4];
                ldbx4(kh4, sKh, ntp*16, ks*16, ALD);
                ldbx4(kl4, sKl, ntp*16, ks*16, ALD);
                mma_bf16(s[2*ntp],   qh[ks], &kh4[0]);
                mma_bf16(s[2*ntp],   qh[ks], &kl4[0]);
                mma_bf16(s[2*ntp],   ql[ks], &kh4[0]);
                mma_bf16(s[2*ntp+1], qh[ks], &kh4[2]);
                mma_bf16(s[2*ntp+1], qh[ks], &kl4[2]);
                mma_bf16(s[2*ntp+1], ql[ks], &kh4[2]);
            }
        }

        // scale + ALiBi, row max
        float mx0 = -1e30f, mx1 = -1e30f;
#pragma unroll
        for (int nt = 0; nt < 8; nt++) {
            int colb = kt*64 + nt*8 + t2;
            float d00 = fminf(0.0f, (float)(colb     - rowg));
            float d01 = fminf(0.0f, (float)(colb + 1 - rowg));
            float d10 = fminf(0.0f, (float)(colb     - rowg - 8));
            float d11 = fminf(0.0f, (float)(colb + 1 - rowg - 8));
            s[nt][0] = s[nt][0]*0.125f + slope8*d00;
            s[nt][1] = s[nt][1]*0.125f + slope8*d01;
            s[nt][2] = s[nt][2]*0.125f + slope8*d10;
            s[nt][3] = s[nt][3]*0.125f + slope8*d11;
            mx0 = fmaxf(mx0, fmaxf(s[nt][0], s[nt][1]));
            mx1 = fmaxf(mx1, fmaxf(s[nt][2], s[nt][3]));
        }
#pragma unroll
        for (int off = 1; off <= 2; off <<= 1) {
            mx0 = fmaxf(mx0, __shfl_xor_sync(0xffffffffu, mx0, off));
            mx1 = fmaxf(mx1, __shfl_xor_sync(0xffffffffu, mx1, off));
        }
        float nm0 = fmaxf(m0, mx0), nm1 = fmaxf(m1, mx1);
        float f0 = __expf(m0 - nm0), f1 = __expf(m1 - nm1);
        m0 = nm0; m1 = nm1;

        float sum0 = 0.0f, sum1 = 0.0f;
#pragma unroll
        for (int nt = 0; nt < 8; nt++) {
            float p0 = __expf(s[nt][0] - nm0);
            float p1 = __expf(s[nt][1] - nm0);
            float p2 = __expf(s[nt][2] - nm1);
            float p3 = __expf(s[nt][3] - nm1);
            sum0 += p0 + p1; sum1 += p2 + p3;
            bf162 lo0, lo1;
            bf162 hi0 = pack_split(p0, p1, lo0);
            bf162 hi1 = pack_split(p2, p3, lo1);
            int r0i = wid*16 + g;
            *(bf162*)(sPh + r0i*ALD + nt*8 + t2)      = hi0;
            *(bf162*)(sPl + r0i*ALD + nt*8 + t2)      = lo0;
            *(bf162*)(sPh + (r0i+8)*ALD + nt*8 + t2)  = hi1;
            *(bf162*)(sPl + (r0i+8)*ALD + nt*8 + t2)  = lo1;
        }
#pragma unroll
        for (int off = 1; off <= 2; off <<= 1) {
            sum0 += __shfl_xor_sync(0xffffffffu, sum0, off);
            sum1 += __shfl_xor_sync(0xffffffffu, sum1, off);
        }
        l0 = l0*f0 + sum0;
        l1 = l1*f1 + sum1;
#pragma unroll
        for (int nt = 0; nt < 8; nt++) {
            o[nt][0] *= f0; o[nt][1] *= f0;
            o[nt][2] *= f1; o[nt][3] *= f1;
        }
        __syncwarp();

        // O += P V  (V natural layout, trans ldmatrix; 3-mma split)
#pragma unroll
        for (int ks = 0; ks < 4; ks++) {
            uint32_t ph[4], pl[4];
            lda_frag(ph, sPh, wid*16, ks*16, ALD);
            lda_frag(pl, sPl, wid*16, ks*16, ALD);
#pragma unroll
            for (int ntp = 0; ntp < 4; ntp++) {
                uint32_t vh4[4], vl4[4];
                ldbx4t(vh4, sVh, ntp*16, ks*16, ALD);
                ldbx4t(vl4, sVl, ntp*16, ks*16, ALD);
                mma_bf16(o[2*ntp],   ph, &vh4[0]);
                mma_bf16(o[2*ntp],   ph, &vl4[0]);
                mma_bf16(o[2*ntp],   pl, &vh4[0]);
                mma_bf16(o[2*ntp+1], ph, &vh4[2]);
                mma_bf16(o[2*ntp+1], ph, &vl4[2]);
                mma_bf16(o[2*ntp+1], pl, &vh4[2]);
            }
        }
        __syncthreads();
    }

    // epilogue: normalize, split, store to ao planes [B, N, H*D]
    float i0 = 1.0f / l0, i1 = 1.0f / l1;
#pragma unroll
    for (int nt = 0; nt < 8; nt++) {
        int col = h*64 + nt*8 + t2;
        size_t idx0 = ((size_t)b*NSEQ + rowg)*CDIM + col;
        size_t idx1 = idx0 + 8*CDIM;
        bf162 lo0, lo1;
        bf162 hi0 = pack_split(o[nt][0]*i0, o[nt][1]*i0, lo0);
        bf162 hi1 = pack_split(o[nt][2]*i1, o[nt][3]*i1, lo1);
        *(bf162*)(g_aohi + idx0) = hi0; *(bf162*)(g_aolo + idx0) = lo0;
        *(bf162*)(g_aohi + idx1) = hi1; *(bf162*)(g_aolo + idx1) = lo1;
    }
}

// ---------------------------------------------------------------------------
extern "C" void kernel_launch(void* const* d_in, const int* in_sizes, int n_in,
                              void* d_out, int out_size)
{
    const float* x      = (const float*)d_in[0];
    const float* qkv_w  = (const float*)d_in[1];
    const float* proj_w = (const float*)d_in[2];
    const float* proj_b = (const float*)d_in[3];
    const float* slopes = (const float*)d_in[4];
    float* out = (float*)d_out;

    bf16 *xhi, *xlo, *wqhi, *wqlo, *wphi, *wplo;
    cudaGetSymbolAddress((void**)&xhi,  g_xhi);  cudaGetSymbolAddress((void**)&xlo,  g_xlo);
    cudaGetSymbolAddress((void**)&wqhi, g_wqhi); cudaGetSymbolAddress((void**)&wqlo, g_wqlo);
    cudaGetSymbolAddress((void**)&wphi, g_wphi); cudaGetSymbolAddress((void**)&wplo, g_wplo);

    split_kernel<<<MTOK*CDIM/1024, 256>>>(x, xhi, xlo);
    split_kernel<<<3*CDIM*CDIM/1024, 256>>>(qkv_w, wqhi, wqlo);
    split_kernel<<<CDIM*CDIM/1024, 256>>>(proj_w, wphi, wplo);

    cudaFuncSetAttribute(qkv_mma_kernel,
                         cudaFuncAttributeMaxDynamicSharedMemorySize, G_SMEM);
    qkv_mma_kernel<<<dim3(3072/128, MTOK/128), 256, G_SMEM>>>();

    rope_split_kernel<<<2*BATCH*HEADS*NSEQ*32/256, 256>>>();

    cudaFuncSetAttribute(attn_mma_kernel,
                         cudaFuncAttributeMaxDynamicSharedMemorySize, ATTN_SMEM);
    attn_mma_kernel<<<dim3(NSEQ/128, HEADS, BATCH), 256, ATTN_SMEM>>>(slopes);

    cudaFuncSetAttribute(proj_mma_kernel,
                         cudaFuncAttributeMaxDynamicSharedMemorySize, G_SMEM);
    proj_mma_kernel<<<dim3(CDIM/128, MTOK/128), 256, G_SMEM>>>(proj_b, out);
}

// round 6
// speedup vs baseline: 2.8477x; 1.0839x over previous
#include <cuda_runtime.h>
#include <cuda_bf16.h>
#include <cstdint>
#include <math.h>

#define NSEQ   2048
#define BATCH  2
#define HEADS  16
#define HD     64
#define CDIM   1024
#define MTOK   (BATCH*NSEQ)      // 4096

typedef __nv_bfloat16  bf16;
typedef __nv_bfloat162 bf162;

// ---------------- device scratch (no allocations allowed) ------------------
__device__ __align__(16) bf16 g_xhi[MTOK*CDIM],  g_xlo[MTOK*CDIM];
__device__ __align__(16) bf16 g_wqhi[3*CDIM*CDIM], g_wqlo[3*CDIM*CDIM];
__device__ __align__(16) bf16 g_wphi[CDIM*CDIM],  g_wplo[CDIM*CDIM];
__device__ __align__(16) float g_qf[MTOK*CDIM], g_kf[MTOK*CDIM];
__device__ __align__(16) bf16 g_qhi[MTOK*CDIM], g_qlo[MTOK*CDIM];
__device__ __align__(16) bf16 g_khi[MTOK*CDIM], g_klo[MTOK*CDIM];
__device__ __align__(16) bf16 g_vhi[MTOK*CDIM], g_vlo[MTOK*CDIM];
__device__ __align__(16) bf16 g_aohi[MTOK*CDIM], g_aolo[MTOK*CDIM];

// ======================= helpers ===========================================
__device__ __forceinline__ bf162 pack_split(float a, float b, bf162& lo) {
    bf16 ha = __float2bfloat16_rn(a);
    bf16 hb = __float2bfloat16_rn(b);
    lo.x = __float2bfloat16_rn(a - __bfloat162float(ha));
    lo.y = __float2bfloat16_rn(b - __bfloat162float(hb));
    bf162 hi; hi.x = ha; hi.y = hb; return hi;
}

__device__ __forceinline__ uint32_t b2u(bf162 v) {
    union { bf162 b; uint32_t u; } cvt; cvt.b = v; return cvt.u;
}

__device__ __forceinline__ void mma_bf16(float c[4], const uint32_t a[4], const uint32_t b[2]) {
    asm volatile(
        "mma.sync.aligned.m16n8k16.row.col.f32.bf16.bf16.f32 "
        "{%0,%1,%2,%3}, {%4,%5,%6,%7}, {%8,%9}, {%0,%1,%2,%3};\n"
        : "+f"(c[0]), "+f"(c[1]), "+f"(c[2]), "+f"(c[3])
        : "r"(a[0]), "r"(a[1]), "r"(a[2]), "r"(a[3]), "r"(b[0]), "r"(b[1]));
}

// A fragment (m16 x k16, row-major in smem)
__device__ __forceinline__ void lda_frag(uint32_t r[4], const bf16* base, int row0, int col0, int ld) {
    const int lane = threadIdx.x & 31;
    const bf16* p = base + (row0 + (lane & 15)) * ld + col0 + ((lane >> 4) << 3);
    uint32_t a = (uint32_t)__cvta_generic_to_shared(p);
    asm volatile("ldmatrix.sync.aligned.m8n8.x4.shared.b16 {%0,%1,%2,%3}, [%4];"
                 : "=r"(r[0]), "=r"(r[1]), "=r"(r[2]), "=r"(r[3]) : "r"(a));
}

// TWO B fragments (k16 x n8 each) for n0..n0+15; smem holds B^T row-major (rows=n, cols=k)
__device__ __forceinline__ void ldbx4(uint32_t r[4], const bf16* base, int n0, int k0, int ld) {
    const int lane = threadIdx.x & 31;
    const bf16* p = base + (n0 + ((lane >> 4) << 3) + (lane & 7)) * ld
                         + k0 + (((lane >> 3) & 1) << 3);
    uint32_t a = (uint32_t)__cvta_generic_to_shared(p);
    asm volatile("ldmatrix.sync.aligned.m8n8.x4.shared.b16 {%0,%1,%2,%3}, [%4];"
                 : "=r"(r[0]), "=r"(r[1]), "=r"(r[2]), "=r"(r[3]) : "r"(a));
}

// TWO B fragments from NATURAL row-major B [k][n] via trans (for V)
__device__ __forceinline__ void ldbx4t(uint32_t r[4], const bf16* base, int n0, int k0, int ld) {
    const int lane = threadIdx.x & 31;
    const bf16* p = base + (k0 + (lane & 15)) * ld + n0 + ((lane >> 4) << 3);
    uint32_t a = (uint32_t)__cvta_generic_to_shared(p);
    asm volatile("ldmatrix.sync.aligned.m8n8.x4.trans.shared.b16 {%0,%1,%2,%3}, [%4];"
                 : "=r"(r[0]), "=r"(r[1]), "=r"(r[2]), "=r"(r[3]) : "r"(a));
}

__device__ __forceinline__ void cp_async16(uint32_t saddr, const void* gaddr) {
    asm volatile("cp.async.cg.shared.global [%0], [%1], 16;" :: "r"(saddr), "l"(gaddr));
}
#define CP_COMMIT()  asm volatile("cp.async.commit_group;" ::: "memory")
#define CP_WAIT(n)   asm volatile("cp.async.wait_group %0;" :: "n"(n) : "memory")

// ---------------- fp32 -> (hi,lo) bf16 split ------------------------------
__global__ __launch_bounds__(256) void split_kernel(
    const float* __restrict__ in, bf16* __restrict__ hi, bf16* __restrict__ lo)
{
    int i = blockIdx.x * 256 + threadIdx.x;
    float4 v = ((const float4*)in)[i];
    bf162 l0, l1;
    bf162 h0 = pack_split(v.x, v.y, l0);
    bf162 h1 = pack_split(v.z, v.w, l1);
    ((bf162*)hi)[2*i]   = h0;  ((bf162*)hi)[2*i+1] = h1;
    ((bf162*)lo)[2*i]   = l0;  ((bf162*)lo)[2*i+1] = l1;
}

// ================= double-buffered split-bf16 GEMM tile =====================
#define GLDS    40
#define G_PLANE (128*GLDS)
#define G_STAGE (4*G_PLANE)
#define G_SMEM  (2*G_STAGE*2)       // 81920 bytes

__device__ __forceinline__ void g_prefetch(
    uint32_t smem_u32, int c,
    const bf16* A0, const bf16* A1, const bf16* B0, const bf16* B1)
{
    const int tid = threadIdx.x;
    uint32_t sb = smem_u32 + (c & 1) * (G_STAGE * 2);
    const bf16* gp[4] = {A0, A1, B0, B1};
#pragma unroll
    for (int i = 0; i < 8; i++) {
        int idx = tid + i * 256;
        int p = idx >> 9, r = (idx >> 2) & 127, seg = idx & 3;
        const bf16* g = gp[p] + (size_t)r * 1024 + c * 32 + seg * 8;
        uint32_t d = sb + p * (G_PLANE * 2) + r * (GLDS * 2) + seg * 16;
        cp_async16(d, g);
    }
    CP_COMMIT();
}

__device__ __forceinline__ void gemm_tile2(
    const bf16* __restrict__ Ah, const bf16* __restrict__ Al,
    const bf16* __restrict__ Bh, const bf16* __restrict__ Bl,
    bf16* smem, float c[4][4][4])
{
    uint32_t smem_u32 = (uint32_t)__cvta_generic_to_shared(smem);
    const int wid = threadIdx.x >> 5;
    const int wm = wid >> 2, wn = wid & 3;

    g_prefetch(smem_u32, 0, Ah, Al, Bh, Bl);

    for (int ch = 0; ch < 32; ch++) {
        if (ch + 1 < 32) {
            g_prefetch(smem_u32, ch + 1, Ah, Al, Bh, Bl);
            CP_WAIT(1);
        } else {
            CP_WAIT(0);
        }
        __syncthreads();

        bf16* st  = smem + (ch & 1) * G_STAGE;
        bf16* sAh = st;
        bf16* sAl = st + G_PLANE;
        bf16* sBh = st + 2 * G_PLANE;
        bf16* sBl = st + 3 * G_PLANE;

#pragma unroll
        for (int ks = 0; ks < 32; ks += 16) {
            uint32_t bh4[2][4], bl4[2][4];
#pragma unroll
            for (int ntp = 0; ntp < 2; ntp++) {
                ldbx4(bh4[ntp], sBh, wn * 32 + ntp * 16, ks, GLDS);
                ldbx4(bl4[ntp], sBl, wn * 32 + ntp * 16, ks, GLDS);
            }
#pragma unroll
            for (int mi = 0; mi < 4; mi++) {
                uint32_t ah[4], al[4];
                lda_frag(ah, sAh, wm * 64 + mi * 16, ks, GLDS);
                lda_frag(al, sAl, wm * 64 + mi * 16, ks, GLDS);
#pragma unroll
                for (int ni = 0; ni < 4; ni++) {
                    const uint32_t* bh2 = &bh4[ni >> 1][(ni & 1) * 2];
                    const uint32_t* bl2 = &bl4[ni >> 1][(ni & 1) * 2];
                    mma_bf16(c[mi][ni], ah, bh2);
                    mma_bf16(c[mi][ni], ah, bl2);
                    mma_bf16(c[mi][ni], al, bh2);
                }
            }
        }
        __syncthreads();
    }
}

// ---------------- QKV GEMM + scatter epilogue ------------------------------
__global__ __launch_bounds__(256, 2) void qkv_mma_kernel()
{
    extern __shared__ bf16 gsm[];
    float c[4][4][4];
#pragma unroll
    for (int a = 0; a < 4; a++)
#pragma unroll
        for (int b = 0; b < 4; b++)
#pragma unroll
            for (int d = 0; d < 4; d++) c[a][b][d] = 0.0f;

    const int rowBase = blockIdx.y * 128, colBase = blockIdx.x * 128;
    gemm_tile2(g_xhi + (size_t)rowBase*1024, g_xlo + (size_t)rowBase*1024,
               g_wqhi + (size_t)colBase*1024, g_wqlo + (size_t)colBase*1024,
               gsm, c);

    const int lane = threadIdx.x & 31, wid = threadIdx.x >> 5;
    const int wm = wid >> 2, wn = wid & 3;
    const int g = lane >> 2, t2 = (lane & 3) << 1;
    const int tix = colBase >> 10;

#pragma unroll
    for (int mi = 0; mi < 4; mi++) {
        int row = rowBase + wm*64 + mi*16 + g;
        int bb = row >> 11, n = row & 2047;
#pragma unroll
        for (int ni = 0; ni < 4; ni++) {
            int colg = colBase + wn*32 + ni*8 + t2;
            int rem = colg & 1023, hh = rem >> 6, d = rem & 63;
            size_t base0 = (((size_t)(bb * HEADS + hh)) * NSEQ + n) * HD + d;
            size_t base1 = base0 + 8*HD;
            float* f = c[mi][ni];
            if (tix == 0) {
                *(float2*)(g_qf + base0) = make_float2(f[0], f[1]);
                *(float2*)(g_qf + base1) = make_float2(f[2], f[3]);
            } else if (tix == 1) {
                *(float2*)(g_kf + base0) = make_float2(f[0], f[1]);
                *(float2*)(g_kf + base1) = make_float2(f[2], f[3]);
            } else {
                bf162 l0, l1;
                bf162 h0 = pack_split(f[0], f[1], l0);
                bf162 h1 = pack_split(f[2], f[3], l1);
                *(bf162*)(g_vhi + base0) = h0; *(bf162*)(g_vlo + base0) = l0;
                *(bf162*)(g_vhi + base1) = h1; *(bf162*)(g_vlo + base1) = l1;
            }
        }
    }
}

// ---------------- output projection ---------------------------------------
__global__ __launch_bounds__(256, 2) void proj_mma_kernel(
    const float* __restrict__ bias, float* __restrict__ out)
{
    extern __shared__ bf16 gsm[];
    float c[4][4][4];
#pragma unroll
    for (int a = 0; a < 4; a++)
#pragma unroll
        for (int b = 0; b < 4; b++)
#pragma unroll
            for (int d = 0; d < 4; d++) c[a][b][d] = 0.0f;

    const int rowBase = blockIdx.y * 128, colBase = blockIdx.x * 128;
    gemm_tile2(g_aohi + (size_t)rowBase*1024, g_aolo + (size_t)rowBase*1024,
               g_wphi + (size_t)colBase*1024, g_wplo + (size_t)colBase*1024,
               gsm, c);

    const int lane = threadIdx.x & 31, wid = threadIdx.x >> 5;
    const int wm = wid >> 2, wn = wid & 3;
    const int g = lane >> 2, t2 = (lane & 3) << 1;

#pragma unroll
    for (int mi = 0; mi < 4; mi++) {
        int row = rowBase + wm*64 + mi*16 + g;
#pragma unroll
        for (int ni = 0; ni < 4; ni++) {
            int colg = colBase + wn*32 + ni*8 + t2;
            float b0 = bias[colg], b1 = bias[colg+1];
            float* f = c[mi][ni];
            *(float2*)(out + (size_t)row*CDIM + colg)     = make_float2(f[0]+b0, f[1]+b1);
            *(float2*)(out + (size_t)(row+8)*CDIM + colg) = make_float2(f[2]+b0, f[3]+b1);
        }
    }
}

// ---------------- RoPE + split -------------------------------------------
__global__ __launch_bounds__(256) void rope_split_kernel()
{
    const int per = BATCH*HEADS*NSEQ*32;
    int idx = blockIdx.x*256 + threadIdx.x;
    bool isq = idx < per;
    int rem = isq ? idx : idx - per;
    int pair = rem & 31;
    int rowI = rem >> 5;
    int n = rowI & (NSEQ-1);

    float inv = powf(10000.0f, -(float)pair * (1.0f/32.0f));
    float s, cc;
    sincosf((float)n * inv, &s, &cc);

    const float* src = isq ? g_qf : g_kf;
    bf16* dh = isq ? g_qhi : g_khi;
    bf16* dl = isq ? g_qlo : g_klo;
    size_t p0 = (size_t)rowI*64 + pair;
    float t1 = src[p0], t2 = src[p0+32];
    float r1 = t1*cc - t2*s;
    float r2 = t2*cc + t1*s;
    bf16 h1 = __float2bfloat16_rn(r1);
    bf16 h2 = __float2bfloat16_rn(r2);
    dh[p0]    = h1; dl[p0]    = __float2bfloat16_rn(r1 - __bfloat162float(h1));
    dh[p0+32] = h2; dl[p0+32] = __float2bfloat16_rn(r2 - __bfloat162float(h2));
}

// ====== flash attention: register-resident P + smem region reuse ===========
// Two 36,864B regions. Region A (offset 0) first holds Q (Qh@0, Ql@+9216 el),
// then becomes the K/V stage for odd kt. Region B = K/V stage for even kt.
// K/V stage layout (elements from region base): Kh@0, Kl@4608, Vh@9216, Vl@13824.
#define ALD      72
#define REG_ELEM (4*64*ALD)          // 18432 elements = 36864 B
#define ATTN_SMEM (2*REG_ELEM*2)     // 73728 B -> 2 CTAs/SM

__device__ __forceinline__ void attn_prefetch(uint32_t smem_u32, int kt, int bh)
{
    const int tid = threadIdx.x;
    const size_t koff = ((size_t)bh * NSEQ + kt * 64) * HD;
    uint32_t base = smem_u32 + ((kt & 1) ? 0u : (uint32_t)(REG_ELEM * 2));
#pragma unroll
    for (int i = 0; i < 8; i++) {
        int idx = tid + i * 256;            // 0..2047
        int t = idx >> 9;                   // 0=kh,1=kl,2=vh,3=vl
        int r = (idx >> 3) & 63;
        int seg = idx & 7;
        const bf16* g = (t == 0 ? g_khi : t == 1 ? g_klo : t == 2 ? g_vhi : g_vlo)
                        + koff + r * 64 + seg * 8;
        uint32_t d = base + t * 9216 + r * (ALD * 2) + seg * 16;
        cp_async16(d, g);
    }
    CP_COMMIT();
}

__global__ __launch_bounds__(256, 2) void attn_mma_kernel(const float* __restrict__ slopes)
{
    extern __shared__ bf16 sm[];
    uint32_t smem_u32 = (uint32_t)__cvta_generic_to_shared(sm);

    const int tid = threadIdx.x, wid = tid >> 5, lane = tid & 31;
    const int g = lane >> 2, t2 = (lane & 3) << 1;
    const int qt = blockIdx.x, h = blockIdx.y, b = blockIdx.z;
    const int bh = b*HEADS + h;
    const float slope8 = slopes[h] * 8.0f;

    // load Q tile (128x64, both planes) into region A
    bf16* sQh = sm;
    bf16* sQl = sm + 9216;
    const size_t qoff = ((size_t)bh*NSEQ + qt*128)*HD;
    for (int v = tid; v < 1024; v += 256) {
        int row = v >> 3, seg = (v & 7) << 3;
        *(uint4*)(sQh + row*ALD + seg) = *(const uint4*)(g_qhi + qoff + row*64 + seg);
        *(uint4*)(sQl + row*ALD + seg) = *(const uint4*)(g_qlo + qoff + row*64 + seg);
    }
    attn_prefetch(smem_u32, 0, bh);      // kt=0 -> region B
    __syncthreads();

    // hoist Q fragments for all 4 k-steps
    uint32_t qh[4][4], ql[4][4];
#pragma unroll
    for (int ks = 0; ks < 4; ks++) {
        lda_frag(qh[ks], sQh, wid*16, ks*16, ALD);
        lda_frag(ql[ks], sQl, wid*16, ks*16, ALD);
    }
    __syncthreads();                     // region A free for kt=1 prefetch

    float o[8][4];
#pragma unroll
    for (int nt = 0; nt < 8; nt++)
#pragma unroll
        for (int d = 0; d < 4; d++) o[nt][d] = 0.0f;
    float m0 = -1e30f, m1 = -1e30f, l0 = 0.0f, l1 = 0.0f;
    const int rowg = qt*128 + wid*16 + g;   // this thread's rows: rowg, rowg+8

    for (int kt = 0; kt < 32; kt++) {
        if (kt + 1 < 32) {
            attn_prefetch(smem_u32, kt + 1, bh);
            CP_WAIT(1);
        } else {
            CP_WAIT(0);
        }
        __syncthreads();

        bf16* reg = sm + ((kt & 1) ? 0 : REG_ELEM);
        bf16* sKh = reg;
        bf16* sKl = reg + 4608;
        bf16* sVh = reg + 9216;
        bf16* sVl = reg + 13824;

        // S = Q K^T (3-mma split)
        float s[8][4];
#pragma unroll
        for (int nt = 0; nt < 8; nt++)
#pragma unroll
            for (int d = 0; d < 4; d++) s[nt][d] = 0.0f;
#pragma unroll
        for (int ks = 0; ks < 4; ks++) {
#pragma unroll
            for (int ntp = 0; ntp < 4; ntp++) {
                uint32_t kh4[4], kl4[4];
                ldbx4(kh4, sKh, ntp*16, ks*16, ALD);
                ldbx4(kl4, sKl, ntp*16, ks*16, ALD);
                mma_bf16(s[2*ntp],   qh[ks], &kh4[0]);
                mma_bf16(s[2*ntp],   qh[ks], &kl4[0]);
                mma_bf16(s[2*ntp],   ql[ks], &kh4[0]);
                mma_bf16(s[2*ntp+1], qh[ks], &kh4[2]);
                mma_bf16(s[2*ntp+1], qh[ks], &kl4[2]);
                mma_bf16(s[2*ntp+1], ql[ks], &kh4[2]);
            }
        }

        // scale + ALiBi, row max
        float mx0 = -1e30f, mx1 = -1e30f;
#pragma unroll
        for (int nt = 0; nt < 8; nt++) {
            int colb = kt*64 + nt*8 + t2;
            float d00 = fminf(0.0f, (float)(colb     - rowg));
            float d01 = fminf(0.0f, (float)(colb + 1 - rowg));
            float d10 = fminf(0.0f, (float)(colb     - rowg - 8));
            float d11 = fminf(0.0f, (float)(colb + 1 - rowg - 8));
            s[nt][0] = s[nt][0]*0.125f + slope8*d00;
            s[nt][1] = s[nt][1]*0.125f + slope8*d01;
            s[nt][2] = s[nt][2]*0.125f + slope8*d10;
            s[nt][3] = s[nt][3]*0.125f + slope8*d11;
            mx0 = fmaxf(mx0, fmaxf(s[nt][0], s[nt][1]));
            mx1 = fmaxf(mx1, fmaxf(s[nt][2], s[nt][3]));
        }
#pragma unroll
        for (int off = 1; off <= 2; off <<= 1) {
            mx0 = fmaxf(mx0, __shfl_xor_sync(0xffffffffu, mx0, off));
            mx1 = fmaxf(mx1, __shfl_xor_sync(0xffffffffu, mx1, off));
        }
        float nm0 = fmaxf(m0, mx0), nm1 = fmaxf(m1, mx1);
        float f0 = __expf(m0 - nm0), f1 = __expf(m1 - nm1);
        m0 = nm0; m1 = nm1;

        // exp -> register-resident P fragments (A-operand layout, no smem)
        uint32_t ph[4][4], pl[4][4];
        float sum0 = 0.0f, sum1 = 0.0f;
#pragma unroll
        for (int nt = 0; nt < 8; nt++) {
            float p0 = __expf(s[nt][0] - nm0);
            float p1 = __expf(s[nt][1] - nm0);
            float p2 = __expf(s[nt][2] - nm1);
            float p3 = __expf(s[nt][3] - nm1);
            sum0 += p0 + p1; sum1 += p2 + p3;
            bf162 lo01, lo23;
            bf162 hi01 = pack_split(p0, p1, lo01);
            bf162 hi23 = pack_split(p2, p3, lo23);
            int ks = nt >> 1, hf = (nt & 1) * 2;
            ph[ks][hf]     = b2u(hi01);  ph[ks][hf + 1] = b2u(hi23);
            pl[ks][hf]     = b2u(lo01);  pl[ks][hf + 1] = b2u(lo23);
        }
#pragma unroll
        for (int off = 1; off <= 2; off <<= 1) {
            sum0 += __shfl_xor_sync(0xffffffffu, sum0, off);
            sum1 += __shfl_xor_sync(0xffffffffu, sum1, off);
        }
        l0 = l0*f0 + sum0;
        l1 = l1*f1 + sum1;
#pragma unroll
        for (int nt = 0; nt < 8; nt++) {
            o[nt][0] *= f0; o[nt][1] *= f0;
            o[nt][2] *= f1; o[nt][3] *= f1;
        }

        // O += P V  (P from registers; V natural layout via trans ldmatrix)
#pragma unroll
        for (int ks = 0; ks < 4; ks++) {
#pragma unroll
            for (int ntp = 0; ntp < 4; ntp++) {
                uint32_t vh4[4], vl4[4];
                ldbx4t(vh4, sVh, ntp*16, ks*16, ALD);
                ldbx4t(vl4, sVl, ntp*16, ks*16, ALD);
                mma_bf16(o[2*ntp],   ph[ks], &vh4[0]);
                mma_bf16(o[2*ntp],   ph[ks], &vl4[0]);
                mma_bf16(o[2*ntp],   pl[ks], &vh4[0]);
                mma_bf16(o[2*ntp+1], ph[ks], &vh4[2]);
                mma_bf16(o[2*ntp+1], ph[ks], &vl4[2]);
                mma_bf16(o[2*ntp+1], pl[ks], &vh4[2]);
            }
        }
        __syncthreads();
    }

    // epilogue: normalize, split, store to ao planes [B, N, H*D]
    float i0 = 1.0f / l0, i1 = 1.0f / l1;
#pragma unroll
    for (int nt = 0; nt < 8; nt++) {
        int col = h*64 + nt*8 + t2;
        size_t idx0 = ((size_t)b*NSEQ + rowg)*CDIM + col;
        size_t idx1 = idx0 + 8*CDIM;
        bf162 lo0, lo1;
        bf162 hi0 = pack_split(o[nt][0]*i0, o[nt][1]*i0, lo0);
        bf162 hi1 = pack_split(o[nt][2]*i1, o[nt][3]*i1, lo1);
        *(bf162*)(g_aohi + idx0) = hi0; *(bf162*)(g_aolo + idx0) = lo0;
        *(bf162*)(g_aohi + idx1) = hi1; *(bf162*)(g_aolo + idx1) = lo1;
    }
}

// ---------------------------------------------------------------------------
extern "C" void kernel_launch(void* const* d_in, const int* in_sizes, int n_in,
                              void* d_out, int out_size)
{
    const float* x      = (const float*)d_in[0];
    const float* qkv_w  = (const float*)d_in[1];
    const float* proj_w = (const float*)d_in[2];
    const float* proj_b = (const float*)d_in[3];
    const float* slopes = (const float*)d_in[4];
    float* out = (float*)d_out;

    bf16 *xhi, *xlo, *wqhi, *wqlo, *wphi, *wplo;
    cudaGetSymbolAddress((void**)&xhi,  g_xhi);  cudaGetSymbolAddress((void**)&xlo,  g_xlo);
    cudaGetSymbolAddress((void**)&wqhi, g_wqhi); cudaGetSymbolAddress((void**)&wqlo, g_wqlo);
    cudaGetSymbolAddress((void**)&wphi, g_wphi); cudaGetSymbolAddress((void**)&wplo, g_wplo);

    split_kernel<<<MTOK*CDIM/1024, 256>>>(x, xhi, xlo);
    split_kernel<<<3*CDIM*CDIM/1024, 256>>>(qkv_w, wqhi, wqlo);
    split_kernel<<<CDIM*CDIM/1024, 256>>>(proj_w, wphi, wplo);

    cudaFuncSetAttribute(qkv_mma_kernel,
                         cudaFuncAttributeMaxDynamicSharedMemorySize, G_SMEM);
    qkv_mma_kernel<<<dim3(3072/128, MTOK/128), 256, G_SMEM>>>();

    rope_split_kernel<<<2*BATCH*HEADS*NSEQ*32/256, 256>>>();

    cudaFuncSetAttribute(attn_mma_kernel,
                         cudaFuncAttributeMaxDynamicSharedMemorySize, ATTN_SMEM);
    attn_mma_kernel<<<dim3(NSEQ/128, HEADS, BATCH), 256, ATTN_SMEM>>>(slopes);

    cudaFuncSetAttribute(proj_mma_kernel,
                         cudaFuncAttributeMaxDynamicSharedMemorySize, G_SMEM);
    proj_mma_kernel<<<dim3(CDIM/128, MTOK/128), 256, G_SMEM>>>(proj_b, out);
}

// round 7
// speedup vs baseline: 3.3433x; 1.1741x over previous
#include <cuda_runtime.h>
#include <cuda_bf16.h>
#include <cuda_fp16.h>
#include <cstdint>
#include <math.h>

#define NSEQ   2048
#define BATCH  2
#define HEADS  16
#define HD     64
#define CDIM   1024
#define MTOK   (BATCH*NSEQ)      // 4096

typedef __nv_bfloat16  bf16;
typedef __nv_bfloat162 bf162;

// ---------------- device scratch (no allocations allowed) ------------------
__device__ __align__(16) bf16 g_xhi[MTOK*CDIM],  g_xlo[MTOK*CDIM];
__device__ __align__(16) bf16 g_wqhi[3*CDIM*CDIM], g_wqlo[3*CDIM*CDIM];
__device__ __align__(16) bf16 g_wphi[CDIM*CDIM],  g_wplo[CDIM*CDIM];
__device__ __align__(16) float g_qf[MTOK*CDIM], g_kf[MTOK*CDIM];
__device__ __align__(16) __half g_qh[MTOK*CDIM];                  // q single plane
__device__ __align__(16) __half g_kh[MTOK*CDIM], g_kl[MTOK*CDIM]; // k hi/lo
__device__ __align__(16) __half g_vh[MTOK*CDIM], g_vl[MTOK*CDIM]; // v hi/lo
__device__ __align__(16) bf16 g_aohi[MTOK*CDIM], g_aolo[MTOK*CDIM];

// ======================= helpers ===========================================
__device__ __forceinline__ bf162 pack_split(float a, float b, bf162& lo) {
    bf16 ha = __float2bfloat16_rn(a);
    bf16 hb = __float2bfloat16_rn(b);
    lo.x = __float2bfloat16_rn(a - __bfloat162float(ha));
    lo.y = __float2bfloat16_rn(b - __bfloat162float(hb));
    bf162 hi; hi.x = ha; hi.y = hb; return hi;
}

__device__ __forceinline__ __half2 pack_split_h(float a, float b, __half2& lo) {
    __half ha = __float2half_rn(a);
    __half hb = __float2half_rn(b);
    lo = __halves2half2(__float2half_rn(a - __half2float(ha)),
                        __float2half_rn(b - __half2float(hb)));
    return __halves2half2(ha, hb);
}

__device__ __forceinline__ uint32_t h2u(__half2 v) {
    union { __half2 h; uint32_t u; } c; c.h = v; return c.u;
}

// bf16 mma (GEMMs)
__device__ __forceinline__ void mma_bf16(float c[4], const uint32_t a[4], const uint32_t b[2]) {
    asm volatile(
        "mma.sync.aligned.m16n8k16.row.col.f32.bf16.bf16.f32 "
        "{%0,%1,%2,%3}, {%4,%5,%6,%7}, {%8,%9}, {%0,%1,%2,%3};\n"
        : "+f"(c[0]), "+f"(c[1]), "+f"(c[2]), "+f"(c[3])
        : "r"(a[0]), "r"(a[1]), "r"(a[2]), "r"(a[3]), "r"(b[0]), "r"(b[1]));
}
// fp16 mma (attention)
__device__ __forceinline__ void mma_f16(float c[4], const uint32_t a[4], const uint32_t b[2]) {
    asm volatile(
        "mma.sync.aligned.m16n8k16.row.col.f32.f16.f16.f32 "
        "{%0,%1,%2,%3}, {%4,%5,%6,%7}, {%8,%9}, {%0,%1,%2,%3};\n"
        : "+f"(c[0]), "+f"(c[1]), "+f"(c[2]), "+f"(c[3])
        : "r"(a[0]), "r"(a[1]), "r"(a[2]), "r"(a[3]), "r"(b[0]), "r"(b[1]));
}

// A fragment (m16 x k16, row-major in smem)
template<typename T>
__device__ __forceinline__ void lda_frag(uint32_t r[4], const T* base, int row0, int col0, int ld) {
    const int lane = threadIdx.x & 31;
    const T* p = base + (row0 + (lane & 15)) * ld + col0 + ((lane >> 4) << 3);
    uint32_t a = (uint32_t)__cvta_generic_to_shared(p);
    asm volatile("ldmatrix.sync.aligned.m8n8.x4.shared.b16 {%0,%1,%2,%3}, [%4];"
                 : "=r"(r[0]), "=r"(r[1]), "=r"(r[2]), "=r"(r[3]) : "r"(a));
}

// TWO B fragments (k16 x n8 each) for n0..n0+15; smem holds B^T row-major
template<typename T>
__device__ __forceinline__ void ldbx4(uint32_t r[4], const T* base, int n0, int k0, int ld) {
    const int lane = threadIdx.x & 31;
    const T* p = base + (n0 + ((lane >> 4) << 3) + (lane & 7)) * ld
                      + k0 + (((lane >> 3) & 1) << 3);
    uint32_t a = (uint32_t)__cvta_generic_to_shared(p);
    asm volatile("ldmatrix.sync.aligned.m8n8.x4.shared.b16 {%0,%1,%2,%3}, [%4];"
                 : "=r"(r[0]), "=r"(r[1]), "=r"(r[2]), "=r"(r[3]) : "r"(a));
}

// TWO B fragments from NATURAL row-major B [k][n] via trans (for V)
template<typename T>
__device__ __forceinline__ void ldbx4t(uint32_t r[4], const T* base, int n0, int k0, int ld) {
    const int lane = threadIdx.x & 31;
    const T* p = base + (k0 + (lane & 15)) * ld + n0 + ((lane >> 4) << 3);
    uint32_t a = (uint32_t)__cvta_generic_to_shared(p);
    asm volatile("ldmatrix.sync.aligned.m8n8.x4.trans.shared.b16 {%0,%1,%2,%3}, [%4];"
                 : "=r"(r[0]), "=r"(r[1]), "=r"(r[2]), "=r"(r[3]) : "r"(a));
}

__device__ __forceinline__ void cp_async16(uint32_t saddr, const void* gaddr) {
    asm volatile("cp.async.cg.shared.global [%0], [%1], 16;" :: "r"(saddr), "l"(gaddr));
}
#define CP_COMMIT()  asm volatile("cp.async.commit_group;" ::: "memory")
#define CP_WAIT(n)   asm volatile("cp.async.wait_group %0;" :: "n"(n) : "memory")

// ---------------- fp32 -> (hi,lo) bf16 split ------------------------------
__global__ __launch_bounds__(256) void split_kernel(
    const float* __restrict__ in, bf16* __restrict__ hi, bf16* __restrict__ lo)
{
    int i = blockIdx.x * 256 + threadIdx.x;
    float4 v = ((const float4*)in)[i];
    bf162 l0, l1;
    bf162 h0 = pack_split(v.x, v.y, l0);
    bf162 h1 = pack_split(v.z, v.w, l1);
    ((bf162*)hi)[2*i]   = h0;  ((bf162*)hi)[2*i+1] = h1;
    ((bf162*)lo)[2*i]   = l0;  ((bf162*)lo)[2*i+1] = l1;
}

// ================= double-buffered split-bf16 GEMM tile =====================
#define GLDS    40
#define G_PLANE (128*GLDS)
#define G_STAGE (4*G_PLANE)
#define G_SMEM  (2*G_STAGE*2)       // 81920 bytes

__device__ __forceinline__ void g_prefetch(
    uint32_t smem_u32, int c,
    const bf16* A0, const bf16* A1, const bf16* B0, const bf16* B1)
{
    const int tid = threadIdx.x;
    uint32_t sb = smem_u32 + (c & 1) * (G_STAGE * 2);
    const bf16* gp[4] = {A0, A1, B0, B1};
#pragma unroll
    for (int i = 0; i < 8; i++) {
        int idx = tid + i * 256;
        int p = idx >> 9, r = (idx >> 2) & 127, seg = idx & 3;
        const bf16* g = gp[p] + (size_t)r * 1024 + c * 32 + seg * 8;
        uint32_t d = sb + p * (G_PLANE * 2) + r * (GLDS * 2) + seg * 16;
        cp_async16(d, g);
    }
    CP_COMMIT();
}

__device__ __forceinline__ void gemm_tile2(
    const bf16* __restrict__ Ah, const bf16* __restrict__ Al,
    const bf16* __restrict__ Bh, const bf16* __restrict__ Bl,
    bf16* smem, float c[4][4][4])
{
    uint32_t smem_u32 = (uint32_t)__cvta_generic_to_shared(smem);
    const int wid = threadIdx.x >> 5;
    const int wm = wid >> 2, wn = wid & 3;

    g_prefetch(smem_u32, 0, Ah, Al, Bh, Bl);

    for (int ch = 0; ch < 32; ch++) {
        CP_WAIT(0);
        __syncthreads();
        if (ch + 1 < 32) g_prefetch(smem_u32, ch + 1, Ah, Al, Bh, Bl);

        bf16* st  = smem + (ch & 1) * G_STAGE;
        bf16* sAh = st;
        bf16* sAl = st + G_PLANE;
        bf16* sBh = st + 2 * G_PLANE;
        bf16* sBl = st + 3 * G_PLANE;

#pragma unroll
        for (int ks = 0; ks < 32; ks += 16) {
            uint32_t bh4[2][4], bl4[2][4];
#pragma unroll
            for (int ntp = 0; ntp < 2; ntp++) {
                ldbx4(bh4[ntp], sBh, wn * 32 + ntp * 16, ks, GLDS);
                ldbx4(bl4[ntp], sBl, wn * 32 + ntp * 16, ks, GLDS);
            }
#pragma unroll
            for (int mi = 0; mi < 4; mi++) {
                uint32_t ah[4], al[4];
                lda_frag(ah, sAh, wm * 64 + mi * 16, ks, GLDS);
                lda_frag(al, sAl, wm * 64 + mi * 16, ks, GLDS);
#pragma unroll
                for (int ni = 0; ni < 4; ni++) {
                    const uint32_t* bh2 = &bh4[ni >> 1][(ni & 1) * 2];
                    const uint32_t* bl2 = &bl4[ni >> 1][(ni & 1) * 2];
                    mma_bf16(c[mi][ni], ah, bh2);
                    mma_bf16(c[mi][ni], ah, bl2);
                    mma_bf16(c[mi][ni], al, bh2);
                }
            }
        }
    }
}

// ---------------- QKV GEMM + scatter epilogue ------------------------------
__global__ __launch_bounds__(256, 2) void qkv_mma_kernel()
{
    extern __shared__ bf16 gsm[];
    float c[4][4][4];
#pragma unroll
    for (int a = 0; a < 4; a++)
#pragma unroll
        for (int b = 0; b < 4; b++)
#pragma unroll
            for (int d = 0; d < 4; d++) c[a][b][d] = 0.0f;

    const int rowBase = blockIdx.y * 128, colBase = blockIdx.x * 128;
    gemm_tile2(g_xhi + (size_t)rowBase*1024, g_xlo + (size_t)rowBase*1024,
               g_wqhi + (size_t)colBase*1024, g_wqlo + (size_t)colBase*1024,
               gsm, c);

    const int lane = threadIdx.x & 31, wid = threadIdx.x >> 5;
    const int wm = wid >> 2, wn = wid & 3;
    const int g = lane >> 2, t2 = (lane & 3) << 1;
    const int tix = colBase >> 10;

#pragma unroll
    for (int mi = 0; mi < 4; mi++) {
        int row = rowBase + wm*64 + mi*16 + g;
        int bb = row >> 11, n = row & 2047;
#pragma unroll
        for (int ni = 0; ni < 4; ni++) {
            int colg = colBase + wn*32 + ni*8 + t2;
            int rem = colg & 1023, hh = rem >> 6, d = rem & 63;
            size_t base0 = (((size_t)(bb * HEADS + hh)) * NSEQ + n) * HD + d;
            size_t base1 = base0 + 8*HD;
            float* f = c[mi][ni];
            if (tix == 0) {
                *(float2*)(g_qf + base0) = make_float2(f[0], f[1]);
                *(float2*)(g_qf + base1) = make_float2(f[2], f[3]);
            } else if (tix == 1) {
                *(float2*)(g_kf + base0) = make_float2(f[0], f[1]);
                *(float2*)(g_kf + base1) = make_float2(f[2], f[3]);
            } else {
                __half2 l0, l1;
                __half2 h0 = pack_split_h(f[0], f[1], l0);
                __half2 h1 = pack_split_h(f[2], f[3], l1);
                *(__half2*)(g_vh + base0) = h0; *(__half2*)(g_vl + base0) = l0;
                *(__half2*)(g_vh + base1) = h1; *(__half2*)(g_vl + base1) = l1;
            }
        }
    }
}

// ---------------- output projection ---------------------------------------
__global__ __launch_bounds__(256, 2) void proj_mma_kernel(
    const float* __restrict__ bias, float* __restrict__ out)
{
    extern __shared__ bf16 gsm[];
    float c[4][4][4];
#pragma unroll
    for (int a = 0; a < 4; a++)
#pragma unroll
        for (int b = 0; b < 4; b++)
#pragma unroll
            for (int d = 0; d < 4; d++) c[a][b][d] = 0.0f;

    const int rowBase = blockIdx.y * 128, colBase = blockIdx.x * 128;
    gemm_tile2(g_aohi + (size_t)rowBase*1024, g_aolo + (size_t)rowBase*1024,
               g_wphi + (size_t)colBase*1024, g_wplo + (size_t)colBase*1024,
               gsm, c);

    const int lane = threadIdx.x & 31, wid = threadIdx.x >> 5;
    const int wm = wid >> 2, wn = wid & 3;
    const int g = lane >> 2, t2 = (lane & 3) << 1;

#pragma unroll
    for (int mi = 0; mi < 4; mi++) {
        int row = rowBase + wm*64 + mi*16 + g;
#pragma unroll
        for (int ni = 0; ni < 4; ni++) {
            int colg = colBase + wn*32 + ni*8 + t2;
            float b0 = bias[colg], b1 = bias[colg+1];
            float* f = c[mi][ni];
            *(float2*)(out + (size_t)row*CDIM + colg)     = make_float2(f[0]+b0, f[1]+b1);
            *(float2*)(out + (size_t)(row+8)*CDIM + colg) = make_float2(f[2]+b0, f[3]+b1);
        }
    }
}

// ---------------- RoPE + fp16 convert --------------------------------------
__global__ __launch_bounds__(256) void rope_split_kernel()
{
    const int per = BATCH*HEADS*NSEQ*32;
    int idx = blockIdx.x*256 + threadIdx.x;
    bool isq = idx < per;
    int rem = isq ? idx : idx - per;
    int pair = rem & 31;
    int rowI = rem >> 5;
    int n = rowI & (NSEQ-1);

    float inv = powf(10000.0f, -(float)pair * (1.0f/32.0f));
    float s, cc;
    sincosf((float)n * inv, &s, &cc);

    const float* src = isq ? g_qf : g_kf;
    size_t p0 = (size_t)rowI*64 + pair;
    float t1 = src[p0], t2 = src[p0+32];
    float r1 = t1*cc - t2*s;
    float r2 = t2*cc + t1*s;
    if (isq) {
        g_qh[p0]    = __float2half_rn(r1);
        g_qh[p0+32] = __float2half_rn(r2);
    } else {
        __half h1 = __float2half_rn(r1);
        __half h2 = __float2half_rn(r2);
        g_kh[p0]    = h1; g_kl[p0]    = __float2half_rn(r1 - __half2float(h1));
        g_kh[p0+32] = h2; g_kl[p0+32] = __float2half_rn(r2 - __half2float(h2));
    }
}

// ====== fp16 flash attention: reg-resident P, 2-mma S, 2-mma PV ============
// Region A (36,864B): first Q hi plane (uses 18KB), then K/V stage for odd kt.
// Region B: K/V stage for even kt. Stage: Kh@0, Kl@4608, Vh@9216, Vl@13824 (el).
#define ALD      72
#define REG_ELEM (4*64*ALD)          // 18432 elements = 36864 B
#define ATTN_SMEM (2*REG_ELEM*2)     // 73728 B -> 2 CTAs/SM

__device__ __forceinline__ void attn_prefetch(uint32_t smem_u32, int kt, int bh)
{
    const int tid = threadIdx.x;
    const size_t koff = ((size_t)bh * NSEQ + kt * 64) * HD;
    uint32_t base = smem_u32 + ((kt & 1) ? 0u : (uint32_t)(REG_ELEM * 2));
#pragma unroll
    for (int i = 0; i < 8; i++) {
        int idx = tid + i * 256;            // 0..2047
        int t = idx >> 9;                   // 0=kh,1=kl,2=vh,3=vl
        int r = (idx >> 3) & 63;
        int seg = idx & 7;
        const __half* g = (t == 0 ? g_kh : t == 1 ? g_kl : t == 2 ? g_vh : g_vl)
                          + koff + r * 64 + seg * 8;
        uint32_t d = base + t * 9216 + r * (ALD * 2) + seg * 16;
        cp_async16(d, g);
    }
    CP_COMMIT();
}

__global__ __launch_bounds__(256, 2) void attn_mma_kernel(const float* __restrict__ slopes)
{
    extern __shared__ __half smh[];
    uint32_t smem_u32 = (uint32_t)__cvta_generic_to_shared(smh);

    const int tid = threadIdx.x, wid = tid >> 5, lane = tid & 31;
    const int g = lane >> 2, t2 = (lane & 3) << 1;
    const int qt = blockIdx.x, h = blockIdx.y, b = blockIdx.z;
    const int bh = b*HEADS + h;
    const float slope8 = slopes[h] * 8.0f;

    // load Q hi plane (128x64) into region A
    __half* sQh = smh;
    const size_t qoff = ((size_t)bh*NSEQ + qt*128)*HD;
    for (int v = tid; v < 1024; v += 256) {
        int row = v >> 3, seg = (v & 7) << 3;
        *(uint4*)(sQh + row*ALD + seg) = *(const uint4*)(g_qh + qoff + row*64 + seg);
    }
    attn_prefetch(smem_u32, 0, bh);      // kt=0 -> region B
    __syncthreads();

    // hoist Q fragments for all 4 k-steps
    uint32_t qh[4][4];
#pragma unroll
    for (int ks = 0; ks < 4; ks++)
        lda_frag(qh[ks], sQh, wid*16, ks*16, ALD);

    float o[8][4];
#pragma unroll
    for (int nt = 0; nt < 8; nt++)
#pragma unroll
        for (int d = 0; d < 4; d++) o[nt][d] = 0.0f;
    float m0 = -1e30f, m1 = -1e30f, l0 = 0.0f, l1 = 0.0f;
    const int rowg = qt*128 + wid*16 + g;   // this thread's rows: rowg, rowg+8

    for (int kt = 0; kt < 32; kt++) {
        CP_WAIT(0);
        __syncthreads();     // all warps done with other region (and Q hoist at kt=0)
        if (kt + 1 < 32) attn_prefetch(smem_u32, kt + 1, bh);

        __half* reg = smh + ((kt & 1) ? 0 : REG_ELEM);
        __half* sKh = reg;
        __half* sKl = reg + 4608;
        __half* sVh = reg + 9216;
        __half* sVl = reg + 13824;

        // S = Q K^T : 2 mmas per n-tile (qh*kh + qh*kl)
        float s[8][4];
#pragma unroll
        for (int nt = 0; nt < 8; nt++)
#pragma unroll
            for (int d = 0; d < 4; d++) s[nt][d] = 0.0f;
#pragma unroll
        for (int ks = 0; ks < 4; ks++) {
#pragma unroll
            for (int ntp = 0; ntp < 4; ntp++) {
                uint32_t kh4[4], kl4[4];
                ldbx4(kh4, sKh, ntp*16, ks*16, ALD);
                ldbx4(kl4, sKl, ntp*16, ks*16, ALD);
                mma_f16(s[2*ntp],   qh[ks], &kh4[0]);
                mma_f16(s[2*ntp],   qh[ks], &kl4[0]);
                mma_f16(s[2*ntp+1], qh[ks], &kh4[2]);
                mma_f16(s[2*ntp+1], qh[ks], &kl4[2]);
            }
        }

        // scale + ALiBi, row max
        float mx0 = -1e30f, mx1 = -1e30f;
#pragma unroll
        for (int nt = 0; nt < 8; nt++) {
            int colb = kt*64 + nt*8 + t2;
            float d00 = fminf(0.0f, (float)(colb     - rowg));
            float d01 = fminf(0.0f, (float)(colb + 1 - rowg));
            float d10 = fminf(0.0f, (float)(colb     - rowg - 8));
            float d11 = fminf(0.0f, (float)(colb + 1 - rowg - 8));
            s[nt][0] = s[nt][0]*0.125f + slope8*d00;
            s[nt][1] = s[nt][1]*0.125f + slope8*d01;
            s[nt][2] = s[nt][2]*0.125f + slope8*d10;
            s[nt][3] = s[nt][3]*0.125f + slope8*d11;
            mx0 = fmaxf(mx0, fmaxf(s[nt][0], s[nt][1]));
            mx1 = fmaxf(mx1, fmaxf(s[nt][2], s[nt][3]));
        }
#pragma unroll
        for (int off = 1; off <= 2; off <<= 1) {
            mx0 = fmaxf(mx0, __shfl_xor_sync(0xffffffffu, mx0, off));
            mx1 = fmaxf(mx1, __shfl_xor_sync(0xffffffffu, mx1, off));
        }
        float nm0 = fmaxf(m0, mx0), nm1 = fmaxf(m1, mx1);
        float f0 = __expf(m0 - nm0), f1 = __expf(m1 - nm1);
        m0 = nm0; m1 = nm1;

        // exp -> register-resident single-plane fp16 P fragments
        uint32_t ph[4][4];
        float sum0 = 0.0f, sum1 = 0.0f;
#pragma unroll
        for (int nt = 0; nt < 8; nt++) {
            float p0 = __expf(s[nt][0] - nm0);
            float p1 = __expf(s[nt][1] - nm0);
            float p2 = __expf(s[nt][2] - nm1);
            float p3 = __expf(s[nt][3] - nm1);
            sum0 += p0 + p1; sum1 += p2 + p3;
            int ks = nt >> 1, hf = (nt & 1) * 2;
            ph[ks][hf]     = h2u(__floats2half2_rn(p0, p1));
            ph[ks][hf + 1] = h2u(__floats2half2_rn(p2, p3));
        }
#pragma unroll
        for (int off = 1; off <= 2; off <<= 1) {
            sum0 += __shfl_xor_sync(0xffffffffu, sum0, off);
            sum1 += __shfl_xor_sync(0xffffffffu, sum1, off);
        }
        l0 = l0*f0 + sum0;
        l1 = l1*f1 + sum1;
#pragma unroll
        for (int nt = 0; nt < 8; nt++) {
            o[nt][0] *= f0; o[nt][1] *= f0;
            o[nt][2] *= f1; o[nt][3] *= f1;
        }

        // O += P V : 2 mmas per n-tile (ph*vh + ph*vl)
#pragma unroll
        for (int ks = 0; ks < 4; ks++) {
#pragma unroll
            for (int ntp = 0; ntp < 4; ntp++) {
                uint32_t vh4[4], vl4[4];
                ldbx4t(vh4, sVh, ntp*16, ks*16, ALD);
                ldbx4t(vl4, sVl, ntp*16, ks*16, ALD);
                mma_f16(o[2*ntp],   ph[ks], &vh4[0]);
                mma_f16(o[2*ntp],   ph[ks], &vl4[0]);
                mma_f16(o[2*ntp+1], ph[ks], &vh4[2]);
                mma_f16(o[2*ntp+1], ph[ks], &vl4[2]);
            }
        }
    }

    // epilogue: normalize, bf16-split, store ao planes [B, N, H*D]
    float i0 = 1.0f / l0, i1 = 1.0f / l1;
#pragma unroll
    for (int nt = 0; nt < 8; nt++) {
        int col = h*64 + nt*8 + t2;
        size_t idx0 = ((size_t)b*NSEQ + rowg)*CDIM + col;
        size_t idx1 = idx0 + 8*CDIM;
        bf162 lo0, lo1;
        bf162 hi0 = pack_split(o[nt][0]*i0, o[nt][1]*i0, lo0);
        bf162 hi1 = pack_split(o[nt][2]*i1, o[nt][3]*i1, lo1);
        *(bf162*)(g_aohi + idx0) = hi0; *(bf162*)(g_aolo + idx0) = lo0;
        *(bf162*)(g_aohi + idx1) = hi1; *(bf162*)(g_aolo + idx1) = lo1;
    }
}

// ---------------------------------------------------------------------------
extern "C" void kernel_launch(void* const* d_in, const int* in_sizes, int n_in,
                              void* d_out, int out_size)
{
    const float* x      = (const float*)d_in[0];
    const float* qkv_w  = (const float*)d_in[1];
    const float* proj_w = (const float*)d_in[2];
    const float* proj_b = (const float*)d_in[3];
    const float* slopes = (const float*)d_in[4];
    float* out = (float*)d_out;

    bf16 *xhi, *xlo, *wqhi, *wqlo, *wphi, *wplo;
    cudaGetSymbolAddress((void**)&xhi,  g_xhi);  cudaGetSymbolAddress((void**)&xlo,  g_xlo);
    cudaGetSymbolAddress((void**)&wqhi, g_wqhi); cudaGetSymbolAddress((void**)&wqlo, g_wqlo);
    cudaGetSymbolAddress((void**)&wphi, g_wphi); cudaGetSymbolAddress((void**)&wplo, g_wplo);

    split_kernel<<<MTOK*CDIM/1024, 256>>>(x, xhi, xlo);
    split_kernel<<<3*CDIM*CDIM/1024, 256>>>(qkv_w, wqhi, wqlo);
    split_kernel<<<CDIM*CDIM/1024, 256>>>(proj_w, wphi, wplo);

    cudaFuncSetAttribute(qkv_mma_kernel,
                         cudaFuncAttributeMaxDynamicSharedMemorySize, G_SMEM);
    qkv_mma_kernel<<<dim3(3072/128, MTOK/128), 256, G_SMEM>>>();

    rope_split_kernel<<<2*BATCH*HEADS*NSEQ*32/256, 256>>>();

    cudaFuncSetAttribute(attn_mma_kernel,
                         cudaFuncAttributeMaxDynamicSharedMemorySize, ATTN_SMEM);
    attn_mma_kernel<<<dim3(NSEQ/128, HEADS, BATCH), 256, ATTN_SMEM>>>(slopes);

    cudaFuncSetAttribute(proj_mma_kernel,
                         cudaFuncAttributeMaxDynamicSharedMemorySize, G_SMEM);
    proj_mma_kernel<<<dim3(CDIM/128, MTOK/128), 256, G_SMEM>>>(proj_b, out);
}

// round 8
// speedup vs baseline: 3.9238x; 1.1736x over previous
#include <cuda_runtime.h>
#include <cuda_bf16.h>
#include <cuda_fp16.h>
#include <cstdint>
#include <math.h>

#define NSEQ   2048
#define BATCH  2
#define HEADS  16
#define HD     64
#define CDIM   1024
#define MTOK   (BATCH*NSEQ)      // 4096

typedef __nv_bfloat16  bf16;
typedef __nv_bfloat162 bf162;

// ---------------- device scratch (no allocations allowed) ------------------
__device__ __align__(16) bf16 g_xhi[MTOK*CDIM],  g_xlo[MTOK*CDIM];
__device__ __align__(16) bf16 g_wqhi[3*CDIM*CDIM], g_wqlo[3*CDIM*CDIM];
__device__ __align__(16) bf16 g_wphi[CDIM*CDIM],  g_wplo[CDIM*CDIM];
__device__ __align__(16) float g_qf[MTOK*CDIM], g_kf[MTOK*CDIM];
__device__ __align__(16) __half g_qh[MTOK*CDIM];   // q single fp16 plane
__device__ __align__(16) __half g_kh[MTOK*CDIM];   // k single fp16 plane
__device__ __align__(16) __half g_vh[MTOK*CDIM];   // v single fp16 plane
__device__ __align__(16) bf16 g_aohi[MTOK*CDIM], g_aolo[MTOK*CDIM];

// ======================= helpers ===========================================
__device__ __forceinline__ bf162 pack_split(float a, float b, bf162& lo) {
    bf16 ha = __float2bfloat16_rn(a);
    bf16 hb = __float2bfloat16_rn(b);
    lo.x = __float2bfloat16_rn(a - __bfloat162float(ha));
    lo.y = __float2bfloat16_rn(b - __bfloat162float(hb));
    bf162 hi; hi.x = ha; hi.y = hb; return hi;
}

__device__ __forceinline__ uint32_t h2u(__half2 v) {
    union { __half2 h; uint32_t u; } c; c.h = v; return c.u;
}

// bf16 mma (GEMMs)
__device__ __forceinline__ void mma_bf16(float c[4], const uint32_t a[4], const uint32_t b[2]) {
    asm volatile(
        "mma.sync.aligned.m16n8k16.row.col.f32.bf16.bf16.f32 "
        "{%0,%1,%2,%3}, {%4,%5,%6,%7}, {%8,%9}, {%0,%1,%2,%3};\n"
        : "+f"(c[0]), "+f"(c[1]), "+f"(c[2]), "+f"(c[3])
        : "r"(a[0]), "r"(a[1]), "r"(a[2]), "r"(a[3]), "r"(b[0]), "r"(b[1]));
}
// fp16 mma (attention)
__device__ __forceinline__ void mma_f16(float c[4], const uint32_t a[4], const uint32_t b[2]) {
    asm volatile(
        "mma.sync.aligned.m16n8k16.row.col.f32.f16.f16.f32 "
        "{%0,%1,%2,%3}, {%4,%5,%6,%7}, {%8,%9}, {%0,%1,%2,%3};\n"
        : "+f"(c[0]), "+f"(c[1]), "+f"(c[2]), "+f"(c[3])
        : "r"(a[0]), "r"(a[1]), "r"(a[2]), "r"(a[3]), "r"(b[0]), "r"(b[1]));
}

// A fragment (m16 x k16, row-major in smem)
template<typename T>
__device__ __forceinline__ void lda_frag(uint32_t r[4], const T* base, int row0, int col0, int ld) {
    const int lane = threadIdx.x & 31;
    const T* p = base + (row0 + (lane & 15)) * ld + col0 + ((lane >> 4) << 3);
    uint32_t a = (uint32_t)__cvta_generic_to_shared(p);
    asm volatile("ldmatrix.sync.aligned.m8n8.x4.shared.b16 {%0,%1,%2,%3}, [%4];"
                 : "=r"(r[0]), "=r"(r[1]), "=r"(r[2]), "=r"(r[3]) : "r"(a));
}

// TWO B fragments (k16 x n8 each) for n0..n0+15; smem holds B^T row-major
template<typename T>
__device__ __forceinline__ void ldbx4(uint32_t r[4], const T* base, int n0, int k0, int ld) {
    const int lane = threadIdx.x & 31;
    const T* p = base + (n0 + ((lane >> 4) << 3) + (lane & 7)) * ld
                      + k0 + (((lane >> 3) & 1) << 3);
    uint32_t a = (uint32_t)__cvta_generic_to_shared(p);
    asm volatile("ldmatrix.sync.aligned.m8n8.x4.shared.b16 {%0,%1,%2,%3}, [%4];"
                 : "=r"(r[0]), "=r"(r[1]), "=r"(r[2]), "=r"(r[3]) : "r"(a));
}

// TWO B fragments from NATURAL row-major B [k][n] via trans (for V)
template<typename T>
__device__ __forceinline__ void ldbx4t(uint32_t r[4], const T* base, int n0, int k0, int ld) {
    const int lane = threadIdx.x & 31;
    const T* p = base + (k0 + (lane & 15)) * ld + n0 + ((lane >> 4) << 3);
    uint32_t a = (uint32_t)__cvta_generic_to_shared(p);
    asm volatile("ldmatrix.sync.aligned.m8n8.x4.trans.shared.b16 {%0,%1,%2,%3}, [%4];"
                 : "=r"(r[0]), "=r"(r[1]), "=r"(r[2]), "=r"(r[3]) : "r"(a));
}

__device__ __forceinline__ void cp_async16(uint32_t saddr, const void* gaddr) {
    asm volatile("cp.async.cg.shared.global [%0], [%1], 16;" :: "r"(saddr), "l"(gaddr));
}
#define CP_COMMIT()  asm volatile("cp.async.commit_group;" ::: "memory")
#define CP_WAIT(n)   asm volatile("cp.async.wait_group %0;" :: "n"(n) : "memory")

// ---------------- fp32 -> (hi,lo) bf16 split ------------------------------
__global__ __launch_bounds__(256) void split_kernel(
    const float* __restrict__ in, bf16* __restrict__ hi, bf16* __restrict__ lo)
{
    int i = blockIdx.x * 256 + threadIdx.x;
    float4 v = ((const float4*)in)[i];
    bf162 l0, l1;
    bf162 h0 = pack_split(v.x, v.y, l0);
    bf162 h1 = pack_split(v.z, v.w, l1);
    ((bf162*)hi)[2*i]   = h0;  ((bf162*)hi)[2*i+1] = h1;
    ((bf162*)lo)[2*i]   = l0;  ((bf162*)lo)[2*i+1] = l1;
}

// ================= double-buffered split-bf16 GEMM tile =====================
#define GLDS    40
#define G_PLANE (128*GLDS)
#define G_STAGE (4*G_PLANE)
#define G_SMEM  (2*G_STAGE*2)       // 81920 bytes

__device__ __forceinline__ void g_prefetch(
    uint32_t smem_u32, int c,
    const bf16* A0, const bf16* A1, const bf16* B0, const bf16* B1)
{
    const int tid = threadIdx.x;
    uint32_t sb = smem_u32 + (c & 1) * (G_STAGE * 2);
    const bf16* gp[4] = {A0, A1, B0, B1};
#pragma unroll
    for (int i = 0; i < 8; i++) {
        int idx = tid + i * 256;
        int p = idx >> 9, r = (idx >> 2) & 127, seg = idx & 3;
        const bf16* g = gp[p] + (size_t)r * 1024 + c * 32 + seg * 8;
        uint32_t d = sb + p * (G_PLANE * 2) + r * (GLDS * 2) + seg * 16;
        cp_async16(d, g);
    }
    CP_COMMIT();
}

__device__ __forceinline__ void gemm_tile2(
    const bf16* __restrict__ Ah, const bf16* __restrict__ Al,
    const bf16* __restrict__ Bh, const bf16* __restrict__ Bl,
    bf16* smem, float c[4][4][4])
{
    uint32_t smem_u32 = (uint32_t)__cvta_generic_to_shared(smem);
    const int wid = threadIdx.x >> 5;
    const int wm = wid >> 2, wn = wid & 3;

    g_prefetch(smem_u32, 0, Ah, Al, Bh, Bl);

    for (int ch = 0; ch < 32; ch++) {
        CP_WAIT(0);
        __syncthreads();
        if (ch + 1 < 32) g_prefetch(smem_u32, ch + 1, Ah, Al, Bh, Bl);

        bf16* st  = smem + (ch & 1) * G_STAGE;
        bf16* sAh = st;
        bf16* sAl = st + G_PLANE;
        bf16* sBh = st + 2 * G_PLANE;
        bf16* sBl = st + 3 * G_PLANE;

#pragma unroll
        for (int ks = 0; ks < 32; ks += 16) {
            uint32_t bh4[2][4], bl4[2][4];
#pragma unroll
            for (int ntp = 0; ntp < 2; ntp++) {
                ldbx4(bh4[ntp], sBh, wn * 32 + ntp * 16, ks, GLDS);
                ldbx4(bl4[ntp], sBl, wn * 32 + ntp * 16, ks, GLDS);
            }
#pragma unroll
            for (int mi = 0; mi < 4; mi++) {
                uint32_t ah[4], al[4];
                lda_frag(ah, sAh, wm * 64 + mi * 16, ks, GLDS);
                lda_frag(al, sAl, wm * 64 + mi * 16, ks, GLDS);
#pragma unroll
                for (int ni = 0; ni < 4; ni++) {
                    const uint32_t* bh2 = &bh4[ni >> 1][(ni & 1) * 2];
                    const uint32_t* bl2 = &bl4[ni >> 1][(ni & 1) * 2];
                    mma_bf16(c[mi][ni], ah, bh2);
                    mma_bf16(c[mi][ni], ah, bl2);
                    mma_bf16(c[mi][ni], al, bh2);
                }
            }
        }
    }
}

// ---------------- QKV GEMM + scatter epilogue ------------------------------
__global__ __launch_bounds__(256, 2) void qkv_mma_kernel()
{
    extern __shared__ bf16 gsm[];
    float c[4][4][4];
#pragma unroll
    for (int a = 0; a < 4; a++)
#pragma unroll
        for (int b = 0; b < 4; b++)
#pragma unroll
            for (int d = 0; d < 4; d++) c[a][b][d] = 0.0f;

    const int rowBase = blockIdx.y * 128, colBase = blockIdx.x * 128;
    gemm_tile2(g_xhi + (size_t)rowBase*1024, g_xlo + (size_t)rowBase*1024,
               g_wqhi + (size_t)colBase*1024, g_wqlo + (size_t)colBase*1024,
               gsm, c);

    const int lane = threadIdx.x & 31, wid = threadIdx.x >> 5;
    const int wm = wid >> 2, wn = wid & 3;
    const int g = lane >> 2, t2 = (lane & 3) << 1;
    const int tix = colBase >> 10;

#pragma unroll
    for (int mi = 0; mi < 4; mi++) {
        int row = rowBase + wm*64 + mi*16 + g;
        int bb = row >> 11, n = row & 2047;
#pragma unroll
        for (int ni = 0; ni < 4; ni++) {
            int colg = colBase + wn*32 + ni*8 + t2;
            int rem = colg & 1023, hh = rem >> 6, d = rem & 63;
            size_t base0 = (((size_t)(bb * HEADS + hh)) * NSEQ + n) * HD + d;
            size_t base1 = base0 + 8*HD;
            float* f = c[mi][ni];
            if (tix == 0) {
                *(float2*)(g_qf + base0) = make_float2(f[0], f[1]);
                *(float2*)(g_qf + base1) = make_float2(f[2], f[3]);
            } else if (tix == 1) {
                *(float2*)(g_kf + base0) = make_float2(f[0], f[1]);
                *(float2*)(g_kf + base1) = make_float2(f[2], f[3]);
            } else {
                *(__half2*)(g_vh + base0) = __floats2half2_rn(f[0], f[1]);
                *(__half2*)(g_vh + base1) = __floats2half2_rn(f[2], f[3]);
            }
        }
    }
}

// ---------------- output projection ---------------------------------------
__global__ __launch_bounds__(256, 2) void proj_mma_kernel(
    const float* __restrict__ bias, float* __restrict__ out)
{
    extern __shared__ bf16 gsm[];
    float c[4][4][4];
#pragma unroll
    for (int a = 0; a < 4; a++)
#pragma unroll
        for (int b = 0; b < 4; b++)
#pragma unroll
            for (int d = 0; d < 4; d++) c[a][b][d] = 0.0f;

    const int rowBase = blockIdx.y * 128, colBase = blockIdx.x * 128;
    gemm_tile2(g_aohi + (size_t)rowBase*1024, g_aolo + (size_t)rowBase*1024,
               g_wphi + (size_t)colBase*1024, g_wplo + (size_t)colBase*1024,
               gsm, c);

    const int lane = threadIdx.x & 31, wid = threadIdx.x >> 5;
    const int wm = wid >> 2, wn = wid & 3;
    const int g = lane >> 2, t2 = (lane & 3) << 1;

#pragma unroll
    for (int mi = 0; mi < 4; mi++) {
        int row = rowBase + wm*64 + mi*16 + g;
#pragma unroll
        for (int ni = 0; ni < 4; ni++) {
            int colg = colBase + wn*32 + ni*8 + t2;
            float b0 = bias[colg], b1 = bias[colg+1];
            float* f = c[mi][ni];
            *(float2*)(out + (size_t)row*CDIM + colg)     = make_float2(f[0]+b0, f[1]+b1);
            *(float2*)(out + (size_t)(row+8)*CDIM + colg) = make_float2(f[2]+b0, f[3]+b1);
        }
    }
}

// ---------------- RoPE + fp16 convert --------------------------------------
__global__ __launch_bounds__(256) void rope_split_kernel()
{
    const int per = BATCH*HEADS*NSEQ*32;
    int idx = blockIdx.x*256 + threadIdx.x;
    bool isq = idx < per;
    int rem = isq ? idx : idx - per;
    int pair = rem & 31;
    int rowI = rem >> 5;
    int n = rowI & (NSEQ-1);

    float inv = powf(10000.0f, -(float)pair * (1.0f/32.0f));
    float s, cc;
    sincosf((float)n * inv, &s, &cc);

    const float* src = isq ? g_qf : g_kf;
    __half* dst = isq ? g_qh : g_kh;
    size_t p0 = (size_t)rowI*64 + pair;
    float t1 = src[p0], t2 = src[p0+32];
    dst[p0]    = __float2half_rn(t1*cc - t2*s);
    dst[p0+32] = __float2half_rn(t2*cc + t1*s);
}

// ====== pure-fp16 flash attention: single-plane Q/K/V/P =====================
// Region A (18,432B = 9216 halves): first Q plane (128x72), then K/V stage
// for odd kt. Region B (at +9216 el): K/V stage for even kt.
// Stage layout (elements): Kh@0 (64x72), Vh@4608 (64x72, natural [j][d]).
#define ALD      72
#define REG_ELEM (2*64*ALD)          // 9216 elements = 18432 B
#define ATTN_SMEM (2*REG_ELEM*2)     // 36864 B

__device__ __forceinline__ void attn_prefetch(uint32_t smem_u32, int kt, int bh)
{
    const int tid = threadIdx.x;
    const size_t koff = ((size_t)bh * NSEQ + kt * 64) * HD;
    uint32_t base = smem_u32 + ((kt & 1) ? 0u : (uint32_t)(REG_ELEM * 2));
#pragma unroll
    for (int i = 0; i < 4; i++) {
        int idx = tid + i * 256;            // 0..1023
        int t = idx >> 9;                   // 0=kh, 1=vh
        int r = (idx >> 3) & 63;
        int seg = idx & 7;
        const __half* g = (t == 0 ? g_kh : g_vh) + koff + r * 64 + seg * 8;
        uint32_t d = base + t * 9216 + r * (ALD * 2) + seg * 16;
        cp_async16(d, g);
    }
    CP_COMMIT();
}

__global__ __launch_bounds__(256, 2) void attn_mma_kernel(const float* __restrict__ slopes)
{
    extern __shared__ __half smh[];
    uint32_t smem_u32 = (uint32_t)__cvta_generic_to_shared(smh);

    const int tid = threadIdx.x, wid = tid >> 5, lane = tid & 31;
    const int g = lane >> 2, t2 = (lane & 3) << 1;
    const int qt = blockIdx.x, h = blockIdx.y, b = blockIdx.z;
    const int bh = b*HEADS + h;
    const float slope8 = slopes[h] * 8.0f;

    // load Q plane (128x64) into region A
    __half* sQh = smh;
    const size_t qoff = ((size_t)bh*NSEQ + qt*128)*HD;
    for (int v = tid; v < 1024; v += 256) {
        int row = v >> 3, seg = (v & 7) << 3;
        *(uint4*)(sQh + row*ALD + seg) = *(const uint4*)(g_qh + qoff + row*64 + seg);
    }
    attn_prefetch(smem_u32, 0, bh);      // kt=0 -> region B
    __syncthreads();

    // hoist Q fragments for all 4 k-steps
    uint32_t qh[4][4];
#pragma unroll
    for (int ks = 0; ks < 4; ks++)
        lda_frag(qh[ks], sQh, wid*16, ks*16, ALD);

    float o[8][4];
#pragma unroll
    for (int nt = 0; nt < 8; nt++)
#pragma unroll
        for (int d = 0; d < 4; d++) o[nt][d] = 0.0f;
    float m0 = -1e30f, m1 = -1e30f, l0 = 0.0f, l1 = 0.0f;
    const int rowg = qt*128 + wid*16 + g;   // this thread's rows: rowg, rowg+8

    for (int kt = 0; kt < 32; kt++) {
        CP_WAIT(0);
        __syncthreads();     // all warps done with other region (and Q hoist at kt=0)
        if (kt + 1 < 32) attn_prefetch(smem_u32, kt + 1, bh);

        __half* reg = smh + ((kt & 1) ? 0 : REG_ELEM);
        __half* sKh = reg;
        __half* sVh = reg + 4608;

        // S = Q K^T : single-plane fp16
        float s[8][4];
#pragma unroll
        for (int nt = 0; nt < 8; nt++)
#pragma unroll
            for (int d = 0; d < 4; d++) s[nt][d] = 0.0f;
#pragma unroll
        for (int ks = 0; ks < 4; ks++) {
#pragma unroll
            for (int ntp = 0; ntp < 4; ntp++) {
                uint32_t kh4[4];
                ldbx4(kh4, sKh, ntp*16, ks*16, ALD);
                mma_f16(s[2*ntp],   qh[ks], &kh4[0]);
                mma_f16(s[2*ntp+1], qh[ks], &kh4[2]);
            }
        }

        // scale + ALiBi, row max
        float mx0 = -1e30f, mx1 = -1e30f;
#pragma unroll
        for (int nt = 0; nt < 8; nt++) {
            int colb = kt*64 + nt*8 + t2;
            float d00 = fminf(0.0f, (float)(colb     - rowg));
            float d01 = fminf(0.0f, (float)(colb + 1 - rowg));
            float d10 = fminf(0.0f, (float)(colb     - rowg - 8));
            float d11 = fminf(0.0f, (float)(colb + 1 - rowg - 8));
            s[nt][0] = s[nt][0]*0.125f + slope8*d00;
            s[nt][1] = s[nt][1]*0.125f + slope8*d01;
            s[nt][2] = s[nt][2]*0.125f + slope8*d10;
            s[nt][3] = s[nt][3]*0.125f + slope8*d11;
            mx0 = fmaxf(mx0, fmaxf(s[nt][0], s[nt][1]));
            mx1 = fmaxf(mx1, fmaxf(s[nt][2], s[nt][3]));
        }
#pragma unroll
        for (int off = 1; off <= 2; off <<= 1) {
            mx0 = fmaxf(mx0, __shfl_xor_sync(0xffffffffu, mx0, off));
            mx1 = fmaxf(mx1, __shfl_xor_sync(0xffffffffu, mx1, off));
        }
        float nm0 = fmaxf(m0, mx0), nm1 = fmaxf(m1, mx1);
        float f0 = __expf(m0 - nm0), f1 = __expf(m1 - nm1);
        m0 = nm0; m1 = nm1;

        // exp -> register-resident single-plane fp16 P fragments
        uint32_t ph[4][4];
        float sum0 = 0.0f, sum1 = 0.0f;
#pragma unroll
        for (int nt = 0; nt < 8; nt++) {
            float p0 = __expf(s[nt][0] - nm0);
            float p1 = __expf(s[nt][1] - nm0);
            float p2 = __expf(s[nt][2] - nm1);
            float p3 = __expf(s[nt][3] - nm1);
            sum0 += p0 + p1; sum1 += p2 + p3;
            int ks = nt >> 1, hf = (nt & 1) * 2;
            ph[ks][hf]     = h2u(__floats2half2_rn(p0, p1));
            ph[ks][hf + 1] = h2u(__floats2half2_rn(p2, p3));
        }
#pragma unroll
        for (int off = 1; off <= 2; off <<= 1) {
            sum0 += __shfl_xor_sync(0xffffffffu, sum0, off);
            sum1 += __shfl_xor_sync(0xffffffffu, sum1, off);
        }
        l0 = l0*f0 + sum0;
        l1 = l1*f1 + sum1;
#pragma unroll
        for (int nt = 0; nt < 8; nt++) {
            o[nt][0] *= f0; o[nt][1] *= f0;
            o[nt][2] *= f1; o[nt][3] *= f1;
        }

        // O += P V : single-plane fp16 (V natural layout via trans ldmatrix)
#pragma unroll
        for (int ks = 0; ks < 4; ks++) {
#pragma unroll
            for (int ntp = 0; ntp < 4; ntp++) {
                uint32_t vh4[4];
                ldbx4t(vh4, sVh, ntp*16, ks*16, ALD);
                mma_f16(o[2*ntp],   ph[ks], &vh4[0]);
                mma_f16(o[2*ntp+1], ph[ks], &vh4[2]);
            }
        }
    }

    // epilogue: normalize, bf16-split, store ao planes [B, N, H*D]
    float i0 = 1.0f / l0, i1 = 1.0f / l1;
#pragma unroll
    for (int nt = 0; nt < 8; nt++) {
        int col = h*64 + nt*8 + t2;
        size_t idx0 = ((size_t)b*NSEQ + rowg)*CDIM + col;
        size_t idx1 = idx0 + 8*CDIM;
        bf162 lo0, lo1;
        bf162 hi0 = pack_split(o[nt][0]*i0, o[nt][1]*i0, lo0);
        bf162 hi1 = pack_split(o[nt][2]*i1, o[nt][3]*i1, lo1);
        *(bf162*)(g_aohi + idx0) = hi0; *(bf162*)(g_aolo + idx0) = lo0;
        *(bf162*)(g_aohi + idx1) = hi1; *(bf162*)(g_aolo + idx1) = lo1;
    }
}

// ---------------------------------------------------------------------------
extern "C" void kernel_launch(void* const* d_in, const int* in_sizes, int n_in,
                              void* d_out, int out_size)
{
    const float* x      = (const float*)d_in[0];
    const float* qkv_w  = (const float*)d_in[1];
    const float* proj_w = (const float*)d_in[2];
    const float* proj_b = (const float*)d_in[3];
    const float* slopes = (const float*)d_in[4];
    float* out = (float*)d_out;

    bf16 *xhi, *xlo, *wqhi, *wqlo, *wphi, *wplo;
    cudaGetSymbolAddress((void**)&xhi,  g_xhi);  cudaGetSymbolAddress((void**)&xlo,  g_xlo);
    cudaGetSymbolAddress((void**)&wqhi, g_wqhi); cudaGetSymbolAddress((void**)&wqlo, g_wqlo);
    cudaGetSymbolAddress((void**)&wphi, g_wphi); cudaGetSymbolAddress((void**)&wplo, g_wplo);

    split_kernel<<<MTOK*CDIM/1024, 256>>>(x, xhi, xlo);
    split_kernel<<<3*CDIM*CDIM/1024, 256>>>(qkv_w, wqhi, wqlo);
    split_kernel<<<CDIM*CDIM/1024, 256>>>(proj_w, wphi, wplo);

    cudaFuncSetAttribute(qkv_mma_kernel,
                         cudaFuncAttributeMaxDynamicSharedMemorySize, G_SMEM);
    qkv_mma_kernel<<<dim3(3072/128, MTOK/128), 256, G_SMEM>>>();

    rope_split_kernel<<<2*BATCH*HEADS*NSEQ*32/256, 256>>>();

    cudaFuncSetAttribute(attn_mma_kernel,
                         cudaFuncAttributeMaxDynamicSharedMemorySize, ATTN_SMEM);
    attn_mma_kernel<<<dim3(NSEQ/128, HEADS, BATCH), 256, ATTN_SMEM>>>(slopes);

    cudaFuncSetAttribute(proj_mma_kernel,
                         cudaFuncAttributeMaxDynamicSharedMemorySize, G_SMEM);
    proj_mma_kernel<<<dim3(CDIM/128, MTOK/128), 256, G_SMEM>>>(proj_b, out);
}

// round 9
// speedup vs baseline: 6.3644x; 1.6220x over previous
#include <cuda_runtime.h>
#include <cuda_fp16.h>
#include <cstdint>
#include <math.h>

#define NSEQ   2048
#define BATCH  2
#define HEADS  16
#define HD     64
#define CDIM   1024
#define MTOK   (BATCH*NSEQ)      // 4096

// ---------------- device scratch (no allocations allowed) ------------------
__device__ __align__(16) __half g_x[MTOK*CDIM];
__device__ __align__(16) __half g_wq[3*CDIM*CDIM];
__device__ __align__(16) __half g_wp[CDIM*CDIM];
__device__ __align__(16) float  g_qf[MTOK*CDIM], g_kf[MTOK*CDIM];
__device__ __align__(16) __half g_qh[MTOK*CDIM];   // q fp16 (post-RoPE)
__device__ __align__(16) __half g_kh[MTOK*CDIM];   // k fp16 (post-RoPE)
__device__ __align__(16) __half g_vh[MTOK*CDIM];   // v fp16
__device__ __align__(16) __half g_ao[MTOK*CDIM];   // attention out fp16

// ======================= helpers ===========================================
__device__ __forceinline__ uint32_t h2u(__half2 v) {
    union { __half2 h; uint32_t u; } c; c.h = v; return c.u;
}

__device__ __forceinline__ void mma_f16(float c[4], const uint32_t a[4], const uint32_t b[2]) {
    asm volatile(
        "mma.sync.aligned.m16n8k16.row.col.f32.f16.f16.f32 "
        "{%0,%1,%2,%3}, {%4,%5,%6,%7}, {%8,%9}, {%0,%1,%2,%3};\n"
        : "+f"(c[0]), "+f"(c[1]), "+f"(c[2]), "+f"(c[3])
        : "r"(a[0]), "r"(a[1]), "r"(a[2]), "r"(a[3]), "r"(b[0]), "r"(b[1]));
}

// A fragment (m16 x k16, row-major in smem)
__device__ __forceinline__ void lda_frag(uint32_t r[4], const __half* base, int row0, int col0, int ld) {
    const int lane = threadIdx.x & 31;
    const __half* p = base + (row0 + (lane & 15)) * ld + col0 + ((lane >> 4) << 3);
    uint32_t a = (uint32_t)__cvta_generic_to_shared(p);
    asm volatile("ldmatrix.sync.aligned.m8n8.x4.shared.b16 {%0,%1,%2,%3}, [%4];"
                 : "=r"(r[0]), "=r"(r[1]), "=r"(r[2]), "=r"(r[3]) : "r"(a));
}

// TWO B fragments (k16 x n8 each) for n0..n0+15; smem holds B^T row-major
__device__ __forceinline__ void ldbx4(uint32_t r[4], const __half* base, int n0, int k0, int ld) {
    const int lane = threadIdx.x & 31;
    const __half* p = base + (n0 + ((lane >> 4) << 3) + (lane & 7)) * ld
                           + k0 + (((lane >> 3) & 1) << 3);
    uint32_t a = (uint32_t)__cvta_generic_to_shared(p);
    asm volatile("ldmatrix.sync.aligned.m8n8.x4.shared.b16 {%0,%1,%2,%3}, [%4];"
                 : "=r"(r[0]), "=r"(r[1]), "=r"(r[2]), "=r"(r[3]) : "r"(a));
}

// TWO B fragments from NATURAL row-major B [k][n] via trans (for V)
__device__ __forceinline__ void ldbx4t(uint32_t r[4], const __half* base, int n0, int k0, int ld) {
    const int lane = threadIdx.x & 31;
    const __half* p = base + (k0 + (lane & 15)) * ld + n0 + ((lane >> 4) << 3);
    uint32_t a = (uint32_t)__cvta_generic_to_shared(p);
    asm volatile("ldmatrix.sync.aligned.m8n8.x4.trans.shared.b16 {%0,%1,%2,%3}, [%4];"
                 : "=r"(r[0]), "=r"(r[1]), "=r"(r[2]), "=r"(r[3]) : "r"(a));
}

__device__ __forceinline__ void cp_async16(uint32_t saddr, const void* gaddr) {
    asm volatile("cp.async.cg.shared.global [%0], [%1], 16;" :: "r"(saddr), "l"(gaddr));
}
#define CP_COMMIT()  asm volatile("cp.async.commit_group;" ::: "memory")
#define CP_WAIT(n)   asm volatile("cp.async.wait_group %0;" :: "n"(n) : "memory")

// ---------------- fp32 -> fp16 convert -------------------------------------
__global__ __launch_bounds__(256) void tohalf_kernel(
    const float* __restrict__ in, __half* __restrict__ out)
{
    int i = blockIdx.x * 256 + threadIdx.x;
    float4 v = ((const float4*)in)[i];
    ((__half2*)out)[2*i]   = __floats2half2_rn(v.x, v.y);
    ((__half2*)out)[2*i+1] = __floats2half2_rn(v.z, v.w);
}

// ================= double-buffered fp16 GEMM tile ==========================
// 128x128 tile, K=1024 in 32 chunks of 32 cols. 2 stages x 2 planes x 128x40.
#define GLDS    40
#define G_PLANE (128*GLDS)          // 5120 halves
#define G_STAGE (2*G_PLANE)         // 10240 halves
#define G_SMEM  (2*G_STAGE*2)       // 40960 bytes

__device__ __forceinline__ void g_prefetch(
    uint32_t smem_u32, int c, const __half* A, const __half* B)
{
    const int tid = threadIdx.x;
    uint32_t sb = smem_u32 + (c & 1) * (G_STAGE * 2);
    const __half* gp[2] = {A, B};
#pragma unroll
    for (int i = 0; i < 4; i++) {
        int idx = tid + i * 256;            // 0..1023
        int p = idx >> 9, r = (idx >> 2) & 127, seg = idx & 3;
        const __half* g = gp[p] + (size_t)r * 1024 + c * 32 + seg * 8;
        uint32_t d = sb + p * (G_PLANE * 2) + r * (GLDS * 2) + seg * 16;
        cp_async16(d, g);
    }
    CP_COMMIT();
}

__device__ __forceinline__ void gemm_tile2(
    const __half* __restrict__ A, const __half* __restrict__ B,
    __half* smem, float c[4][4][4])
{
    uint32_t smem_u32 = (uint32_t)__cvta_generic_to_shared(smem);
    const int wid = threadIdx.x >> 5;
    const int wm = wid >> 2, wn = wid & 3;

    g_prefetch(smem_u32, 0, A, B);

    for (int ch = 0; ch < 32; ch++) {
        CP_WAIT(0);
        __syncthreads();
        if (ch + 1 < 32) g_prefetch(smem_u32, ch + 1, A, B);

        __half* st = smem + (ch & 1) * G_STAGE;
        __half* sA = st;
        __half* sB = st + G_PLANE;

#pragma unroll
        for (int ks = 0; ks < 32; ks += 16) {
            uint32_t b4[2][4];
#pragma unroll
            for (int ntp = 0; ntp < 2; ntp++)
                ldbx4(b4[ntp], sB, wn * 32 + ntp * 16, ks, GLDS);
#pragma unroll
            for (int mi = 0; mi < 4; mi++) {
                uint32_t a4[4];
                lda_frag(a4, sA, wm * 64 + mi * 16, ks, GLDS);
#pragma unroll
                for (int ni = 0; ni < 4; ni++)
                    mma_f16(c[mi][ni], a4, &b4[ni >> 1][(ni & 1) * 2]);
            }
        }
    }
}

// ---------------- QKV GEMM + scatter epilogue ------------------------------
__global__ __launch_bounds__(256, 2) void qkv_mma_kernel()
{
    extern __shared__ __half gsm[];
    float c[4][4][4];
#pragma unroll
    for (int a = 0; a < 4; a++)
#pragma unroll
        for (int b = 0; b < 4; b++)
#pragma unroll
            for (int d = 0; d < 4; d++) c[a][b][d] = 0.0f;

    const int rowBase = blockIdx.y * 128, colBase = blockIdx.x * 128;
    gemm_tile2(g_x + (size_t)rowBase*1024, g_wq + (size_t)colBase*1024, gsm, c);

    const int lane = threadIdx.x & 31, wid = threadIdx.x >> 5;
    const int wm = wid >> 2, wn = wid & 3;
    const int g = lane >> 2, t2 = (lane & 3) << 1;
    const int tix = colBase >> 10;   // 0=q, 1=k, 2=v (uniform per block)

#pragma unroll
    for (int mi = 0; mi < 4; mi++) {
        int row = rowBase + wm*64 + mi*16 + g;
        int bb = row >> 11, n = row & 2047;
#pragma unroll
        for (int ni = 0; ni < 4; ni++) {
            int colg = colBase + wn*32 + ni*8 + t2;
            int rem = colg & 1023, hh = rem >> 6, d = rem & 63;
            size_t base0 = (((size_t)(bb * HEADS + hh)) * NSEQ + n) * HD + d;
            size_t base1 = base0 + 8*HD;
            float* f = c[mi][ni];
            if (tix == 0) {
                *(float2*)(g_qf + base0) = make_float2(f[0], f[1]);
                *(float2*)(g_qf + base1) = make_float2(f[2], f[3]);
            } else if (tix == 1) {
                *(float2*)(g_kf + base0) = make_float2(f[0], f[1]);
                *(float2*)(g_kf + base1) = make_float2(f[2], f[3]);
            } else {
                *(__half2*)(g_vh + base0) = __floats2half2_rn(f[0], f[1]);
                *(__half2*)(g_vh + base1) = __floats2half2_rn(f[2], f[3]);
            }
        }
    }
}

// ---------------- output projection ---------------------------------------
__global__ __launch_bounds__(256, 2) void proj_mma_kernel(
    const float* __restrict__ bias, float* __restrict__ out)
{
    extern __shared__ __half gsm[];
    float c[4][4][4];
#pragma unroll
    for (int a = 0; a < 4; a++)
#pragma unroll
        for (int b = 0; b < 4; b++)
#pragma unroll
            for (int d = 0; d < 4; d++) c[a][b][d] = 0.0f;

    const int rowBase = blockIdx.y * 128, colBase = blockIdx.x * 128;
    gemm_tile2(g_ao + (size_t)rowBase*1024, g_wp + (size_t)colBase*1024, gsm, c);

    const int lane = threadIdx.x & 31, wid = threadIdx.x >> 5;
    const int wm = wid >> 2, wn = wid & 3;
    const int g = lane >> 2, t2 = (lane & 3) << 1;

#pragma unroll
    for (int mi = 0; mi < 4; mi++) {
        int row = rowBase + wm*64 + mi*16 + g;
#pragma unroll
        for (int ni = 0; ni < 4; ni++) {
            int colg = colBase + wn*32 + ni*8 + t2;
            float b0 = bias[colg], b1 = bias[colg+1];
            float* f = c[mi][ni];
            *(float2*)(out + (size_t)row*CDIM + colg)     = make_float2(f[0]+b0, f[1]+b1);
            *(float2*)(out + (size_t)(row+8)*CDIM + colg) = make_float2(f[2]+b0, f[3]+b1);
        }
    }
}

// ---------------- RoPE + fp16 convert --------------------------------------
__global__ __launch_bounds__(256) void rope_split_kernel()
{
    const int per = BATCH*HEADS*NSEQ*32;
    int idx = blockIdx.x*256 + threadIdx.x;
    bool isq = idx < per;
    int rem = isq ? idx : idx - per;
    int pair = rem & 31;
    int rowI = rem >> 5;
    int n = rowI & (NSEQ-1);

    float inv = powf(10000.0f, -(float)pair * (1.0f/32.0f));
    float s, cc;
    sincosf((float)n * inv, &s, &cc);

    const float* src = isq ? g_qf : g_kf;
    __half* dst = isq ? g_qh : g_kh;
    size_t p0 = (size_t)rowI*64 + pair;
    float t1 = src[p0], t2 = src[p0+32];
    dst[p0]    = __float2half_rn(t1*cc - t2*s);
    dst[p0+32] = __float2half_rn(t2*cc + t1*s);
}

// ====== pure-fp16 flash attention: single-plane Q/K/V/P =====================
// Region A (18,432B = 9216 halves): first Q plane (128x72), then K/V stage
// for odd kt. Region B (at +9216 el): K/V stage for even kt.
// Stage layout (elements): Kh@0 (64x72), Vh@4608 (64x72, natural [j][d]).
#define ALD      72
#define REG_ELEM (2*64*ALD)          // 9216 elements = 18432 B
#define ATTN_SMEM (2*REG_ELEM*2)     // 36864 B

__device__ __forceinline__ void attn_prefetch(uint32_t smem_u32, int kt, int bh)
{
    const int tid = threadIdx.x;
    const size_t koff = ((size_t)bh * NSEQ + kt * 64) * HD;
    uint32_t base = smem_u32 + ((kt & 1) ? 0u : (uint32_t)(REG_ELEM * 2));
#pragma unroll
    for (int i = 0; i < 4; i++) {
        int idx = tid + i * 256;            // 0..1023
        int t = idx >> 9;                   // 0=kh, 1=vh
        int r = (idx >> 3) & 63;
        int seg = idx & 7;
        const __half* g = (t == 0 ? g_kh : g_vh) + koff + r * 64 + seg * 8;
        uint32_t d = base + t * 9216 + r * (ALD * 2) + seg * 16;
        cp_async16(d, g);
    }
    CP_COMMIT();
}

__global__ __launch_bounds__(256, 2) void attn_mma_kernel(const float* __restrict__ slopes)
{
    extern __shared__ __half smh[];
    uint32_t smem_u32 = (uint32_t)__cvta_generic_to_shared(smh);

    const int tid = threadIdx.x, wid = tid >> 5, lane = tid & 31;
    const int g = lane >> 2, t2 = (lane & 3) << 1;
    const int qt = blockIdx.x, h = blockIdx.y, b = blockIdx.z;
    const int bh = b*HEADS + h;
    const float slope8 = slopes[h] * 8.0f;

    // load Q plane (128x64) into region A
    __half* sQh = smh;
    const size_t qoff = ((size_t)bh*NSEQ + qt*128)*HD;
    for (int v = tid; v < 1024; v += 256) {
        int row = v >> 3, seg = (v & 7) << 3;
        *(uint4*)(sQh + row*ALD + seg) = *(const uint4*)(g_qh + qoff + row*64 + seg);
    }
    attn_prefetch(smem_u32, 0, bh);      // kt=0 -> region B
    __syncthreads();

    // hoist Q fragments for all 4 k-steps
    uint32_t qh[4][4];
#pragma unroll
    for (int ks = 0; ks < 4; ks++)
        lda_frag(qh[ks], sQh, wid*16, ks*16, ALD);

    float o[8][4];
#pragma unroll
    for (int nt = 0; nt < 8; nt++)
#pragma unroll
        for (int d = 0; d < 4; d++) o[nt][d] = 0.0f;
    float m0 = -1e30f, m1 = -1e30f, l0 = 0.0f, l1 = 0.0f;
    const int rowg = qt*128 + wid*16 + g;   // this thread's rows: rowg, rowg+8

    for (int kt = 0; kt < 32; kt++) {
        CP_WAIT(0);
        __syncthreads();     // all warps done with other region (and Q hoist at kt=0)
        if (kt + 1 < 32) attn_prefetch(smem_u32, kt + 1, bh);

        __half* reg = smh + ((kt & 1) ? 0 : REG_ELEM);
        __half* sKh = reg;
        __half* sVh = reg + 4608;

        // S = Q K^T : single-plane fp16
        float s[8][4];
#pragma unroll
        for (int nt = 0; nt < 8; nt++)
#pragma unroll
            for (int d = 0; d < 4; d++) s[nt][d] = 0.0f;
#pragma unroll
        for (int ks = 0; ks < 4; ks++) {
#pragma unroll
            for (int ntp = 0; ntp < 4; ntp++) {
                uint32_t kh4[4];
                ldbx4(kh4, sKh, ntp*16, ks*16, ALD);
                mma_f16(s[2*ntp],   qh[ks], &kh4[0]);
                mma_f16(s[2*ntp+1], qh[ks], &kh4[2]);
            }
        }

        // scale + ALiBi, row max
        float mx0 = -1e30f, mx1 = -1e30f;
#pragma unroll
        for (int nt = 0; nt < 8; nt++) {
            int colb = kt*64 + nt*8 + t2;
            float d00 = fminf(0.0f, (float)(colb     - rowg));
            float d01 = fminf(0.0f, (float)(colb + 1 - rowg));
            float d10 = fminf(0.0f, (float)(colb     - rowg - 8));
            float d11 = fminf(0.0f, (float)(colb + 1 - rowg - 8));
            s[nt][0] = s[nt][0]*0.125f + slope8*d00;
            s[nt][1] = s[nt][1]*0.125f + slope8*d01;
            s[nt][2] = s[nt][2]*0.125f + slope8*d10;
            s[nt][3] = s[nt][3]*0.125f + slope8*d11;
            mx0 = fmaxf(mx0, fmaxf(s[nt][0], s[nt][1]));
            mx1 = fmaxf(mx1, fmaxf(s[nt][2], s[nt][3]));
        }
#pragma unroll
        for (int off = 1; off <= 2; off <<= 1) {
            mx0 = fmaxf(mx0, __shfl_xor_sync(0xffffffffu, mx0, off));
            mx1 = fmaxf(mx1, __shfl_xor_sync(0xffffffffu, mx1, off));
        }
        float nm0 = fmaxf(m0, mx0), nm1 = fmaxf(m1, mx1);
        float f0 = __expf(m0 - nm0), f1 = __expf(m1 - nm1);
        m0 = nm0; m1 = nm1;

        // exp -> register-resident single-plane fp16 P fragments
        uint32_t ph[4][4];
        float sum0 = 0.0f, sum1 = 0.0f;
#pragma unroll
        for (int nt = 0; nt < 8; nt++) {
            float p0 = __expf(s[nt][0] - nm0);
            float p1 = __expf(s[nt][1] - nm0);
            float p2 = __expf(s[nt][2] - nm1);
            float p3 = __expf(s[nt][3] - nm1);
            sum0 += p0 + p1; sum1 += p2 + p3;
            int ks = nt >> 1, hf = (nt & 1) * 2;
            ph[ks][hf]     = h2u(__floats2half2_rn(p0, p1));
            ph[ks][hf + 1] = h2u(__floats2half2_rn(p2, p3));
        }
#pragma unroll
        for (int off = 1; off <= 2; off <<= 1) {
            sum0 += __shfl_xor_sync(0xffffffffu, sum0, off);
            sum1 += __shfl_xor_sync(0xffffffffu, sum1, off);
        }
        l0 = l0*f0 + sum0;
        l1 = l1*f1 + sum1;
#pragma unroll
        for (int nt = 0; nt < 8; nt++) {
            o[nt][0] *= f0; o[nt][1] *= f0;
            o[nt][2] *= f1; o[nt][3] *= f1;
        }

        // O += P V : single-plane fp16 (V natural layout via trans ldmatrix)
#pragma unroll
        for (int ks = 0; ks < 4; ks++) {
#pragma unroll
            for (int ntp = 0; ntp < 4; ntp++) {
                uint32_t vh4[4];
                ldbx4t(vh4, sVh, ntp*16, ks*16, ALD);
                mma_f16(o[2*ntp],   ph[ks], &vh4[0]);
                mma_f16(o[2*ntp+1], ph[ks], &vh4[2]);
            }
        }
    }

    // epilogue: normalize, store ao as fp16 [B, N, H*D]
    float i0 = 1.0f / l0, i1 = 1.0f / l1;
#pragma unroll
    for (int nt = 0; nt < 8; nt++) {
        int col = h*64 + nt*8 + t2;
        size_t idx0 = ((size_t)b*NSEQ + rowg)*CDIM + col;
        size_t idx1 = idx0 + 8*CDIM;
        *(__half2*)(g_ao + idx0) = __floats2half2_rn(o[nt][0]*i0, o[nt][1]*i0);
        *(__half2*)(g_ao + idx1) = __floats2half2_rn(o[nt][2]*i1, o[nt][3]*i1);
    }
}

// ---------------------------------------------------------------------------
extern "C" void kernel_launch(void* const* d_in, const int* in_sizes, int n_in,
                              void* d_out, int out_size)
{
    const float* x      = (const float*)d_in[0];
    const float* qkv_w  = (const float*)d_in[1];
    const float* proj_w = (const float*)d_in[2];
    const float* proj_b = (const float*)d_in[3];
    const float* slopes = (const float*)d_in[4];
    float* out = (float*)d_out;

    __half *xh, *wqh, *wph;
    cudaGetSymbolAddress((void**)&xh,  g_x);
    cudaGetSymbolAddress((void**)&wqh, g_wq);
    cudaGetSymbolAddress((void**)&wph, g_wp);

    tohalf_kernel<<<MTOK*CDIM/1024, 256>>>(x, xh);
    tohalf_kernel<<<3*CDIM*CDIM/1024, 256>>>(qkv_w, wqh);
    tohalf_kernel<<<CDIM*CDIM/1024, 256>>>(proj_w, wph);

    cudaFuncSetAttribute(qkv_mma_kernel,
                         cudaFuncAttributeMaxDynamicSharedMemorySize, G_SMEM);
    qkv_mma_kernel<<<dim3(3072/128, MTOK/128), 256, G_SMEM>>>();

    rope_split_kernel<<<2*BATCH*HEADS*NSEQ*32/256, 256>>>();

    cudaFuncSetAttribute(attn_mma_kernel,
                         cudaFuncAttributeMaxDynamicSharedMemorySize, ATTN_SMEM);
    attn_mma_kernel<<<dim3(NSEQ/128, HEADS, BATCH), 256, ATTN_SMEM>>>(slopes);

    cudaFuncSetAttribute(proj_mma_kernel,
                         cudaFuncAttributeMaxDynamicSharedMemorySize, G_SMEM);
    proj_mma_kernel<<<dim3(CDIM/128, MTOK/128), 256, G_SMEM>>>(proj_b, out);
}

// round 10
// speedup vs baseline: 6.5620x; 1.0311x over previous
#include <cuda_runtime.h>
#include <cuda_fp16.h>
#include <cstdint>
#include <math.h>

#define NSEQ   2048
#define BATCH  2
#define HEADS  16
#define HD     64
#define CDIM   1024
#define MTOK   (BATCH*NSEQ)      // 4096

// ---------------- device scratch (no allocations allowed) ------------------
__device__ __align__(16) __half g_x[MTOK*CDIM];
__device__ __align__(16) __half g_wq[3*CDIM*CDIM];
__device__ __align__(16) __half g_wp[CDIM*CDIM];
__device__ __align__(16) float  g_qf[MTOK*CDIM], g_kf[MTOK*CDIM];
__device__ __align__(16) __half g_qh[MTOK*CDIM];   // q fp16 (post-RoPE)
__device__ __align__(16) __half g_kh[MTOK*CDIM];   // k fp16 (post-RoPE)
__device__ __align__(16) __half g_vh[MTOK*CDIM];   // v fp16
__device__ __align__(16) __half g_ao[MTOK*CDIM];   // attention out fp16
__device__ __align__(16) float  g_sin[NSEQ*32], g_cos[NSEQ*32];

// ======================= helpers ===========================================
__device__ __forceinline__ uint32_t h2u(__half2 v) {
    union { __half2 h; uint32_t u; } c; c.h = v; return c.u;
}

__device__ __forceinline__ void mma_f16(float c[4], const uint32_t a[4], const uint32_t b[2]) {
    asm volatile(
        "mma.sync.aligned.m16n8k16.row.col.f32.f16.f16.f32 "
        "{%0,%1,%2,%3}, {%4,%5,%6,%7}, {%8,%9}, {%0,%1,%2,%3};\n"
        : "+f"(c[0]), "+f"(c[1]), "+f"(c[2]), "+f"(c[3])
        : "r"(a[0]), "r"(a[1]), "r"(a[2]), "r"(a[3]), "r"(b[0]), "r"(b[1]));
}

// A fragment (m16 x k16, row-major in smem)
__device__ __forceinline__ void lda_frag(uint32_t r[4], const __half* base, int row0, int col0, int ld) {
    const int lane = threadIdx.x & 31;
    const __half* p = base + (row0 + (lane & 15)) * ld + col0 + ((lane >> 4) << 3);
    uint32_t a = (uint32_t)__cvta_generic_to_shared(p);
    asm volatile("ldmatrix.sync.aligned.m8n8.x4.shared.b16 {%0,%1,%2,%3}, [%4];"
                 : "=r"(r[0]), "=r"(r[1]), "=r"(r[2]), "=r"(r[3]) : "r"(a));
}

// TWO B fragments (k16 x n8 each) for n0..n0+15; smem holds B^T row-major
__device__ __forceinline__ void ldbx4(uint32_t r[4], const __half* base, int n0, int k0, int ld) {
    const int lane = threadIdx.x & 31;
    const __half* p = base + (n0 + ((lane >> 4) << 3) + (lane & 7)) * ld
                           + k0 + (((lane >> 3) & 1) << 3);
    uint32_t a = (uint32_t)__cvta_generic_to_shared(p);
    asm volatile("ldmatrix.sync.aligned.m8n8.x4.shared.b16 {%0,%1,%2,%3}, [%4];"
                 : "=r"(r[0]), "=r"(r[1]), "=r"(r[2]), "=r"(r[3]) : "r"(a));
}

// TWO B fragments from NATURAL row-major B [k][n] via trans (for V)
__device__ __forceinline__ void ldbx4t(uint32_t r[4], const __half* base, int n0, int k0, int ld) {
    const int lane = threadIdx.x & 31;
    const __half* p = base + (k0 + (lane & 15)) * ld + n0 + ((lane >> 4) << 3);
    uint32_t a = (uint32_t)__cvta_generic_to_shared(p);
    asm volatile("ldmatrix.sync.aligned.m8n8.x4.trans.shared.b16 {%0,%1,%2,%3}, [%4];"
                 : "=r"(r[0]), "=r"(r[1]), "=r"(r[2]), "=r"(r[3]) : "r"(a));
}

__device__ __forceinline__ void cp_async16(uint32_t saddr, const void* gaddr) {
    asm volatile("cp.async.cg.shared.global [%0], [%1], 16;" :: "r"(saddr), "l"(gaddr));
}
#define CP_COMMIT()  asm volatile("cp.async.commit_group;" ::: "memory")
#define CP_WAIT(n)   asm volatile("cp.async.wait_group %0;" :: "n"(n) : "memory")

// ---------------- fp32 -> fp16 convert -------------------------------------
__global__ __launch_bounds__(256) void tohalf_kernel(
    const float* __restrict__ in, __half* __restrict__ out)
{
    int i = blockIdx.x * 256 + threadIdx.x;
    float4 v = ((const float4*)in)[i];
    ((__half2*)out)[2*i]   = __floats2half2_rn(v.x, v.y);
    ((__half2*)out)[2*i+1] = __floats2half2_rn(v.z, v.w);
}

// ================= double-buffered fp16 GEMM tile ==========================
// 128x128 tile, K=1024 in 16 chunks of 64 cols. 2 stages x 2 planes x 128x72.
#define GLDS    72
#define G_PLANE (128*GLDS)          // 9216 halves
#define G_STAGE (2*G_PLANE)         // 18432 halves
#define G_SMEM  (2*G_STAGE*2)       // 73728 bytes

__device__ __forceinline__ void g_prefetch(
    uint32_t smem_u32, int c, const __half* A, const __half* B)
{
    const int tid = threadIdx.x;
    uint32_t sb = smem_u32 + (c & 1) * (G_STAGE * 2);
    const __half* gp[2] = {A, B};
#pragma unroll
    for (int i = 0; i < 8; i++) {
        int idx = tid + i * 256;            // 0..2047
        int p = idx >> 10, r = (idx >> 3) & 127, seg = idx & 7;
        const __half* g = gp[p] + (size_t)r * 1024 + c * 64 + seg * 8;
        uint32_t d = sb + p * (G_PLANE * 2) + r * (GLDS * 2) + seg * 16;
        cp_async16(d, g);
    }
    CP_COMMIT();
}

__device__ __forceinline__ void gemm_tile2(
    const __half* __restrict__ A, const __half* __restrict__ B,
    __half* smem, float c[4][4][4])
{
    uint32_t smem_u32 = (uint32_t)__cvta_generic_to_shared(smem);
    const int wid = threadIdx.x >> 5;
    const int wm = wid >> 2, wn = wid & 3;

    g_prefetch(smem_u32, 0, A, B);

    for (int ch = 0; ch < 16; ch++) {
        CP_WAIT(0);
        __syncthreads();
        if (ch + 1 < 16) g_prefetch(smem_u32, ch + 1, A, B);

        __half* st = smem + (ch & 1) * G_STAGE;
        __half* sA = st;
        __half* sB = st + G_PLANE;

#pragma unroll
        for (int ks = 0; ks < 64; ks += 16) {
            uint32_t b4[2][4];
#pragma unroll
            for (int ntp = 0; ntp < 2; ntp++)
                ldbx4(b4[ntp], sB, wn * 32 + ntp * 16, ks, GLDS);
#pragma unroll
            for (int mi = 0; mi < 4; mi++) {
                uint32_t a4[4];
                lda_frag(a4, sA, wm * 64 + mi * 16, ks, GLDS);
#pragma unroll
                for (int ni = 0; ni < 4; ni++)
                    mma_f16(c[mi][ni], a4, &b4[ni >> 1][(ni & 1) * 2]);
            }
        }
    }
}

// ---------------- QKV GEMM + scatter epilogue ------------------------------
__global__ __launch_bounds__(256, 2) void qkv_mma_kernel()
{
    extern __shared__ __half gsm[];
    float c[4][4][4];
#pragma unroll
    for (int a = 0; a < 4; a++)
#pragma unroll
        for (int b = 0; b < 4; b++)
#pragma unroll
            for (int d = 0; d < 4; d++) c[a][b][d] = 0.0f;

    const int rowBase = blockIdx.y * 128, colBase = blockIdx.x * 128;
    gemm_tile2(g_x + (size_t)rowBase*1024, g_wq + (size_t)colBase*1024, gsm, c);

    const int lane = threadIdx.x & 31, wid = threadIdx.x >> 5;
    const int wm = wid >> 2, wn = wid & 3;
    const int g = lane >> 2, t2 = (lane & 3) << 1;
    const int tix = colBase >> 10;   // 0=q, 1=k, 2=v (uniform per block)

#pragma unroll
    for (int mi = 0; mi < 4; mi++) {
        int row = rowBase + wm*64 + mi*16 + g;
        int bb = row >> 11, n = row & 2047;
#pragma unroll
        for (int ni = 0; ni < 4; ni++) {
            int colg = colBase + wn*32 + ni*8 + t2;
            int rem = colg & 1023, hh = rem >> 6, d = rem & 63;
            size_t base0 = (((size_t)(bb * HEADS + hh)) * NSEQ + n) * HD + d;
            size_t base1 = base0 + 8*HD;
            float* f = c[mi][ni];
            if (tix == 0) {
                *(float2*)(g_qf + base0) = make_float2(f[0], f[1]);
                *(float2*)(g_qf + base1) = make_float2(f[2], f[3]);
            } else if (tix == 1) {
                *(float2*)(g_kf + base0) = make_float2(f[0], f[1]);
                *(float2*)(g_kf + base1) = make_float2(f[2], f[3]);
            } else {
                *(__half2*)(g_vh + base0) = __floats2half2_rn(f[0], f[1]);
                *(__half2*)(g_vh + base1) = __floats2half2_rn(f[2], f[3]);
            }
        }
    }
}

// ---------------- output projection ---------------------------------------
__global__ __launch_bounds__(256, 2) void proj_mma_kernel(
    const float* __restrict__ bias, float* __restrict__ out)
{
    extern __shared__ __half gsm[];
    float c[4][4][4];
#pragma unroll
    for (int a = 0; a < 4; a++)
#pragma unroll
        for (int b = 0; b < 4; b++)
#pragma unroll
            for (int d = 0; d < 4; d++) c[a][b][d] = 0.0f;

    const int rowBase = blockIdx.y * 128, colBase = blockIdx.x * 128;
    gemm_tile2(g_ao + (size_t)rowBase*1024, g_wp + (size_t)colBase*1024, gsm, c);

    const int lane = threadIdx.x & 31, wid = threadIdx.x >> 5;
    const int wm = wid >> 2, wn = wid & 3;
    const int g = lane >> 2, t2 = (lane & 3) << 1;

#pragma unroll
    for (int mi = 0; mi < 4; mi++) {
        int row = rowBase + wm*64 + mi*16 + g;
#pragma unroll
        for (int ni = 0; ni < 4; ni++) {
            int colg = colBase + wn*32 + ni*8 + t2;
            float b0 = bias[colg], b1 = bias[colg+1];
            float* f = c[mi][ni];
            *(float2*)(out + (size_t)row*CDIM + colg)     = make_float2(f[0]+b0, f[1]+b1);
            *(float2*)(out + (size_t)(row+8)*CDIM + colg) = make_float2(f[2]+b0, f[3]+b1);
        }
    }
}

// ---------------- RoPE: table + apply --------------------------------------
__global__ __launch_bounds__(256) void rope_table_kernel()
{
    int idx = blockIdx.x * 256 + threadIdx.x;      // 0..65535
    int n = idx >> 5, pair = idx & 31;
    float inv = powf(10000.0f, -(float)pair * (1.0f/32.0f));
    float s, cc;
    sincosf((float)n * inv, &s, &cc);
    g_sin[idx] = s;
    g_cos[idx] = cc;
}

__global__ __launch_bounds__(256) void rope_apply_kernel()
{
    const int per = BATCH*HEADS*NSEQ*32;
    int idx = blockIdx.x*256 + threadIdx.x;
    bool isq = idx < per;
    int rem = isq ? idx : idx - per;
    int pair = rem & 31;
    int rowI = rem >> 5;
    int n = rowI & (NSEQ-1);

    float s  = g_sin[n*32 + pair];
    float cc = g_cos[n*32 + pair];

    const float* src = isq ? g_qf : g_kf;
    __half* dst = isq ? g_qh : g_kh;
    size_t p0 = (size_t)rowI*64 + pair;
    float t1 = src[p0], t2 = src[p0+32];
    dst[p0]    = __float2half_rn(t1*cc - t2*s);
    dst[p0+32] = __float2half_rn(t2*cc + t1*s);
}

// ====== pure-fp16 flash attention: single-plane Q/K/V/P =====================
// Region A (18,432B = 9216 halves): first Q plane (128x72), then K/V stage
// for odd kt. Region B (at +9216 el): K/V stage for even kt.
// Stage layout (elements): Kh@0 (64x72), Vh@4608 (64x72, natural [j][d]).
#define ALD      72
#define REG_ELEM (2*64*ALD)          // 9216 elements = 18432 B
#define ATTN_SMEM (2*REG_ELEM*2)     // 36864 B

__device__ __forceinline__ void attn_prefetch(uint32_t smem_u32, int kt, int bh)
{
    const int tid = threadIdx.x;
    const size_t koff = ((size_t)bh * NSEQ + kt * 64) * HD;
    uint32_t base = smem_u32 + ((kt & 1) ? 0u : (uint32_t)(REG_ELEM * 2));
#pragma unroll
    for (int i = 0; i < 4; i++) {
        int idx = tid + i * 256;            // 0..1023
        int t = idx >> 9;                   // 0=kh, 1=vh
        int r = (idx >> 3) & 63;
        int seg = idx & 7;
        const __half* g = (t == 0 ? g_kh : g_vh) + koff + r * 64 + seg * 8;
        uint32_t d = base + t * 9216 + r * (ALD * 2) + seg * 16;
        cp_async16(d, g);
    }
    CP_COMMIT();
}

__global__ __launch_bounds__(256, 2) void attn_mma_kernel(const float* __restrict__ slopes)
{
    extern __shared__ __half smh[];
    uint32_t smem_u32 = (uint32_t)__cvta_generic_to_shared(smh);

    const int tid = threadIdx.x, wid = tid >> 5, lane = tid & 31;
    const int g = lane >> 2, t2 = (lane & 3) << 1;
    const int qt = blockIdx.x, h = blockIdx.y, b = blockIdx.z;
    const int bh = b*HEADS + h;
    const float slope8 = slopes[h] * 8.0f;

    // load Q plane (128x64) into region A
    __half* sQh = smh;
    const size_t qoff = ((size_t)bh*NSEQ + qt*128)*HD;
    for (int v = tid; v < 1024; v += 256) {
        int row = v >> 3, seg = (v & 7) << 3;
        *(uint4*)(sQh + row*ALD + seg) = *(const uint4*)(g_qh + qoff + row*64 + seg);
    }
    attn_prefetch(smem_u32, 0, bh);      // kt=0 -> region B
    __syncthreads();

    // hoist Q fragments for all 4 k-steps
    uint32_t qh[4][4];
#pragma unroll
    for (int ks = 0; ks < 4; ks++)
        lda_frag(qh[ks], sQh, wid*16, ks*16, ALD);

    float o[8][4];
#pragma unroll
    for (int nt = 0; nt < 8; nt++)
#pragma unroll
        for (int d = 0; d < 4; d++) o[nt][d] = 0.0f;
    float m0 = -1e30f, m1 = -1e30f, l0 = 0.0f, l1 = 0.0f;
    const int rowg = qt*128 + wid*16 + g;   // this thread's rows: rowg, rowg+8

    for (int kt = 0; kt < 32; kt++) {
        CP_WAIT(0);
        __syncthreads();     // all warps done with other region (and Q hoist at kt=0)
        if (kt + 1 < 32) attn_prefetch(smem_u32, kt + 1, bh);

        __half* reg = smh + ((kt & 1) ? 0 : REG_ELEM);
        __half* sKh = reg;
        __half* sVh = reg + 4608;

        // S = Q K^T : single-plane fp16
        float s[8][4];
#pragma unroll
        for (int nt = 0; nt < 8; nt++)
#pragma unroll
            for (int d = 0; d < 4; d++) s[nt][d] = 0.0f;
#pragma unroll
        for (int ks = 0; ks < 4; ks++) {
#pragma unroll
            for (int ntp = 0; ntp < 4; ntp++) {
                uint32_t kh4[4];
                ldbx4(kh4, sKh, ntp*16, ks*16, ALD);
                mma_f16(s[2*ntp],   qh[ks], &kh4[0]);
                mma_f16(s[2*ntp+1], qh[ks], &kh4[2]);
            }
        }

        // scale + ALiBi, row max
        float mx0 = -1e30f, mx1 = -1e30f;
#pragma unroll
        for (int nt = 0; nt < 8; nt++) {
            int colb = kt*64 + nt*8 + t2;
            float d00 = fminf(0.0f, (float)(colb     - rowg));
            float d01 = fminf(0.0f, (float)(colb + 1 - rowg));
            float d10 = fminf(0.0f, (float)(colb     - rowg - 8));
            float d11 = fminf(0.0f, (float)(colb + 1 - rowg - 8));
            s[nt][0] = s[nt][0]*0.125f + slope8*d00;
            s[nt][1] = s[nt][1]*0.125f + slope8*d01;
            s[nt][2] = s[nt][2]*0.125f + slope8*d10;
            s[nt][3] = s[nt][3]*0.125f + slope8*d11;
            mx0 = fmaxf(mx0, fmaxf(s[nt][0], s[nt][1]));
            mx1 = fmaxf(mx1, fmaxf(s[nt][2], s[nt][3]));
        }
#pragma unroll
        for (int off = 1; off <= 2; off <<= 1) {
            mx0 = fmaxf(mx0, __shfl_xor_sync(0xffffffffu, mx0, off));
            mx1 = fmaxf(mx1, __shfl_xor_sync(0xffffffffu, mx1, off));
        }
        float nm0 = fmaxf(m0, mx0), nm1 = fmaxf(m1, mx1);
        float f0 = __expf(m0 - nm0), f1 = __expf(m1 - nm1);
        m0 = nm0; m1 = nm1;

        // exp -> register-resident single-plane fp16 P fragments
        uint32_t ph[4][4];
        float sum0 = 0.0f, sum1 = 0.0f;
#pragma unroll
        for (int nt = 0; nt < 8; nt++) {
            float p0 = __expf(s[nt][0] - nm0);
            float p1 = __expf(s[nt][1] - nm0);
            float p2 = __expf(s[nt][2] - nm1);
            float p3 = __expf(s[nt][3] - nm1);
            sum0 += p0 + p1; sum1 += p2 + p3;
            int ks = nt >> 1, hf = (nt & 1) * 2;
            ph[ks][hf]     = h2u(__floats2half2_rn(p0, p1));
            ph[ks][hf + 1] = h2u(__floats2half2_rn(p2, p3));
        }
#pragma unroll
        for (int off = 1; off <= 2; off <<= 1) {
            sum0 += __shfl_xor_sync(0xffffffffu, sum0, off);
            sum1 += __shfl_xor_sync(0xffffffffu, sum1, off);
        }
        l0 = l0*f0 + sum0;
        l1 = l1*f1 + sum1;
#pragma unroll
        for (int nt = 0; nt < 8; nt++) {
            o[nt][0] *= f0; o[nt][1] *= f0;
            o[nt][2] *= f1; o[nt][3] *= f1;
        }

        // O += P V : single-plane fp16 (V natural layout via trans ldmatrix)
#pragma unroll
        for (int ks = 0; ks < 4; ks++) {
#pragma unroll
            for (int ntp = 0; ntp < 4; ntp++) {
                uint32_t vh4[4];
                ldbx4t(vh4, sVh, ntp*16, ks*16, ALD);
                mma_f16(o[2*ntp],   ph[ks], &vh4[0]);
                mma_f16(o[2*ntp+1], ph[ks], &vh4[2]);
            }
        }
    }

    // epilogue: normalize, store ao as fp16 [B, N, H*D]
    float i0 = 1.0f / l0, i1 = 1.0f / l1;
#pragma unroll
    for (int nt = 0; nt < 8; nt++) {
        int col = h*64 + nt*8 + t2;
        size_t idx0 = ((size_t)b*NSEQ + rowg)*CDIM + col;
        size_t idx1 = idx0 + 8*CDIM;
        *(__half2*)(g_ao + idx0) = __floats2half2_rn(o[nt][0]*i0, o[nt][1]*i0);
        *(__half2*)(g_ao + idx1) = __floats2half2_rn(o[nt][2]*i1, o[nt][3]*i1);
    }
}

// ---------------------------------------------------------------------------
extern "C" void kernel_launch(void* const* d_in, const int* in_sizes, int n_in,
                              void* d_out, int out_size)
{
    const float* x      = (const float*)d_in[0];
    const float* qkv_w  = (const float*)d_in[1];
    const float* proj_w = (const float*)d_in[2];
    const float* proj_b = (const float*)d_in[3];
    const float* slopes = (const float*)d_in[4];
    float* out = (float*)d_out;

    __half *xh, *wqh, *wph;
    cudaGetSymbolAddress((void**)&xh,  g_x);
    cudaGetSymbolAddress((void**)&wqh, g_wq);
    cudaGetSymbolAddress((void**)&wph, g_wp);

    rope_table_kernel<<<NSEQ*32/256, 256>>>();
    tohalf_kernel<<<MTOK*CDIM/1024, 256>>>(x, xh);
    tohalf_kernel<<<3*CDIM*CDIM/1024, 256>>>(qkv_w, wqh);
    tohalf_kernel<<<CDIM*CDIM/1024, 256>>>(proj_w, wph);

    cudaFuncSetAttribute(qkv_mma_kernel,
                         cudaFuncAttributeMaxDynamicSharedMemorySize, G_SMEM);
    qkv_mma_kernel<<<dim3(3072/128, MTOK/128), 256, G_SMEM>>>();

    rope_apply_kernel<<<2*BATCH*HEADS*NSEQ*32/256, 256>>>();

    cudaFuncSetAttribute(attn_mma_kernel,
                         cudaFuncAttributeMaxDynamicSharedMemorySize, ATTN_SMEM);
    attn_mma_kernel<<<dim3(NSEQ/128, HEADS, BATCH), 256, ATTN_SMEM>>>(slopes);

    cudaFuncSetAttribute(proj_mma_kernel,
                         cudaFuncAttributeMaxDynamicSharedMemorySize, G_SMEM);
    proj_mma_kernel<<<dim3(CDIM/128, MTOK/128), 256, G_SMEM>>>(proj_b, out);
}

// round 11
// speedup vs baseline: 6.7426x; 1.0275x over previous
#include <cuda_runtime.h>
#include <cuda_fp16.h>
#include <cstdint>
#include <math.h>

#define NSEQ   2048
#define BATCH  2
#define HEADS  16
#define HD     64
#define CDIM   1024
#define MTOK   (BATCH*NSEQ)      // 4096

// ---------------- device scratch (no allocations allowed) ------------------
__device__ __align__(16) __half g_x[MTOK*CDIM];
__device__ __align__(16) __half g_wq[3*CDIM*CDIM];
__device__ __align__(16) __half g_wp[CDIM*CDIM];
__device__ __align__(16) float  g_qf[MTOK*CDIM], g_kf[MTOK*CDIM];
__device__ __align__(16) __half g_qh[MTOK*CDIM];   // q fp16 (post-RoPE)
__device__ __align__(16) __half g_kh[MTOK*CDIM];   // k fp16 (post-RoPE)
__device__ __align__(16) __half g_vh[MTOK*CDIM];   // v fp16
__device__ __align__(16) __half g_ao[MTOK*CDIM];   // attention out fp16
__device__ __align__(16) float  g_sin[NSEQ*32], g_cos[NSEQ*32];

// ======================= helpers ===========================================
__device__ __forceinline__ uint32_t h2u(__half2 v) {
    union { __half2 h; uint32_t u; } c; c.h = v; return c.u;
}

__device__ __forceinline__ void mma_f16(float c[4], const uint32_t a[4], const uint32_t b[2]) {
    asm volatile(
        "mma.sync.aligned.m16n8k16.row.col.f32.f16.f16.f32 "
        "{%0,%1,%2,%3}, {%4,%5,%6,%7}, {%8,%9}, {%0,%1,%2,%3};\n"
        : "+f"(c[0]), "+f"(c[1]), "+f"(c[2]), "+f"(c[3])
        : "r"(a[0]), "r"(a[1]), "r"(a[2]), "r"(a[3]), "r"(b[0]), "r"(b[1]));
}

// A fragment (m16 x k16, row-major in smem)
__device__ __forceinline__ void lda_frag(uint32_t r[4], const __half* base, int row0, int col0, int ld) {
    const int lane = threadIdx.x & 31;
    const __half* p = base + (row0 + (lane & 15)) * ld + col0 + ((lane >> 4) << 3);
    uint32_t a = (uint32_t)__cvta_generic_to_shared(p);
    asm volatile("ldmatrix.sync.aligned.m8n8.x4.shared.b16 {%0,%1,%2,%3}, [%4];"
                 : "=r"(r[0]), "=r"(r[1]), "=r"(r[2]), "=r"(r[3]) : "r"(a));
}

// TWO B fragments (k16 x n8 each) for n0..n0+15; smem holds B^T row-major
__device__ __forceinline__ void ldbx4(uint32_t r[4], const __half* base, int n0, int k0, int ld) {
    const int lane = threadIdx.x & 31;
    const __half* p = base + (n0 + ((lane >> 4) << 3) + (lane & 7)) * ld
                           + k0 + (((lane >> 3) & 1) << 3);
    uint32_t a = (uint32_t)__cvta_generic_to_shared(p);
    asm volatile("ldmatrix.sync.aligned.m8n8.x4.shared.b16 {%0,%1,%2,%3}, [%4];"
                 : "=r"(r[0]), "=r"(r[1]), "=r"(r[2]), "=r"(r[3]) : "r"(a));
}

// TWO B fragments from NATURAL row-major B [k][n] via trans (for V)
__device__ __forceinline__ void ldbx4t(uint32_t r[4], const __half* base, int n0, int k0, int ld) {
    const int lane = threadIdx.x & 31;
    const __half* p = base + (k0 + (lane & 15)) * ld + n0 + ((lane >> 4) << 3);
    uint32_t a = (uint32_t)__cvta_generic_to_shared(p);
    asm volatile("ldmatrix.sync.aligned.m8n8.x4.trans.shared.b16 {%0,%1,%2,%3}, [%4];"
                 : "=r"(r[0]), "=r"(r[1]), "=r"(r[2]), "=r"(r[3]) : "r"(a));
}

__device__ __forceinline__ void cp_async16(uint32_t saddr, const void* gaddr) {
    asm volatile("cp.async.cg.shared.global [%0], [%1], 16;" :: "r"(saddr), "l"(gaddr));
}
#define CP_COMMIT()  asm volatile("cp.async.commit_group;" ::: "memory")
#define CP_WAIT(n)   asm volatile("cp.async.wait_group %0;" :: "n"(n) : "memory")

// ---------------- merged prep: 3x fp32->fp16 convert + rope table ----------
// block i handles: [0, 4096) x, [4096, 16384) wq, [16384, 20480) wp,
// [20480, 20736) rope table (256 blocks x 256 threads = 65536 entries).
#define PREP_X  (MTOK*CDIM/1024)        // 4096
#define PREP_WQ (PREP_X + 3*CDIM*CDIM/1024)  // 16384
#define PREP_WP (PREP_WQ + CDIM*CDIM/1024)   // 20480
__global__ __launch_bounds__(256) void prep_kernel(
    const float* __restrict__ x, const float* __restrict__ wq,
    const float* __restrict__ wp)
{
    int blk = blockIdx.x;
    if (blk < PREP_WP) {
        const float* in;
        __half* out;
        int i;
        if (blk < PREP_X)        { in = x;  out = g_x;  i = blk * 256 + threadIdx.x; }
        else if (blk < PREP_WQ)  { in = wq; out = g_wq; i = (blk - PREP_X) * 256 + threadIdx.x; }
        else                     { in = wp; out = g_wp; i = (blk - PREP_WQ) * 256 + threadIdx.x; }
        float4 v = ((const float4*)in)[i];
        ((__half2*)out)[2*i]   = __floats2half2_rn(v.x, v.y);
        ((__half2*)out)[2*i+1] = __floats2half2_rn(v.z, v.w);
    } else {
        int idx = (blk - PREP_WP) * 256 + threadIdx.x;   // 0..65535
        int n = idx >> 5, pair = idx & 31;
        float inv = powf(10000.0f, -(float)pair * (1.0f/32.0f));
        float s, cc;
        sincosf((float)n * inv, &s, &cc);
        g_sin[idx] = s;
        g_cos[idx] = cc;
    }
}
#define PREP_GRID (PREP_WP + NSEQ*32/256)    // 20736

// ================= double-buffered fp16 GEMM tile ==========================
// 128x128 tile, K=1024 in 16 chunks of 64 cols. 2 stages x 2 planes x 128x72.
#define GLDS    72
#define G_PLANE (128*GLDS)          // 9216 halves
#define G_STAGE (2*G_PLANE)         // 18432 halves
#define G_SMEM  (2*G_STAGE*2)       // 73728 bytes

__device__ __forceinline__ void g_prefetch(
    uint32_t smem_u32, int c, const __half* A, const __half* B)
{
    const int tid = threadIdx.x;
    uint32_t sb = smem_u32 + (c & 1) * (G_STAGE * 2);
    const __half* gp[2] = {A, B};
#pragma unroll
    for (int i = 0; i < 8; i++) {
        int idx = tid + i * 256;            // 0..2047
        int p = idx >> 10, r = (idx >> 3) & 127, seg = idx & 7;
        const __half* g = gp[p] + (size_t)r * 1024 + c * 64 + seg * 8;
        uint32_t d = sb + p * (G_PLANE * 2) + r * (GLDS * 2) + seg * 16;
        cp_async16(d, g);
    }
    CP_COMMIT();
}

__device__ __forceinline__ void gemm_tile2(
    const __half* __restrict__ A, const __half* __restrict__ B,
    __half* smem, float c[4][4][4])
{
    uint32_t smem_u32 = (uint32_t)__cvta_generic_to_shared(smem);
    const int wid = threadIdx.x >> 5;
    const int wm = wid >> 2, wn = wid & 3;

    g_prefetch(smem_u32, 0, A, B);

    for (int ch = 0; ch < 16; ch++) {
        CP_WAIT(0);
        __syncthreads();
        if (ch + 1 < 16) g_prefetch(smem_u32, ch + 1, A, B);

        __half* st = smem + (ch & 1) * G_STAGE;
        __half* sA = st;
        __half* sB = st + G_PLANE;

#pragma unroll
        for (int ks = 0; ks < 64; ks += 16) {
            uint32_t b4[2][4];
#pragma unroll
            for (int ntp = 0; ntp < 2; ntp++)
                ldbx4(b4[ntp], sB, wn * 32 + ntp * 16, ks, GLDS);
#pragma unroll
            for (int mi = 0; mi < 4; mi++) {
                uint32_t a4[4];
                lda_frag(a4, sA, wm * 64 + mi * 16, ks, GLDS);
#pragma unroll
                for (int ni = 0; ni < 4; ni++)
                    mma_f16(c[mi][ni], a4, &b4[ni >> 1][(ni & 1) * 2]);
            }
        }
    }
}

// ---------------- QKV GEMM + scatter epilogue ------------------------------
__global__ __launch_bounds__(256, 2) void qkv_mma_kernel()
{
    extern __shared__ __half gsm[];
    float c[4][4][4];
#pragma unroll
    for (int a = 0; a < 4; a++)
#pragma unroll
        for (int b = 0; b < 4; b++)
#pragma unroll
            for (int d = 0; d < 4; d++) c[a][b][d] = 0.0f;

    const int rowBase = blockIdx.y * 128, colBase = blockIdx.x * 128;
    gemm_tile2(g_x + (size_t)rowBase*1024, g_wq + (size_t)colBase*1024, gsm, c);

    const int lane = threadIdx.x & 31, wid = threadIdx.x >> 5;
    const int wm = wid >> 2, wn = wid & 3;
    const int g = lane >> 2, t2 = (lane & 3) << 1;
    const int tix = colBase >> 10;   // 0=q, 1=k, 2=v (uniform per block)

#pragma unroll
    for (int mi = 0; mi < 4; mi++) {
        int row = rowBase + wm*64 + mi*16 + g;
        int bb = row >> 11, n = row & 2047;
#pragma unroll
        for (int ni = 0; ni < 4; ni++) {
            int colg = colBase + wn*32 + ni*8 + t2;
            int rem = colg & 1023, hh = rem >> 6, d = rem & 63;
            size_t base0 = (((size_t)(bb * HEADS + hh)) * NSEQ + n) * HD + d;
            size_t base1 = base0 + 8*HD;
            float* f = c[mi][ni];
            if (tix == 0) {
                *(float2*)(g_qf + base0) = make_float2(f[0], f[1]);
                *(float2*)(g_qf + base1) = make_float2(f[2], f[3]);
            } else if (tix == 1) {
                *(float2*)(g_kf + base0) = make_float2(f[0], f[1]);
                *(float2*)(g_kf + base1) = make_float2(f[2], f[3]);
            } else {
                *(__half2*)(g_vh + base0) = __floats2half2_rn(f[0], f[1]);
                *(__half2*)(g_vh + base1) = __floats2half2_rn(f[2], f[3]);
            }
        }
    }
}

// ---------------- output projection ---------------------------------------
__global__ __launch_bounds__(256, 2) void proj_mma_kernel(
    const float* __restrict__ bias, float* __restrict__ out)
{
    extern __shared__ __half gsm[];
    float c[4][4][4];
#pragma unroll
    for (int a = 0; a < 4; a++)
#pragma unroll
        for (int b = 0; b < 4; b++)
#pragma unroll
            for (int d = 0; d < 4; d++) c[a][b][d] = 0.0f;

    const int rowBase = blockIdx.y * 128, colBase = blockIdx.x * 128;
    gemm_tile2(g_ao + (size_t)rowBase*1024, g_wp + (size_t)colBase*1024, gsm, c);

    const int lane = threadIdx.x & 31, wid = threadIdx.x >> 5;
    const int wm = wid >> 2, wn = wid & 3;
    const int g = lane >> 2, t2 = (lane & 3) << 1;

#pragma unroll
    for (int mi = 0; mi < 4; mi++) {
        int row = rowBase + wm*64 + mi*16 + g;
#pragma unroll
        for (int ni = 0; ni < 4; ni++) {
            int colg = colBase + wn*32 + ni*8 + t2;
            float b0 = bias[colg], b1 = bias[colg+1];
            float* f = c[mi][ni];
            *(float2*)(out + (size_t)row*CDIM + colg)     = make_float2(f[0]+b0, f[1]+b1);
            *(float2*)(out + (size_t)(row+8)*CDIM + colg) = make_float2(f[2]+b0, f[3]+b1);
        }
    }
}

// ---------------- RoPE apply ------------------------------------------------
__global__ __launch_bounds__(256) void rope_apply_kernel()
{
    const int per = BATCH*HEADS*NSEQ*32;
    int idx = blockIdx.x*256 + threadIdx.x;
    bool isq = idx < per;
    int rem = isq ? idx : idx - per;
    int pair = rem & 31;
    int rowI = rem >> 5;
    int n = rowI & (NSEQ-1);

    float s  = g_sin[n*32 + pair];
    float cc = g_cos[n*32 + pair];

    const float* src = isq ? g_qf : g_kf;
    __half* dst = isq ? g_qh : g_kh;
    size_t p0 = (size_t)rowI*64 + pair;
    float t1 = src[p0], t2 = src[p0+32];
    dst[p0]    = __float2half_rn(t1*cc - t2*s);
    dst[p0+32] = __float2half_rn(t2*cc + t1*s);
}

// ====== pure-fp16 flash attention: 256-row q-tile, single wave ==============
// smem (halves): Q @0 (256x72 = 18432), stage0 @18432, stage1 @27648.
// Stage layout: Kh@0 (64x72 = 4608), Vh@4608 (64x72, natural [j][d]).
#define ALD       72
#define AQ_ELEM   (256*ALD)            // 18432
#define AST_ELEM  (2*64*ALD)           // 9216
#define ATTN_SMEM ((AQ_ELEM + 2*AST_ELEM) * 2)   // 73728 B

__device__ __forceinline__ void attn_prefetch(uint32_t smem_u32, int kt, int bh)
{
    const int tid = threadIdx.x;   // 0..511
    const size_t koff = ((size_t)bh * NSEQ + kt * 64) * HD;
    uint32_t base = smem_u32 + (AQ_ELEM + (kt & 1) * AST_ELEM) * 2;
#pragma unroll
    for (int i = 0; i < 2; i++) {
        int idx = tid + i * 512;            // 0..1023
        int t = idx >> 9;                   // 0=kh, 1=vh
        int r = (idx >> 3) & 63;
        int seg = idx & 7;
        const __half* g = (t == 0 ? g_kh : g_vh) + koff + r * 64 + seg * 8;
        uint32_t d = base + t * 9216 + r * (ALD * 2) + seg * 16;
        cp_async16(d, g);
    }
    CP_COMMIT();
}

__global__ __launch_bounds__(512, 1) void attn_mma_kernel(const float* __restrict__ slopes)
{
    extern __shared__ __half smh[];
    uint32_t smem_u32 = (uint32_t)__cvta_generic_to_shared(smh);

    const int tid = threadIdx.x, wid = tid >> 5, lane = tid & 31;
    const int g = lane >> 2, t2 = (lane & 3) << 1;
    const int qt = blockIdx.x, h = blockIdx.y, b = blockIdx.z;
    const int bh = b*HEADS + h;
    const float slope8 = slopes[h] * 8.0f;

    // load Q plane (256x64)
    __half* sQh = smh;
    const size_t qoff = ((size_t)bh*NSEQ + qt*256)*HD;
    for (int v = tid; v < 2048; v += 512) {
        int row = v >> 3, seg = (v & 7) << 3;
        *(uint4*)(sQh + row*ALD + seg) = *(const uint4*)(g_qh + qoff + row*64 + seg);
    }
    attn_prefetch(smem_u32, 0, bh);
    __syncthreads();

    // hoist Q fragments for all 4 k-steps (warp owns rows [wid*16, wid*16+16))
    uint32_t qh[4][4];
#pragma unroll
    for (int ks = 0; ks < 4; ks++)
        lda_frag(qh[ks], sQh, wid*16, ks*16, ALD);

    float o[8][4];
#pragma unroll
    for (int nt = 0; nt < 8; nt++)
#pragma unroll
        for (int d = 0; d < 4; d++) o[nt][d] = 0.0f;
    float m0 = -1e30f, m1 = -1e30f, l0 = 0.0f, l1 = 0.0f;
    const int rowg = qt*256 + wid*16 + g;   // this thread's rows: rowg, rowg+8

    for (int kt = 0; kt < 32; kt++) {
        CP_WAIT(0);
        __syncthreads();
        if (kt + 1 < 32) attn_prefetch(smem_u32, kt + 1, bh);

        __half* reg = smh + AQ_ELEM + (kt & 1) * AST_ELEM;
        __half* sKh = reg;
        __half* sVh = reg + 4608;

        // S = Q K^T
        float s[8][4];
#pragma unroll
        for (int nt = 0; nt < 8; nt++)
#pragma unroll
            for (int d = 0; d < 4; d++) s[nt][d] = 0.0f;
#pragma unroll
        for (int ks = 0; ks < 4; ks++) {
#pragma unroll
            for (int ntp = 0; ntp < 4; ntp++) {
                uint32_t kh4[4];
                ldbx4(kh4, sKh, ntp*16, ks*16, ALD);
                mma_f16(s[2*ntp],   qh[ks], &kh4[0]);
                mma_f16(s[2*ntp+1], qh[ks], &kh4[2]);
            }
        }

        // scale + ALiBi, row max
        float mx0 = -1e30f, mx1 = -1e30f;
#pragma unroll
        for (int nt = 0; nt < 8; nt++) {
            int colb = kt*64 + nt*8 + t2;
            float d00 = fminf(0.0f, (float)(colb     - rowg));
            float d01 = fminf(0.0f, (float)(colb + 1 - rowg));
            float d10 = fminf(0.0f, (float)(colb     - rowg - 8));
            float d11 = fminf(0.0f, (float)(colb + 1 - rowg - 8));
            s[nt][0] = s[nt][0]*0.125f + slope8*d00;
            s[nt][1] = s[nt][1]*0.125f + slope8*d01;
            s[nt][2] = s[nt][2]*0.125f + slope8*d10;
            s[nt][3] = s[nt][3]*0.125f + slope8*d11;
            mx0 = fmaxf(mx0, fmaxf(s[nt][0], s[nt][1]));
            mx1 = fmaxf(mx1, fmaxf(s[nt][2], s[nt][3]));
        }
#pragma unroll
        for (int off = 1; off <= 2; off <<= 1) {
            mx0 = fmaxf(mx0, __shfl_xor_sync(0xffffffffu, mx0, off));
            mx1 = fmaxf(mx1, __shfl_xor_sync(0xffffffffu, mx1, off));
        }
        float nm0 = fmaxf(m0, mx0), nm1 = fmaxf(m1, mx1);
        float f0 = __expf(m0 - nm0), f1 = __expf(m1 - nm1);
        m0 = nm0; m1 = nm1;

        // exp -> register-resident single-plane fp16 P fragments
        uint32_t ph[4][4];
        float sum0 = 0.0f, sum1 = 0.0f;
#pragma unroll
        for (int nt = 0; nt < 8; nt++) {
            float p0 = __expf(s[nt][0] - nm0);
            float p1 = __expf(s[nt][1] - nm0);
            float p2 = __expf(s[nt][2] - nm1);
            float p3 = __expf(s[nt][3] - nm1);
            sum0 += p0 + p1; sum1 += p2 + p3;
            int ks = nt >> 1, hf = (nt & 1) * 2;
            ph[ks][hf]     = h2u(__floats2half2_rn(p0, p1));
            ph[ks][hf + 1] = h2u(__floats2half2_rn(p2, p3));
        }
#pragma unroll
        for (int off = 1; off <= 2; off <<= 1) {
            sum0 += __shfl_xor_sync(0xffffffffu, sum0, off);
            sum1 += __shfl_xor_sync(0xffffffffu, sum1, off);
        }
        l0 = l0*f0 + sum0;
        l1 = l1*f1 + sum1;
#pragma unroll
        for (int nt = 0; nt < 8; nt++) {
            o[nt][0] *= f0; o[nt][1] *= f0;
            o[nt][2] *= f1; o[nt][3] *= f1;
        }

        // O += P V (V natural layout via trans ldmatrix)
#pragma unroll
        for (int ks = 0; ks < 4; ks++) {
#pragma unroll
            for (int ntp = 0; ntp < 4; ntp++) {
                uint32_t vh4[4];
                ldbx4t(vh4, sVh, ntp*16, ks*16, ALD);
                mma_f16(o[2*ntp],   ph[ks], &vh4[0]);
                mma_f16(o[2*ntp+1], ph[ks], &vh4[2]);
            }
        }
    }

    // epilogue: normalize, store ao as fp16 [B, N, H*D]
    float i0 = 1.0f / l0, i1 = 1.0f / l1;
#pragma unroll
    for (int nt = 0; nt < 8; nt++) {
        int col = h*64 + nt*8 + t2;
        size_t idx0 = ((size_t)b*NSEQ + rowg)*CDIM + col;
        size_t idx1 = idx0 + 8*CDIM;
        *(__half2*)(g_ao + idx0) = __floats2half2_rn(o[nt][0]*i0, o[nt][1]*i0);
        *(__half2*)(g_ao + idx1) = __floats2half2_rn(o[nt][2]*i1, o[nt][3]*i1);
    }
}

// ---------------------------------------------------------------------------
extern "C" void kernel_launch(void* const* d_in, const int* in_sizes, int n_in,
                              void* d_out, int out_size)
{
    const float* x      = (const float*)d_in[0];
    const float* qkv_w  = (const float*)d_in[1];
    const float* proj_w = (const float*)d_in[2];
    const float* proj_b = (const float*)d_in[3];
    const float* slopes = (const float*)d_in[4];
    float* out = (float*)d_out;

    prep_kernel<<<PREP_GRID, 256>>>(x, qkv_w, proj_w);

    cudaFuncSetAttribute(qkv_mma_kernel,
                         cudaFuncAttributeMaxDynamicSharedMemorySize, G_SMEM);
    qkv_mma_kernel<<<dim3(3072/128, MTOK/128), 256, G_SMEM>>>();

    rope_apply_kernel<<<2*BATCH*HEADS*NSEQ*32/256, 256>>>();

    cudaFuncSetAttribute(attn_mma_kernel,
                         cudaFuncAttributeMaxDynamicSharedMemorySize, ATTN_SMEM);
    attn_mma_kernel<<<dim3(NSEQ/256, HEADS, BATCH), 512, ATTN_SMEM>>>(slopes);

    cudaFuncSetAttribute(proj_mma_kernel,
                         cudaFuncAttributeMaxDynamicSharedMemorySize, G_SMEM);
    proj_mma_kernel<<<dim3(CDIM/128, MTOK/128), 256, G_SMEM>>>(proj_b, out);
}

// round 12
// speedup vs baseline: 6.9484x; 1.0305x over previous
#include <cuda_runtime.h>
#include <cuda_fp16.h>
#include <cstdint>
#include <math.h>

#define NSEQ   2048
#define BATCH  2
#define HEADS  16
#define HD     64
#define CDIM   1024
#define MTOK   (BATCH*NSEQ)      // 4096
#define LOG2E  1.4426950408889634f
#define QSCALE (0.125f * LOG2E)

// ---------------- device scratch (no allocations allowed) ------------------
__device__ __align__(16) __half g_x[MTOK*CDIM];
__device__ __align__(16) __half g_wq[3*CDIM*CDIM];
__device__ __align__(16) __half g_wp[CDIM*CDIM];
__device__ __align__(16) float  g_qf[MTOK*CDIM], g_kf[MTOK*CDIM];
__device__ __align__(16) __half g_qh[MTOK*CDIM];   // q fp16 (post-RoPE, pre-scaled by QSCALE)
__device__ __align__(16) __half g_kh[MTOK*CDIM];   // k fp16 (post-RoPE)
__device__ __align__(16) __half g_vh[MTOK*CDIM];   // v fp16
__device__ __align__(16) __half g_ao[MTOK*CDIM];   // attention out fp16
__device__ __align__(16) float  g_sin[NSEQ*32], g_cos[NSEQ*32];

// ======================= helpers ===========================================
__device__ __forceinline__ uint32_t h2u(__half2 v) {
    union { __half2 h; uint32_t u; } c; c.h = v; return c.u;
}

__device__ __forceinline__ float ex2(float x) {
    float r;
    asm("ex2.approx.f32 %0, %1;" : "=f"(r) : "f"(x));
    return r;
}

__device__ __forceinline__ void mma_f16(float c[4], const uint32_t a[4], const uint32_t b[2]) {
    asm volatile(
        "mma.sync.aligned.m16n8k16.row.col.f32.f16.f16.f32 "
        "{%0,%1,%2,%3}, {%4,%5,%6,%7}, {%8,%9}, {%0,%1,%2,%3};\n"
        : "+f"(c[0]), "+f"(c[1]), "+f"(c[2]), "+f"(c[3])
        : "r"(a[0]), "r"(a[1]), "r"(a[2]), "r"(a[3]), "r"(b[0]), "r"(b[1]));
}

// A fragment (m16 x k16, row-major in smem)
__device__ __forceinline__ void lda_frag(uint32_t r[4], const __half* base, int row0, int col0, int ld) {
    const int lane = threadIdx.x & 31;
    const __half* p = base + (row0 + (lane & 15)) * ld + col0 + ((lane >> 4) << 3);
    uint32_t a = (uint32_t)__cvta_generic_to_shared(p);
    asm volatile("ldmatrix.sync.aligned.m8n8.x4.shared.b16 {%0,%1,%2,%3}, [%4];"
                 : "=r"(r[0]), "=r"(r[1]), "=r"(r[2]), "=r"(r[3]) : "r"(a));
}

// TWO B fragments (k16 x n8 each) for n0..n0+15; smem holds B^T row-major
__device__ __forceinline__ void ldbx4(uint32_t r[4], const __half* base, int n0, int k0, int ld) {
    const int lane = threadIdx.x & 31;
    const __half* p = base + (n0 + ((lane >> 4) << 3) + (lane & 7)) * ld
                           + k0 + (((lane >> 3) & 1) << 3);
    uint32_t a = (uint32_t)__cvta_generic_to_shared(p);
    asm volatile("ldmatrix.sync.aligned.m8n8.x4.shared.b16 {%0,%1,%2,%3}, [%4];"
                 : "=r"(r[0]), "=r"(r[1]), "=r"(r[2]), "=r"(r[3]) : "r"(a));
}

// TWO B fragments from NATURAL row-major B [k][n] via trans (for V)
__device__ __forceinline__ void ldbx4t(uint32_t r[4], const __half* base, int n0, int k0, int ld) {
    const int lane = threadIdx.x & 31;
    const __half* p = base + (k0 + (lane & 15)) * ld + n0 + ((lane >> 4) << 3);
    uint32_t a = (uint32_t)__cvta_generic_to_shared(p);
    asm volatile("ldmatrix.sync.aligned.m8n8.x4.trans.shared.b16 {%0,%1,%2,%3}, [%4];"
                 : "=r"(r[0]), "=r"(r[1]), "=r"(r[2]), "=r"(r[3]) : "r"(a));
}

__device__ __forceinline__ void cp_async16(uint32_t saddr, const void* gaddr) {
    asm volatile("cp.async.cg.shared.global [%0], [%1], 16;" :: "r"(saddr), "l"(gaddr));
}
#define CP_COMMIT()  asm volatile("cp.async.commit_group;" ::: "memory")
#define CP_WAIT(n)   asm volatile("cp.async.wait_group %0;" :: "n"(n) : "memory")

// ---------------- merged prep: 3x fp32->fp16 convert + rope table ----------
#define PREP_X  (MTOK*CDIM/1024)             // 4096
#define PREP_WQ (PREP_X + 3*CDIM*CDIM/1024)  // 16384
#define PREP_WP (PREP_WQ + CDIM*CDIM/1024)   // 20480
__global__ __launch_bounds__(256) void prep_kernel(
    const float* __restrict__ x, const float* __restrict__ wq,
    const float* __restrict__ wp)
{
    int blk = blockIdx.x;
    if (blk < PREP_WP) {
        const float* in;
        __half* out;
        int i;
        if (blk < PREP_X)        { in = x;  out = g_x;  i = blk * 256 + threadIdx.x; }
        else if (blk < PREP_WQ)  { in = wq; out = g_wq; i = (blk - PREP_X) * 256 + threadIdx.x; }
        else                     { in = wp; out = g_wp; i = (blk - PREP_WQ) * 256 + threadIdx.x; }
        float4 v = ((const float4*)in)[i];
        ((__half2*)out)[2*i]   = __floats2half2_rn(v.x, v.y);
        ((__half2*)out)[2*i+1] = __floats2half2_rn(v.z, v.w);
    } else {
        int idx = (blk - PREP_WP) * 256 + threadIdx.x;   // 0..65535
        int n = idx >> 5, pair = idx & 31;
        float inv = powf(10000.0f, -(float)pair * (1.0f/32.0f));
        float s, cc;
        sincosf((float)n * inv, &s, &cc);
        g_sin[idx] = s;
        g_cos[idx] = cc;
    }
}
#define PREP_GRID (PREP_WP + NSEQ*32/256)    // 20736

// ================= double-buffered fp16 GEMM tile ==========================
#define GLDS    72
#define G_PLANE (128*GLDS)          // 9216 halves
#define G_STAGE (2*G_PLANE)         // 18432 halves
#define G_SMEM  (2*G_STAGE*2)       // 73728 bytes

__device__ __forceinline__ void g_prefetch(
    uint32_t smem_u32, int c, const __half* A, const __half* B)
{
    const int tid = threadIdx.x;
    uint32_t sb = smem_u32 + (c & 1) * (G_STAGE * 2);
    const __half* gp[2] = {A, B};
#pragma unroll
    for (int i = 0; i < 8; i++) {
        int idx = tid + i * 256;            // 0..2047
        int p = idx >> 10, r = (idx >> 3) & 127, seg = idx & 7;
        const __half* g = gp[p] + (size_t)r * 1024 + c * 64 + seg * 8;
        uint32_t d = sb + p * (G_PLANE * 2) + r * (GLDS * 2) + seg * 16;
        cp_async16(d, g);
    }
    CP_COMMIT();
}

__device__ __forceinline__ void gemm_tile2(
    const __half* __restrict__ A, const __half* __restrict__ B,
    __half* smem, float c[4][4][4])
{
    uint32_t smem_u32 = (uint32_t)__cvta_generic_to_shared(smem);
    const int wid = threadIdx.x >> 5;
    const int wm = wid >> 2, wn = wid & 3;

    g_prefetch(smem_u32, 0, A, B);

    for (int ch = 0; ch < 16; ch++) {
        CP_WAIT(0);
        __syncthreads();
        if (ch + 1 < 16) g_prefetch(smem_u32, ch + 1, A, B);

        __half* st = smem + (ch & 1) * G_STAGE;
        __half* sA = st;
        __half* sB = st + G_PLANE;

#pragma unroll
        for (int ks = 0; ks < 64; ks += 16) {
            uint32_t b4[2][4];
#pragma unroll
            for (int ntp = 0; ntp < 2; ntp++)
                ldbx4(b4[ntp], sB, wn * 32 + ntp * 16, ks, GLDS);
#pragma unroll
            for (int mi = 0; mi < 4; mi++) {
                uint32_t a4[4];
                lda_frag(a4, sA, wm * 64 + mi * 16, ks, GLDS);
#pragma unroll
                for (int ni = 0; ni < 4; ni++)
                    mma_f16(c[mi][ni], a4, &b4[ni >> 1][(ni & 1) * 2]);
            }
        }
    }
}

// ---------------- QKV GEMM + scatter epilogue ------------------------------
__global__ __launch_bounds__(256, 2) void qkv_mma_kernel()
{
    extern __shared__ __half gsm[];
    float c[4][4][4];
#pragma unroll
    for (int a = 0; a < 4; a++)
#pragma unroll
        for (int b = 0; b < 4; b++)
#pragma unroll
            for (int d = 0; d < 4; d++) c[a][b][d] = 0.0f;

    const int rowBase = blockIdx.y * 128, colBase = blockIdx.x * 128;
    gemm_tile2(g_x + (size_t)rowBase*1024, g_wq + (size_t)colBase*1024, gsm, c);

    const int lane = threadIdx.x & 31, wid = threadIdx.x >> 5;
    const int wm = wid >> 2, wn = wid & 3;
    const int g = lane >> 2, t2 = (lane & 3) << 1;
    const int tix = colBase >> 10;   // 0=q, 1=k, 2=v (uniform per block)

#pragma unroll
    for (int mi = 0; mi < 4; mi++) {
        int row = rowBase + wm*64 + mi*16 + g;
        int bb = row >> 11, n = row & 2047;
#pragma unroll
        for (int ni = 0; ni < 4; ni++) {
            int colg = colBase + wn*32 + ni*8 + t2;
            int rem = colg & 1023, hh = rem >> 6, d = rem & 63;
            size_t base0 = (((size_t)(bb * HEADS + hh)) * NSEQ + n) * HD + d;
            size_t base1 = base0 + 8*HD;
            float* f = c[mi][ni];
            if (tix == 0) {
                *(float2*)(g_qf + base0) = make_float2(f[0], f[1]);
                *(float2*)(g_qf + base1) = make_float2(f[2], f[3]);
            } else if (tix == 1) {
                *(float2*)(g_kf + base0) = make_float2(f[0], f[1]);
                *(float2*)(g_kf + base1) = make_float2(f[2], f[3]);
            } else {
                *(__half2*)(g_vh + base0) = __floats2half2_rn(f[0], f[1]);
                *(__half2*)(g_vh + base1) = __floats2half2_rn(f[2], f[3]);
            }
        }
    }
}

// ---------------- output projection ---------------------------------------
__global__ __launch_bounds__(256, 2) void proj_mma_kernel(
    const float* __restrict__ bias, float* __restrict__ out)
{
    extern __shared__ __half gsm[];
    float c[4][4][4];
#pragma unroll
    for (int a = 0; a < 4; a++)
#pragma unroll
        for (int b = 0; b < 4; b++)
#pragma unroll
            for (int d = 0; d < 4; d++) c[a][b][d] = 0.0f;

    const int rowBase = blockIdx.y * 128, colBase = blockIdx.x * 128;
    gemm_tile2(g_ao + (size_t)rowBase*1024, g_wp + (size_t)colBase*1024, gsm, c);

    const int lane = threadIdx.x & 31, wid = threadIdx.x >> 5;
    const int wm = wid >> 2, wn = wid & 3;
    const int g = lane >> 2, t2 = (lane & 3) << 1;

#pragma unroll
    for (int mi = 0; mi < 4; mi++) {
        int row = rowBase + wm*64 + mi*16 + g;
#pragma unroll
        for (int ni = 0; ni < 4; ni++) {
            int colg = colBase + wn*32 + ni*8 + t2;
            float b0 = bias[colg], b1 = bias[colg+1];
            float* f = c[mi][ni];
            *(float2*)(out + (size_t)row*CDIM + colg)     = make_float2(f[0]+b0, f[1]+b1);
            *(float2*)(out + (size_t)(row+8)*CDIM + colg) = make_float2(f[2]+b0, f[3]+b1);
        }
    }
}

// ---------------- RoPE apply (q pre-scaled by QSCALE) ----------------------
__global__ __launch_bounds__(256) void rope_apply_kernel()
{
    const int per = BATCH*HEADS*NSEQ*32;
    int idx = blockIdx.x*256 + threadIdx.x;
    bool isq = idx < per;
    int rem = isq ? idx : idx - per;
    int pair = rem & 31;
    int rowI = rem >> 5;
    int n = rowI & (NSEQ-1);

    float s  = g_sin[n*32 + pair];
    float cc = g_cos[n*32 + pair];

    const float* src = isq ? g_qf : g_kf;
    __half* dst = isq ? g_qh : g_kh;
    float sc = isq ? QSCALE : 1.0f;
    size_t p0 = (size_t)rowI*64 + pair;
    float t1 = src[p0], t2 = src[p0+32];
    dst[p0]    = __float2half_rn((t1*cc - t2*s) * sc);
    dst[p0+32] = __float2half_rn((t2*cc + t1*s) * sc);
}

// ====== pure-fp16 flash attention: 256-row q-tile, log2-domain softmax ======
// smem (halves): Q @0 (256x72 = 18432), stage0 @18432, stage1 @27648.
// Stage layout: Kh@0 (64x72 = 4608), Vh@4608 (64x72, natural [j][d]).
#define ALD       72
#define AQ_ELEM   (256*ALD)            // 18432
#define AST_ELEM  (2*64*ALD)           // 9216
#define ATTN_SMEM ((AQ_ELEM + 2*AST_ELEM) * 2)   // 73728 B

__device__ __forceinline__ void attn_prefetch(uint32_t smem_u32, int kt, int bh)
{
    const int tid = threadIdx.x;   // 0..511
    const size_t koff = ((size_t)bh * NSEQ + kt * 64) * HD;
    uint32_t base = smem_u32 + (AQ_ELEM + (kt & 1) * AST_ELEM) * 2;
#pragma unroll
    for (int i = 0; i < 2; i++) {
        int idx = tid + i * 512;            // 0..1023
        int t = idx >> 9;                   // 0=kh, 1=vh
        int r = (idx >> 3) & 63;
        int seg = idx & 7;
        const __half* g = (t == 0 ? g_kh : g_vh) + koff + r * 64 + seg * 8;
        uint32_t d = base + t * 9216 + r * (ALD * 2) + seg * 16;
        cp_async16(d, g);
    }
    CP_COMMIT();
}

__global__ __launch_bounds__(512, 1) void attn_mma_kernel(const float* __restrict__ slopes)
{
    extern __shared__ __half smh[];
    uint32_t smem_u32 = (uint32_t)__cvta_generic_to_shared(smh);

    const int tid = threadIdx.x, wid = tid >> 5, lane = tid & 31;
    const int g = lane >> 2, t2 = (lane & 3) << 1;
    const int qt = blockIdx.x, h = blockIdx.y, b = blockIdx.z;
    const int bh = b*HEADS + h;
    const float sl = slopes[h] * 8.0f * LOG2E;   // ALiBi slope in log2 domain
    const float sl8 = 8.0f * sl;

    // load Q plane (256x64)
    __half* sQh = smh;
    const size_t qoff = ((size_t)bh*NSEQ + qt*256)*HD;
    for (int v = tid; v < 2048; v += 512) {
        int row = v >> 3, seg = (v & 7) << 3;
        *(uint4*)(sQh + row*ALD + seg) = *(const uint4*)(g_qh + qoff + row*64 + seg);
    }
    attn_prefetch(smem_u32, 0, bh);
    __syncthreads();

    // hoist Q fragments for all 4 k-steps (warp owns rows [wid*16, wid*16+16))
    uint32_t qh[4][4];
#pragma unroll
    for (int ks = 0; ks < 4; ks++)
        lda_frag(qh[ks], sQh, wid*16, ks*16, ALD);

    float o[8][4];
#pragma unroll
    for (int nt = 0; nt < 8; nt++)
#pragma unroll
        for (int d = 0; d < 4; d++) o[nt][d] = 0.0f;
    float m0 = -1e30f, m1 = -1e30f, l0 = 0.0f, l1 = 0.0f;
    const int rowg = qt*256 + wid*16 + g;   // this thread's rows: rowg, rowg+8

    for (int kt = 0; kt < 32; kt++) {
        CP_WAIT(0);
        __syncthreads();
        if (kt + 1 < 32) attn_prefetch(smem_u32, kt + 1, bh);

        __half* reg = smh + AQ_ELEM + (kt & 1) * AST_ELEM;
        __half* sKh = reg;
        __half* sVh = reg + 4608;

        // S = Q K^T  (already in log2 domain: q pre-scaled by 0.125*log2e)
        float s[8][4];
#pragma unroll
        for (int nt = 0; nt < 8; nt++)
#pragma unroll
            for (int d = 0; d < 4; d++) s[nt][d] = 0.0f;
#pragma unroll
        for (int ks = 0; ks < 4; ks++) {
#pragma unroll
            for (int ntp = 0; ntp < 4; ntp++) {
                uint32_t kh4[4];
                ldbx4(kh4, sKh, ntp*16, ks*16, ALD);
                mma_f16(s[2*ntp],   qh[ks], &kh4[0]);
                mma_f16(s[2*ntp+1], qh[ks], &kh4[2]);
            }
        }

        // ALiBi (log2 domain) with tile classification, then row max
        const int lo = kt * 64;
        float mx0 = -1e30f, mx1 = -1e30f;
        if (lo > rowg + 8) {
            // whole tile above both rows: alibi = 0 (s unchanged)
#pragma unroll
            for (int nt = 0; nt < 8; nt++) {
                mx0 = fmaxf(mx0, fmaxf(s[nt][0], s[nt][1]));
                mx1 = fmaxf(mx1, fmaxf(s[nt][2], s[nt][3]));
            }
        } else if (lo + 63 <= rowg) {
            // whole tile at/below both rows: alibi linear, no clamp
            float base0 = sl * (float)(lo + t2 - rowg);   // row rowg, col offset 0
#pragma unroll
            for (int nt = 0; nt < 8; nt++) {
                float a = fmaf(sl8, (float)nt, base0);    // col = lo + nt*8 + t2
                s[nt][0] += a;
                s[nt][1] += a + sl;
                s[nt][2] += a - sl8;        // row rowg+8: diff -8
                s[nt][3] += a + sl - sl8;
                mx0 = fmaxf(mx0, fmaxf(s[nt][0], s[nt][1]));
                mx1 = fmaxf(mx1, fmaxf(s[nt][2], s[nt][3]));
            }
        } else {
            // boundary tile: exact clamped path
#pragma unroll
            for (int nt = 0; nt < 8; nt++) {
                int colb = lo + nt*8 + t2;
                float d00 = fminf(0.0f, (float)(colb     - rowg));
                float d01 = fminf(0.0f, (float)(colb + 1 - rowg));
                float d10 = fminf(0.0f, (float)(colb     - rowg - 8));
                float d11 = fminf(0.0f, (float)(colb + 1 - rowg - 8));
                s[nt][0] = fmaf(sl, d00, s[nt][0]);
                s[nt][1] = fmaf(sl, d01, s[nt][1]);
                s[nt][2] = fmaf(sl, d10, s[nt][2]);
                s[nt][3] = fmaf(sl, d11, s[nt][3]);
                mx0 = fmaxf(mx0, fmaxf(s[nt][0], s[nt][1]));
                mx1 = fmaxf(mx1, fmaxf(s[nt][2], s[nt][3]));
            }
        }
#pragma unroll
        for (int off = 1; off <= 2; off <<= 1) {
            mx0 = fmaxf(mx0, __shfl_xor_sync(0xffffffffu, mx0, off));
            mx1 = fmaxf(mx1, __shfl_xor_sync(0xffffffffu, mx1, off));
        }
        float nm0 = fmaxf(m0, mx0), nm1 = fmaxf(m1, mx1);
        float f0 = ex2(m0 - nm0), f1 = ex2(m1 - nm1);
        m0 = nm0; m1 = nm1;

        // exp2 -> register-resident fp16 P fragments
        uint32_t ph[4][4];
        float sum0 = 0.0f, sum1 = 0.0f;
#pragma unroll
        for (int nt = 0; nt < 8; nt++) {
            float p0 = ex2(s[nt][0] - nm0);
            float p1 = ex2(s[nt][1] - nm0);
            float p2 = ex2(s[nt][2] - nm1);
            float p3 = ex2(s[nt][3] - nm1);
            sum0 += p0 + p1; sum1 += p2 + p3;
            int ks = nt >> 1, hf = (nt & 1) * 2;
            ph[ks][hf]     = h2u(__floats2half2_rn(p0, p1));
            ph[ks][hf + 1] = h2u(__floats2half2_rn(p2, p3));
        }
#pragma unroll
        for (int off = 1; off <= 2; off <<= 1) {
            sum0 += __shfl_xor_sync(0xffffffffu, sum0, off);
            sum1 += __shfl_xor_sync(0xffffffffu, sum1, off);
        }
        l0 = l0*f0 + sum0;
        l1 = l1*f1 + sum1;
#pragma unroll
        for (int nt = 0; nt < 8; nt++) {
            o[nt][0] *= f0; o[nt][1] *= f0;
            o[nt][2] *= f1; o[nt][3] *= f1;
        }

        // O += P V (V natural layout via trans ldmatrix)
#pragma unroll
        for (int ks = 0; ks < 4; ks++) {
#pragma unroll
            for (int ntp = 0; ntp < 4; ntp++) {
                uint32_t vh4[4];
                ldbx4t(vh4, sVh, ntp*16, ks*16, ALD);
                mma_f16(o[2*ntp],   ph[ks], &vh4[0]);
                mma_f16(o[2*ntp+1], ph[ks], &vh4[2]);
            }
        }
    }

    // epilogue: normalize, store ao as fp16 [B, N, H*D]
    float i0 = 1.0f / l0, i1 = 1.0f / l1;
#pragma unroll
    for (int nt = 0; nt < 8; nt++) {
        int col = h*64 + nt*8 + t2;
        size_t idx0 = ((size_t)b*NSEQ + rowg)*CDIM + col;
        size_t idx1 = idx0 + 8*CDIM;
        *(__half2*)(g_ao + idx0) = __floats2half2_rn(o[nt][0]*i0, o[nt][1]*i0);
        *(__half2*)(g_ao + idx1) = __floats2half2_rn(o[nt][2]*i1, o[nt][3]*i1);
    }
}

// ---------------------------------------------------------------------------
extern "C" void kernel_launch(void* const* d_in, const int* in_sizes, int n_in,
                              void* d_out, int out_size)
{
    const float* x      = (const float*)d_in[0];
    const float* qkv_w  = (const float*)d_in[1];
    const float* proj_w = (const float*)d_in[2];
    const float* proj_b = (const float*)d_in[3];
    const float* slopes = (const float*)d_in[4];
    float* out = (float*)d_out;

    prep_kernel<<<PREP_GRID, 256>>>(x, qkv_w, proj_w);

    cudaFuncSetAttribute(qkv_mma_kernel,
                         cudaFuncAttributeMaxDynamicSharedMemorySize, G_SMEM);
    qkv_mma_kernel<<<dim3(3072/128, MTOK/128), 256, G_SMEM>>>();

    rope_apply_kernel<<<2*BATCH*HEADS*NSEQ*32/256, 256>>>();

    cudaFuncSetAttribute(attn_mma_kernel,
                         cudaFuncAttributeMaxDynamicSharedMemorySize, ATTN_SMEM);
    attn_mma_kernel<<<dim3(NSEQ/256, HEADS, BATCH), 512, ATTN_SMEM>>>(slopes);

    cudaFuncSetAttribute(proj_mma_kernel,
                         cudaFuncAttributeMaxDynamicSharedMemorySize, G_SMEM);
    proj_mma_kernel<<<dim3(CDIM/128, MTOK/128), 256, G_SMEM>>>(proj_b, out);
}